// round 1
// baseline (speedup 1.0000x reference)
#include <cuda_runtime.h>
#include <math.h>
#include <stdint.h>

#define BB 64      // batch
#define KB 8       // beams
#define RR 512     // BB*KB rows
#define HH 1024    // hidden
#define VV 400     // vocab
#define V1 401
#define LL 13      // program_len
#define G4 4096    // 4*HH
#define NP 1000    // log_R quadrature points

// ---------------- persistent scratch (device globals; no allocs) -------------
__device__ float d_h[2][RR*HH];
__device__ float d_c[2][RR*HH];
__device__ float d_htmp[RR*HH];
__device__ float d_ctmp[RR*HH];
__device__ float d_Gmx[2][RR];
__device__ float d_logp[2][RR];
__device__ int   d_prev[RR];
__device__ float d_samples[2][RR*LL];
__device__ float d_outputs[2][RR*LL];
__device__ float d_entplot[BB];
__device__ float d_entelem[BB];
__device__ float d_xW[BB*G4];
__device__ float d_E[V1*128];
__device__ float d_Gt[V1*G4];
__device__ float d_gates[RR*G4];
__device__ float d_hd[RR*HH];
__device__ float d_lp[RR*VV];     // logits -> log_probs (in place)
__device__ float d_gm[RR*VV];     // gumbel-perturbed scores
__device__ float d_entrow[RR];
__device__ int   d_order[RR];
__device__ int   d_snew[RR];
__device__ float d_phik[BB*KB];
__device__ float d_logRs[BB*KB];
__device__ float d_logRss[BB*KB*KB];
__device__ float d_entbeams[BB*KB];

// ---------------- helpers ----------------------------------------------------
__device__ __forceinline__ float sigmoidf(float x){ return 1.f/(1.f+expf(-x)); }

__device__ __forceinline__ float log1mexp(float x){
    // log(1 - exp(x)) for x <= 0, matching the reference's clamp & branch
    x = fminf(x, -1e-38f);
    if (x > -0.6931472f) return logf(-expm1f(x));
    return log1pf(-expf(x));
}

// ---------------- init: zero state + E table ---------------------------------
__global__ void init_kernel(const float* __restrict__ W_in_op,
                            const float* __restrict__ b_in_op){
    int idx = blockIdx.x*blockDim.x + threadIdx.x;
    int stride = gridDim.x*blockDim.x;
    for (int i = idx; i < RR*HH; i += stride){ d_h[0][i]=0.f; d_c[0][i]=0.f; }
    for (int i = idx; i < RR;    i += stride){ d_Gmx[0][i]=0.f; d_logp[0][i]=0.f; d_prev[i]=VV; }
    for (int i = idx; i < RR*LL; i += stride){ d_samples[0][i]=0.f; d_outputs[0][i]=0.f; }
    for (int i = idx; i < BB;    i += stride){ d_entplot[i]=0.f; d_entelem[i]=0.f; }
    for (int i = idx; i < V1*128; i += stride){
        int s = i >> 7, m = i & 127;
        d_E[i] = fmaxf(W_in_op[m*V1 + s] + b_in_op[m], 0.f);
    }
}

// ---------------- generic NT SGEMM: C = A(MxK) * B(NxK)^T + epilogue ----------
// MODE: 0 = none, 1 = +bias1+bias2, 3 = relu(+bias1), 4 = +bias1
// Requires BM==BN? no — requires BM*BK == 1024 and BN*BK == 1024 (one float4/thread per tile)
template<int BM, int BN, int BK, int TM, int TN, int MODE>
__global__ void __launch_bounds__(256) gemm_nt(
    const float* __restrict__ A, int lda,
    const float* __restrict__ Bm, int ldb,
    float* __restrict__ C, int ldc,
    int M, int N, int K,
    const float* __restrict__ bias1,
    const float* __restrict__ bias2)
{
    __shared__ float As[BK][BM+4];
    __shared__ float Bs[BK][BN+4];
    const int tid  = threadIdx.x;
    const int row0 = blockIdx.y * BM;
    const int col0 = blockIdx.x * BN;
    const int KV   = BK/4;
    const int arow = tid / KV;
    const int ak   = (tid % KV) * 4;
    const int ty = tid >> 4, tx = tid & 15;

    float acc[TM][TN];
#pragma unroll
    for (int i=0;i<TM;i++)
#pragma unroll
        for (int j=0;j<TN;j++) acc[i][j]=0.f;

    for (int k0 = 0; k0 < K; k0 += BK){
        float4 a4 = make_float4(0.f,0.f,0.f,0.f);
        float4 b4 = make_float4(0.f,0.f,0.f,0.f);
        int ar = row0 + arow;
        if (ar < M) a4 = *(const float4*)(A  + (size_t)ar*lda + k0 + ak);
        int br = col0 + arow;
        if (br < N) b4 = *(const float4*)(Bm + (size_t)br*ldb + k0 + ak);
        As[ak+0][arow]=a4.x; As[ak+1][arow]=a4.y; As[ak+2][arow]=a4.z; As[ak+3][arow]=a4.w;
        Bs[ak+0][arow]=b4.x; Bs[ak+1][arow]=b4.y; Bs[ak+2][arow]=b4.z; Bs[ak+3][arow]=b4.w;
        __syncthreads();
#pragma unroll
        for (int kk=0; kk<BK; kk++){
            float ra[TM], rb[TN];
#pragma unroll
            for (int i=0;i<TM;i+=4) *(float4*)&ra[i] = *(const float4*)&As[kk][ty*TM+i];
#pragma unroll
            for (int j=0;j<TN;j+=4) *(float4*)&rb[j] = *(const float4*)&Bs[kk][tx*TN+j];
#pragma unroll
            for (int i=0;i<TM;i++)
#pragma unroll
                for (int j=0;j<TN;j++) acc[i][j] = fmaf(ra[i], rb[j], acc[i][j]);
        }
        __syncthreads();
    }
#pragma unroll
    for (int i=0;i<TM;i++){
        int r = row0 + ty*TM + i;
        if (r >= M) continue;
#pragma unroll
        for (int j=0;j<TN;j++){
            int cidx = col0 + tx*TN + j;
            if (cidx >= N) continue;
            float v = acc[i][j];
            if (MODE==1) v += bias1[cidx] + bias2[cidx];
            else if (MODE==3) v = fmaxf(v + bias1[cidx], 0.f);
            else if (MODE==4) v += bias1[cidx];
            C[(size_t)r*ldc + cidx] = v;
        }
    }
}

// ---------------- LSTM elementwise (adds xW + Gt gathered rows) ---------------
__global__ void __launch_bounds__(256) lstm_kernel(int cur){
    int r = blockIdx.x, tid = threadIdx.x;
    int b = r & 63, pv = d_prev[r];
    const float* gr = d_gates + (size_t)r*G4;
    const float* xw = d_xW    + (size_t)b*G4;
    const float* gt = d_Gt    + (size_t)pv*G4;
    for (int hh = tid; hh < HH; hh += 256){
        float ig = gr[hh]        + xw[hh]        + gt[hh];
        float fg = gr[HH+hh]     + xw[HH+hh]     + gt[HH+hh];
        float gg = gr[2*HH+hh]   + xw[2*HH+hh]   + gt[2*HH+hh];
        float og = gr[3*HH+hh]   + xw[3*HH+hh]   + gt[3*HH+hh];
        float cold = d_c[cur][(size_t)r*HH + hh];
        float cn = sigmoidf(fg)*cold + sigmoidf(ig)*tanhf(gg);
        d_ctmp[(size_t)r*HH + hh] = cn;
        d_htmp[(size_t)r*HH + hh] = sigmoidf(og)*tanhf(cn);
    }
}

// ---------------- per-row softmax + entropy + gumbel-with-max -----------------
__global__ void __launch_bounds__(128) rowsoft_kernel(const float* __restrict__ gu,
                                                      int t, int cur){
    int r = blockIdx.x, tid = threadIdx.x;
    __shared__ float red[128];
    float* lp = d_lp + (size_t)r*VV;

    float m = -INFINITY;
    for (int v=tid; v<VV; v+=128) m = fmaxf(m, lp[v]);
    red[tid]=m; __syncthreads();
    for (int off=64; off>0; off>>=1){ if(tid<off) red[tid]=fmaxf(red[tid],red[tid+off]); __syncthreads(); }
    m = red[0]; __syncthreads();

    float s = 0.f;
    for (int v=tid; v<VV; v+=128) s += expf(lp[v]-m);
    red[tid]=s; __syncthreads();
    for (int off=64; off>0; off>>=1){ if(tid<off) red[tid]+=red[tid+off]; __syncthreads(); }
    float lse = m + logf(red[0]); __syncthreads();

    float ent = 0.f;
    for (int v=tid; v<VV; v+=128){
        float l = lp[v]-lse; lp[v] = l; ent += l*expf(l);
    }
    red[tid]=ent; __syncthreads();
    for (int off=64; off>0; off>>=1){ if(tid<off) red[tid]+=red[tid+off]; __syncthreads(); }
    if (tid==0) d_entrow[r] = red[0];
    __syncthreads();

    float lpr = d_logp[cur][r];
    float Gr  = d_Gmx[cur][r];
    const float* u = gu + ((size_t)t*RR + r)*VV;
    float zm = -INFINITY;
    for (int v=tid; v<VV; v+=128){
        float gmb = -logf(-logf(u[v]*(1.f-2e-7f)+1e-7f));
        float gph = lp[v] + lpr + gmb;
        d_gm[(size_t)r*VV+v] = gph;
        zm = fmaxf(zm, gph);
    }
    red[tid]=zm; __syncthreads();
    for (int off=64; off>0; off>>=1){ if(tid<off) red[tid]=fmaxf(red[tid],red[tid+off]); __syncthreads(); }
    float Z = red[0]; __syncthreads();

    for (int v=tid; v<VV; v+=128){
        float gph = d_gm[(size_t)r*VV+v];
        float vv = Gr - gph + log1mexp(gph - Z);
        d_gm[(size_t)r*VV+v] = Gr - fmaxf(vv,0.f) - log1pf(expf(-fabsf(vv)));
    }
}

// ---------------- per-batch top-k (jax-stable: value desc, index asc) ---------
__global__ void __launch_bounds__(256) topk_kernel(int t, int cur){
    __shared__ float vals[KB*VV];
    __shared__ float rv[256];
    __shared__ int   ri[256];
    int i = blockIdx.x, tid = threadIdx.x;
    int nxt = cur^1;
    for (int idx = tid; idx < KB*VV; idx += 256){
        int j = idx / VV, v = idx - j*VV;
        float val = d_gm[(size_t)(j*BB + i)*VV + v];
        if (t == 0 && j > 0) val = -INFINITY;
        vals[idx] = val;
    }
    __syncthreads();
    for (int round=0; round<KB; round++){
        float bv = -INFINITY; int bi = 0x7fffffff;
        for (int idx=tid; idx<KB*VV; idx+=256){
            float v = vals[idx];
            if (v > bv || (v == bv && idx < bi)){ bv=v; bi=idx; }
        }
        rv[tid]=bv; ri[tid]=bi; __syncthreads();
        for (int off=128; off>0; off>>=1){
            if (tid<off){
                if (rv[tid+off] > rv[tid] || (rv[tid+off]==rv[tid] && ri[tid+off]<ri[tid])){
                    rv[tid]=rv[tid+off]; ri[tid]=ri[tid+off];
                }
            }
            __syncthreads();
        }
        if (tid==0){
            int widx = ri[0]; float wval = rv[0];
            int j = widx / VV, v = widx - j*VV;
            int rnew = round*BB + i;
            d_Gmx[nxt][rnew] = wval;
            d_snew[rnew]     = v;
            d_order[rnew]    = j*BB + i;
            vals[widx] = -INFINITY;
        }
        __syncthreads();
    }
}

// ---------------- gather scalar per-row state ---------------------------------
__global__ void gather_kernel(int t, int cur){
    int r = blockIdx.x*blockDim.x + threadIdx.x;
    if (r >= RR) return;
    int nxt = cur^1;
    int o = d_order[r], s = d_snew[r];
    float lpv = d_lp[(size_t)o*VV + s];
    float nl = d_logp[cur][o] + lpv;
    d_logp[nxt][r] = nl;
#pragma unroll
    for (int tt=0; tt<LL; tt++){
        d_samples[nxt][r*LL+tt] = d_samples[cur][o*LL+tt];
        d_outputs[nxt][r*LL+tt] = d_outputs[cur][o*LL+tt];
    }
    d_samples[nxt][r*LL+t] = (float)s;
    d_outputs[nxt][r*LL+t] = lpv;
    d_prev[r] = s;
    int i = r & 63, j = r >> 6;
    d_phik[i*KB + j]     = nl;
    d_entbeams[i*KB + j] = d_entrow[o];
}

// ---------------- gather h/c rows ----------------------------------------------
__global__ void __launch_bounds__(256) gather_hc(int cur){
    int r = blockIdx.x, tid = threadIdx.x, nxt = cur^1;
    int o = d_order[r];
    const float4* hs = (const float4*)(d_htmp + (size_t)o*HH);
    const float4* cs = (const float4*)(d_ctmp + (size_t)o*HH);
    float4* hdst = (float4*)(d_h[nxt] + (size_t)r*HH);
    float4* cdst = (float4*)(d_c[nxt] + (size_t)r*HH);
    hdst[tid] = hs[tid];
    cdst[tid] = cs[tid];
}

// ---------------- compute_log_R + entropy accumulation -------------------------
__device__ float block_lse(const float* __restrict__ b,
                           const float* __restrict__ t1,
                           const float* __restrict__ t2,
                           float* rm, float* rs){
    int tid = threadIdx.x;
    float m = -INFINITY, s = 0.f;
    for (int n = tid; n < NP; n += 256){
        float x = b[n];
        if (t1) x -= t1[n];
        if (t2) x -= t2[n];
        if (x > m){ s = s*expf(m-x) + 1.f; m = x; } else s += expf(x-m);
    }
    __syncthreads();     // protect reduction arrays from previous call
    rm[tid]=m; rs[tid]=s; __syncthreads();
    for (int off=128; off>0; off>>=1){
        if (tid < off){
            float m1=rm[tid], s1=rs[tid], m2=rm[tid+off], s2=rs[tid+off];
            float mm = fmaxf(m1,m2);
            rs[tid] = s1*expf(m1-mm) + s2*expf(m2-mm);
            rm[tid] = mm;
        }
        __syncthreads();
    }
    return rm[0] + logf(rs[0]);
}

__global__ void __launch_bounds__(256) logR_kernel(){
    __shared__ float Ts[KB][NP];
    __shared__ float base_s[NP];
    __shared__ float red_m[256], red_s[256];
    int i = blockIdx.x, tid = threadIdx.x;

    float phi[KB], p[KB], pS = 0.f;
#pragma unroll
    for (int j=0;j<KB;j++){ phi[j] = d_phik[i*KB+j]; p[j] = expf(phi[j]); pS += p[j]; }

    for (int n = tid; n < NP; n += 256){
        float lu = logf(((float)n + 0.5f) / (float)NP);
        float bsum = -pS * lu;
#pragma unroll
        for (int j=0;j<KB;j++){
            float x = log1mexp(p[j]*lu);
            Ts[j][n] = x;
            bsum += x;
        }
        base_s[n] = bsum;
    }
    __syncthreads();

    const float logN = logf((float)NP);
    float logI = block_lse(base_s, nullptr, nullptr, red_m, red_s) - logN;
    float logIs[KB];
#pragma unroll
    for (int j=0;j<KB;j++)
        logIs[j] = block_lse(base_s, Ts[j], nullptr, red_m, red_s) - logN;
    if (tid < KB) d_logRs[i*KB+tid] = logIs[tid] - logI;

    for (int a=0;a<KB;a++){
        for (int b=a+1;b<KB;b++){
            float lss = block_lse(base_s, Ts[a], Ts[b], red_m, red_s) - logN;
            if (tid==0){
                d_logRss[i*64 + a*8 + b] = lss - logIs[a];
                d_logRss[i*64 + b*8 + a] = lss - logIs[b];
            }
        }
    }
    if (tid==0){
#pragma unroll
        for (int j=0;j<KB;j++) d_logRss[i*64 + j*8 + j] = 0.f;
        float Wsum = 0.f, ws = 0.f;
#pragma unroll
        for (int j=0;j<KB;j++){
            float w = expf(phi[j] + (logIs[j]-logI));
            Wsum += w;
            ws   += w * d_entbeams[i*KB+j];
        }
        d_entplot[i] += ws;
        d_entelem[i] += ws / Wsum;
    }
}

// ---------------- assemble output tuple ---------------------------------------
__global__ void finalize_kernel(float* __restrict__ out, int out_size){
    int idx = blockIdx.x*blockDim.x + threadIdx.x;
    if (idx >= out_size || idx >= 18560) return;
    const int FIN = LL & 1;  // final buffer = 1
    if (idx < 6656){
        int i = idx/104, rem = idx%104, j = rem/13, tt = rem%13;
        out[idx] = d_outputs[FIN][(j*BB+i)*LL + tt];
    } else if (idx < 13312){
        int q = idx - 6656;
        int i = q/104, rem = q%104, j = rem/13, tt = rem%13;
        out[idx] = d_samples[FIN][(j*BB+i)*LL + tt];
    } else if (idx < 13376){
        out[idx] = d_entelem[idx-13312];
    } else if (idx < 13888){
        out[idx] = d_logRs[idx-13376];
    } else if (idx < 17984){
        out[idx] = d_logRss[idx-13888];
    } else if (idx < 18496){
        out[idx] = d_phik[idx-17984];
    } else {
        out[idx] = d_entplot[idx-18496];
    }
}

// ---------------- host driver ---------------------------------------------------
extern "C" void kernel_launch(void* const* d_in, const int* in_sizes, int n_in,
                              void* d_out, int out_size){
    const float* x_feat  = (const float*)d_in[0];
    const float* W_in_op = (const float*)d_in[1];
    const float* b_in_op = (const float*)d_in[2];
    const float* W_ih    = (const float*)d_in[3];
    const float* W_hh    = (const float*)d_in[4];
    const float* b_ih    = (const float*)d_in[5];
    const float* b_hh    = (const float*)d_in[6];
    const float* W_fc1   = (const float*)d_in[7];
    const float* b_fc1   = (const float*)d_in[8];
    const float* W_out   = (const float*)d_in[9];
    const float* b_out   = (const float*)d_in[10];
    const float* gu      = (const float*)d_in[11];
    (void)in_sizes; (void)n_in;

    void* tmp;
    cudaGetSymbolAddress(&tmp, d_h);     float* p_h    = (float*)tmp;
    cudaGetSymbolAddress(&tmp, d_htmp);  float* p_htmp = (float*)tmp;
    cudaGetSymbolAddress(&tmp, d_xW);    float* p_xW   = (float*)tmp;
    cudaGetSymbolAddress(&tmp, d_E);     float* p_E    = (float*)tmp;
    cudaGetSymbolAddress(&tmp, d_Gt);    float* p_Gt   = (float*)tmp;
    cudaGetSymbolAddress(&tmp, d_gates); float* p_gates= (float*)tmp;
    cudaGetSymbolAddress(&tmp, d_hd);    float* p_hd   = (float*)tmp;
    cudaGetSymbolAddress(&tmp, d_lp);    float* p_lp   = (float*)tmp;

    init_kernel<<<256,256>>>(W_in_op, b_in_op);

    // xW = x_feat @ W_ih[:, :1024]^T + b_ih + b_hh    (64 x 4096)
    gemm_nt<64,64,16,4,4,1><<<dim3(64,1),256>>>(
        x_feat,1024, W_ih,1152, p_xW,G4, BB,G4,1024, b_ih, b_hh);
    // Gt = E @ W_ih[:, 1024:]^T                        (401 x 4096)
    gemm_nt<64,64,16,4,4,0><<<dim3(64,7),256>>>(
        p_E,128, W_ih+1024,1152, p_Gt,G4, V1,G4,128, nullptr, nullptr);

    for (int t = 0; t < LL; t++){
        int cur = t & 1;
        // gates_raw = h @ W_hh^T  (512 x 4096 x 1024); xW/Gt added in lstm
        gemm_nt<128,128,8,8,8,0><<<dim3(32,4),256>>>(
            p_h + (size_t)cur*RR*HH,1024, W_hh,1024, p_gates,G4,
            RR,G4,1024, nullptr, nullptr);
        lstm_kernel<<<RR,256>>>(cur);
        // hd = relu(h_new @ W_fc1^T + b_fc1)           (512 x 1024 x 1024)
        gemm_nt<128,128,8,8,8,3><<<dim3(8,4),256>>>(
            p_htmp,1024, W_fc1,1024, p_hd,HH, RR,HH,1024, b_fc1, nullptr);
        // logits = hd @ W_out^T + b_out                (512 x 400 x 1024)
        gemm_nt<64,64,16,4,4,4><<<dim3(7,8),256>>>(
            p_hd,1024, W_out,1024, p_lp,VV, RR,VV,1024, b_out, nullptr);
        rowsoft_kernel<<<RR,128>>>(gu, t, cur);
        topk_kernel<<<BB,256>>>(t, cur);
        gather_kernel<<<2,256>>>(t, cur);
        gather_hc<<<RR,256>>>(cur);
        logR_kernel<<<BB,256>>>();
    }

    finalize_kernel<<<(18560+255)/256,256>>>((float*)d_out, out_size);
}

// round 2
// speedup vs baseline: 1.8665x; 1.8665x over previous
#include <cuda_runtime.h>
#include <math.h>
#include <stdint.h>

#define BB 64      // batch
#define KB 8       // beams
#define RR 512     // BB*KB
#define HH 1024    // hidden
#define VV 400     // vocab
#define V1 401
#define LL 13      // program_len
#define G4 4096    // 4*HH
#define NP 1000    // log_R quadrature points

// ---------------- persistent scratch -----------------------------------------
__device__ float d_ht[2][RR*HH];     // h double buffer (per-step parity)
__device__ float d_ct[2][RR*HH];     // c double buffer
__device__ float d_Gmx[2][RR];
__device__ float d_logp[2][RR];
__device__ int   d_prev[RR];         // sampled token per (current) row
__device__ int   d_order[RR];        // parent row per (current) row
__device__ float d_samples[2][RR*LL];
__device__ float d_outputs[2][RR*LL];
__device__ float d_entplot[BB];
__device__ float d_entelem[BB];
__device__ float d_xW[BB*G4];        // x_feat @ W_ih[:, :1024]^T + b_ih + b_hh (gate-major)
__device__ float d_xW2[BB*G4];       // interleaved (4h+g)
__device__ float d_E[V1*128];        // relu(W_in_op col s + b)
__device__ float d_Gt[V1*G4];        // E @ W_ih[:,1024:]^T (gate-major)
__device__ float d_Gt2[V1*G4];       // interleaved
__device__ float d_Whh2[G4*HH];      // W_hh rows reordered to (4h+g)
__device__ float d_hd[RR*HH];
__device__ float d_lp[RR*VV];        // logits -> normalized log_probs (in place)
__device__ float d_phik[BB*KB];
__device__ float d_logRs[BB*KB];
__device__ float d_logRss[BB*KB*KB];

// ---------------- helpers ------------------------------------------------------
__device__ __forceinline__ float sigmoidf(float x){ return 1.f/(1.f+expf(-x)); }

__device__ __forceinline__ float log1mexp(float x){
    x = fminf(x, -1e-38f);
    if (x > -0.6931472f) return logf(-expm1f(x));
    return log1pf(-expf(x));
}

// ---------------- init ----------------------------------------------------------
__global__ void init_kernel(const float* __restrict__ W_in_op,
                            const float* __restrict__ b_in_op){
    int idx = blockIdx.x*blockDim.x + threadIdx.x;
    int stride = gridDim.x*blockDim.x;
    for (int i = idx; i < RR;    i += stride){ d_Gmx[0][i]=0.f; d_logp[0][i]=0.f; }
    for (int i = idx; i < RR*LL; i += stride){ d_samples[0][i]=0.f; d_outputs[0][i]=0.f; }
    for (int i = idx; i < BB;    i += stride){ d_entplot[i]=0.f; d_entelem[i]=0.f; }
    for (int i = idx; i < V1*128; i += stride){
        int s = i >> 7, m = i & 127;
        d_E[i] = fmaxf(W_in_op[m*V1 + s] + b_in_op[m], 0.f);
    }
}

__global__ void reorder_whh(const float* __restrict__ W){
    int idx = blockIdx.x*blockDim.x + threadIdx.x;     // over 4096*1024
    if (idx >= G4*HH) return;
    int c = idx >> 10, k = idx & 1023;
    int h = c >> 2, g = c & 3;
    d_Whh2[idx] = W[(size_t)(g*HH + h)*HH + k];
}

// permute gate-major (g*1024+h) -> interleaved (4h+g) for xW and Gt
__global__ void permute_gates(){
    int idx = blockIdx.x*blockDim.x + threadIdx.x;     // over (BB+V1)*4096
    if (idx >= (BB+V1)*G4) return;
    int row = idx / G4, c = idx - row*G4;              // c = g*1024+h (src col)
    int g = c >> 10, h = c & 1023;
    int dstc = 4*h + g;
    if (row < BB) d_xW2[row*G4 + dstc] = d_xW[idx];
    else          d_Gt2[(row-BB)*G4 + dstc] = d_Gt[idx - BB*G4];
}

// ---------------- t=0 LSTM (h=0, c=0, prev token = VV) ---------------------------
__global__ void __launch_bounds__(256) lstm0(float* __restrict__ h0, float* __restrict__ c0){
    int r = blockIdx.x, tid = threadIdx.x;
    int b = r & 63;
    for (int u = tid; u < HH; u += 256){
        float4 xw = *(const float4*)&d_xW2[(size_t)b*G4 + u*4];
        float4 gt = *(const float4*)&d_Gt2[(size_t)VV*G4 + u*4];
        float ig = xw.x+gt.x, gg = xw.z+gt.z, og = xw.w+gt.w;
        float cn = sigmoidf(ig)*tanhf(gg);
        c0[(size_t)r*HH+u] = cn;
        h0[(size_t)r*HH+u] = sigmoidf(og)*tanhf(cn);
    }
}

// ---------------- gates GEMM + fused LSTM (128x128x16, 512 thr, double buffered) --
// A rows gathered via d_order; B = W_hh2 (interleaved); epilogue does LSTM.
__global__ void __launch_bounds__(512) gemm_gates(
    const float* __restrict__ hprev, const float* __restrict__ cprev,
    float* __restrict__ hcur, float* __restrict__ ccur,
    const float* __restrict__ Bw)
{
    __shared__ float As[2][16][128+4];
    __shared__ float Bs[2][16][128+4];
    __shared__ int ord_s[128];
    const int tid = threadIdx.x;
    const int row0 = blockIdx.y*128, col0 = blockIdx.x*128;
    if (tid < 128) ord_s[tid] = d_order[row0 + tid];
    const int arow = tid >> 2, ak = (tid & 3)*4;
    const int ty = tid >> 4, tx = tid & 15;   // ty 0..31, tx 0..15
    __syncthreads();

    const float* Arow = hprev + (size_t)ord_s[arow]*HH + ak;
    const float* Brow = Bw   + (size_t)(col0+arow)*HH + ak;
    float4 a4 = *(const float4*)(Arow);
    float4 b4 = *(const float4*)(Brow);
    As[0][ak+0][arow]=a4.x; As[0][ak+1][arow]=a4.y; As[0][ak+2][arow]=a4.z; As[0][ak+3][arow]=a4.w;
    Bs[0][ak+0][arow]=b4.x; Bs[0][ak+1][arow]=b4.y; Bs[0][ak+2][arow]=b4.z; Bs[0][ak+3][arow]=b4.w;
    __syncthreads();

    float acc[4][8];
#pragma unroll
    for (int i=0;i<4;i++)
#pragma unroll
        for (int j=0;j<8;j++) acc[i][j]=0.f;

    const int NT = HH/16;
    for (int it = 0; it < NT; it++){
        int cur = it & 1;
        float4 a4n, b4n;
        if (it+1 < NT){
            a4n = *(const float4*)(Arow + (it+1)*16);
            b4n = *(const float4*)(Brow + (it+1)*16);
        }
#pragma unroll
        for (int kk=0; kk<16; kk++){
            float4 ra  = *(const float4*)&As[cur][kk][ty*4];
            float4 rb0 = *(const float4*)&Bs[cur][kk][tx*4];
            float4 rb1 = *(const float4*)&Bs[cur][kk][64+tx*4];
            float r[4]={ra.x,ra.y,ra.z,ra.w};
            float cb[8]={rb0.x,rb0.y,rb0.z,rb0.w,rb1.x,rb1.y,rb1.z,rb1.w};
#pragma unroll
            for (int i=0;i<4;i++)
#pragma unroll
                for (int j=0;j<8;j++) acc[i][j] = fmaf(r[i], cb[j], acc[i][j]);
        }
        if (it+1 < NT){
            int nb = cur^1;
            As[nb][ak+0][arow]=a4n.x; As[nb][ak+1][arow]=a4n.y; As[nb][ak+2][arow]=a4n.z; As[nb][ak+3][arow]=a4n.w;
            Bs[nb][ak+0][arow]=b4n.x; Bs[nb][ak+1][arow]=b4n.y; Bs[nb][ak+2][arow]=b4n.z; Bs[nb][ak+3][arow]=b4n.w;
        }
        __syncthreads();
    }

    // epilogue: cols group A = col0+tx*4.. (+3), group B = col0+64+tx*4.. => hidden units
    const int uA = (col0 >> 2) + tx;
    const int uB = uA + 16;
#pragma unroll
    for (int i=0;i<4;i++){
        int r_ = row0 + ty*4 + i;
        int b  = r_ & 63;
        int pv = d_prev[r_];
        int o  = ord_s[ty*4 + i];
        float4 xwA = *(const float4*)&d_xW2[(size_t)b*G4 + col0 + tx*4];
        float4 gtA = *(const float4*)&d_Gt2[(size_t)pv*G4 + col0 + tx*4];
        float4 xwB = *(const float4*)&d_xW2[(size_t)b*G4 + col0 + 64 + tx*4];
        float4 gtB = *(const float4*)&d_Gt2[(size_t)pv*G4 + col0 + 64 + tx*4];
        {
            float ig = acc[i][0]+xwA.x+gtA.x;
            float fg = acc[i][1]+xwA.y+gtA.y;
            float gg = acc[i][2]+xwA.z+gtA.z;
            float og = acc[i][3]+xwA.w+gtA.w;
            float cold = cprev[(size_t)o*HH + uA];
            float cn = sigmoidf(fg)*cold + sigmoidf(ig)*tanhf(gg);
            ccur[(size_t)r_*HH + uA] = cn;
            hcur[(size_t)r_*HH + uA] = sigmoidf(og)*tanhf(cn);
        }
        {
            float ig = acc[i][4]+xwB.x+gtB.x;
            float fg = acc[i][5]+xwB.y+gtB.y;
            float gg = acc[i][6]+xwB.z+gtB.z;
            float og = acc[i][7]+xwB.w+gtB.w;
            float cold = cprev[(size_t)o*HH + uB];
            float cn = sigmoidf(fg)*cold + sigmoidf(ig)*tanhf(gg);
            ccur[(size_t)r_*HH + uB] = cn;
            hcur[(size_t)r_*HH + uB] = sigmoidf(og)*tanhf(cn);
        }
    }
}

// ---------------- generic 64x64x16 double-buffered NT GEMM -----------------------
// MODE: 0 none, 1 +bias1+bias2, 3 relu(+bias1), 4 +bias1
template<int MODE>
__global__ void __launch_bounds__(256) gemm_db(
    const float* __restrict__ A, int lda,
    const float* __restrict__ B, int ldb,
    float* __restrict__ C, int ldc,
    int M, int N, int K,
    const float* __restrict__ bias1,
    const float* __restrict__ bias2)
{
    __shared__ float As[2][16][64+4];
    __shared__ float Bs[2][16][64+4];
    const int tid = threadIdx.x;
    const int row0 = blockIdx.y*64, col0 = blockIdx.x*64;
    const int arow = tid >> 2, ak = (tid & 3)*4;
    const int ty = tid >> 4, tx = tid & 15;

    const int ar = row0 + arow;
    const int br = col0 + arow;
    float4 a4 = make_float4(0,0,0,0), b4 = make_float4(0,0,0,0);
    if (ar < M) a4 = *(const float4*)(A + (size_t)ar*lda + ak);
    if (br < N) b4 = *(const float4*)(B + (size_t)br*ldb + ak);
    As[0][ak+0][arow]=a4.x; As[0][ak+1][arow]=a4.y; As[0][ak+2][arow]=a4.z; As[0][ak+3][arow]=a4.w;
    Bs[0][ak+0][arow]=b4.x; Bs[0][ak+1][arow]=b4.y; Bs[0][ak+2][arow]=b4.z; Bs[0][ak+3][arow]=b4.w;
    __syncthreads();

    float acc[4][4];
#pragma unroll
    for (int i=0;i<4;i++)
#pragma unroll
        for (int j=0;j<4;j++) acc[i][j]=0.f;

    const int NT = K/16;
    for (int it=0; it<NT; it++){
        int cur = it & 1;
        float4 a4n, b4n;
        if (it+1 < NT){
            int k0 = (it+1)*16;
            a4n = make_float4(0,0,0,0); b4n = make_float4(0,0,0,0);
            if (ar < M) a4n = *(const float4*)(A + (size_t)ar*lda + k0 + ak);
            if (br < N) b4n = *(const float4*)(B + (size_t)br*ldb + k0 + ak);
        }
#pragma unroll
        for (int kk=0; kk<16; kk++){
            float4 ra = *(const float4*)&As[cur][kk][ty*4];
            float4 rb = *(const float4*)&Bs[cur][kk][tx*4];
            float r[4]={ra.x,ra.y,ra.z,ra.w};
            float cb[4]={rb.x,rb.y,rb.z,rb.w};
#pragma unroll
            for (int i=0;i<4;i++)
#pragma unroll
                for (int j=0;j<4;j++) acc[i][j] = fmaf(r[i], cb[j], acc[i][j]);
        }
        if (it+1 < NT){
            int nb = cur^1;
            As[nb][ak+0][arow]=a4n.x; As[nb][ak+1][arow]=a4n.y; As[nb][ak+2][arow]=a4n.z; As[nb][ak+3][arow]=a4n.w;
            Bs[nb][ak+0][arow]=b4n.x; Bs[nb][ak+1][arow]=b4n.y; Bs[nb][ak+2][arow]=b4n.z; Bs[nb][ak+3][arow]=b4n.w;
        }
        __syncthreads();
    }
#pragma unroll
    for (int i=0;i<4;i++){
        int r = row0 + ty*4 + i;
        if (r >= M) continue;
#pragma unroll
        for (int j=0;j<4;j++){
            int c = col0 + tx*4 + j;
            if (c >= N) continue;
            float v = acc[i][j];
            if (MODE==1) v += bias1[c] + bias2[c];
            else if (MODE==3) v = fmaxf(v + bias1[c], 0.f);
            else if (MODE==4) v += bias1[c];
            C[(size_t)r*ldc + c] = v;
        }
    }
}

// ---------------- warp LSE over NP points of base(-t1)(-t2) ----------------------
__device__ __forceinline__ float warpLSE(const float* __restrict__ base,
                                         const float* __restrict__ t1,
                                         const float* __restrict__ t2){
    int lane = threadIdx.x & 31;
    float m = -INFINITY, s = 0.f;
    for (int n = lane; n < NP; n += 32){
        float x = base[n];
        if (t1) x -= t1[n];
        if (t2) x -= t2[n];
        if (x > m){ s = s*expf(m-x) + 1.f; m = x; } else s += expf(x-m);
    }
#pragma unroll
    for (int off=16; off; off>>=1){
        float m2 = __shfl_xor_sync(0xffffffffu, m, off);
        float s2 = __shfl_xor_sync(0xffffffffu, s, off);
        float mm = fmaxf(m, m2);
        s = s*expf(m-mm) + s2*expf(m2-mm);
        m = mm;
    }
    return m + logf(s);
}

// ---------------- fused select: softmax+gumbel+topk+gather+logR (per batch elem) --
__global__ void __launch_bounds__(256) select_kernel(const float* __restrict__ gu,
                                                     int t, int cur){
    __shared__ float pool[KB*NP + NP];   // gm[8][400] then Ts[8][1000]+base[1000]
    __shared__ float rv[256];
    __shared__ int   ri[256];
    __shared__ float entS[KB], phiS[KB], gvalS[KB], logIs_s[KB+1];
    __shared__ int   ordS[KB], snewS[KB];

    const int i = blockIdx.x, tid = threadIdx.x;
    const int lane = tid & 31, w = tid >> 5;
    float (*gm)[VV] = (float(*)[VV])pool;

    // ---- per-warp: softmax + entropy + gumbel-with-max for row r = w*64+i ----
    const int r = w*BB + i;
    float* lp = d_lp + (size_t)r*VV;
    float m = -INFINITY;
    for (int v=lane; v<VV; v+=32) m = fmaxf(m, lp[v]);
#pragma unroll
    for (int off=16; off; off>>=1) m = fmaxf(m, __shfl_xor_sync(0xffffffffu, m, off));
    float s = 0.f;
    for (int v=lane; v<VV; v+=32) s += expf(lp[v]-m);
#pragma unroll
    for (int off=16; off; off>>=1) s += __shfl_xor_sync(0xffffffffu, s, off);
    float lse = m + logf(s);

    float lpr = d_logp[cur][r];
    float Gr  = d_Gmx[cur][r];
    const float* u = gu + ((size_t)t*RR + r)*VV;
    float ent = 0.f, zm = -INFINITY;
    for (int v=lane; v<VV; v+=32){
        float l = lp[v]-lse; lp[v] = l; ent += l*expf(l);
        float gmb = -logf(-logf(u[v]*(1.f-2e-7f)+1e-7f));
        float gph = l + lpr + gmb;
        gm[w][v] = gph;
        zm = fmaxf(zm, gph);
    }
#pragma unroll
    for (int off=16; off; off>>=1){
        ent += __shfl_xor_sync(0xffffffffu, ent, off);
        zm = fmaxf(zm, __shfl_xor_sync(0xffffffffu, zm, off));
    }
    if (lane==0) entS[w] = ent;
    for (int v=lane; v<VV; v+=32){
        float gph = gm[w][v];
        float vv = Gr - gph + log1mexp(gph - zm);
        float val = Gr - fmaxf(vv,0.f) - log1pf(expf(-fabsf(vv)));
        gm[w][v] = (t==0 && w>0) ? -INFINITY : val;
    }
    __syncthreads();

    // ---- top-k (jax-stable: value desc, flat-index asc; flat idx = beam*400+v) ----
    for (int round=0; round<KB; round++){
        float bv = -INFINITY; int bi = 0x7fffffff;
        for (int idx=tid; idx<KB*VV; idx+=256){
            float v = pool[idx];
            if (v > bv || (v == bv && idx < bi)){ bv=v; bi=idx; }
        }
        rv[tid]=bv; ri[tid]=bi; __syncthreads();
        for (int off=128; off; off>>=1){
            if (tid < off){
                if (rv[tid+off] > rv[tid] || (rv[tid+off]==rv[tid] && ri[tid+off]<ri[tid])){
                    rv[tid]=rv[tid+off]; ri[tid]=ri[tid+off];
                }
            }
            __syncthreads();
        }
        if (tid==0){
            int widx = ri[0]; int j = widx/VV, v = widx - j*VV;
            gvalS[round]=rv[0]; ordS[round]=j; snewS[round]=v;
            pool[widx] = -INFINITY;
        }
        __syncthreads();
    }

    // ---- gather (rows j*64+i owned by this block) ----
    const int nxt = cur^1;
    for (int idx=tid; idx<KB*LL; idx+=256){
        int j = idx/LL, tt = idx - j*LL;
        if (tt == t) continue;
        int rn = j*BB+i, o = ordS[j]*BB+i;
        d_samples[nxt][rn*LL+tt] = d_samples[cur][o*LL+tt];
        d_outputs[nxt][rn*LL+tt] = d_outputs[cur][o*LL+tt];
    }
    if (tid < KB){
        int j = tid, rn = j*BB+i, o = ordS[j]*BB+i, sv = snewS[j];
        float lpv = d_lp[(size_t)o*VV + sv];
        float nl  = d_logp[cur][o] + lpv;
        d_samples[nxt][rn*LL+t] = (float)sv;
        d_outputs[nxt][rn*LL+t] = lpv;
        d_logp[nxt][rn] = nl;
        d_Gmx[nxt][rn]  = gvalS[j];
        d_prev[rn]  = sv;
        d_order[rn] = o;
        d_phik[i*KB+j] = nl;
        phiS[j] = nl;
    }
    __syncthreads();

    // ---- compute_log_R (warp-parallel LSEs) ----
    float (*Ts)[NP] = (float(*)[NP])pool;
    float* base = pool + KB*NP;
    float p[KB], pS = 0.f;
#pragma unroll
    for (int j=0;j<KB;j++){ p[j] = expf(phiS[j]); pS += p[j]; }
    for (int n=tid; n<NP; n+=256){
        float lu = logf(((float)n + 0.5f)/(float)NP);
        float bs = -pS*lu;
#pragma unroll
        for (int j=0;j<KB;j++){
            float x = log1mexp(p[j]*lu);
            Ts[j][n] = x;
            bs += x;
        }
        base[n] = bs;
    }
    __syncthreads();

    const float logN = logf((float)NP);
    float resA = warpLSE(base, Ts[w], nullptr) - logN;   // w in 0..7
    if (lane==0) logIs_s[w] = resA;
    if (w==0){
        float li = warpLSE(base, nullptr, nullptr) - logN;
        if (lane==0) logIs_s[KB] = li;
    }
    __syncthreads();
    float logI = logIs_s[KB];
    if (tid < KB) d_logRs[i*KB+tid] = logIs_s[tid] - logI;

    for (int pp = w; pp < 28; pp += 8){
        int a = 0, rem = pp;
        while (rem >= 7 - a){ rem -= (7 - a); a++; }
        int b = a + 1 + rem;
        float lss = warpLSE(base, Ts[a], Ts[b]) - logN;
        if (lane==0){
            d_logRss[i*64 + a*8 + b] = lss - logIs_s[a];
            d_logRss[i*64 + b*8 + a] = lss - logIs_s[b];
        }
    }
    if (tid < KB) d_logRss[i*64 + tid*9] = 0.f;
    if (tid == 0){
        float Wsum = 0.f, ws = 0.f;
#pragma unroll
        for (int j=0;j<KB;j++){
            float wq = expf(phiS[j] + logIs_s[j] - logI);
            Wsum += wq;
            ws   += wq * entS[ordS[j]];
        }
        d_entplot[i] += ws;
        d_entelem[i] += ws / Wsum;
    }
}

// ---------------- output assembly ------------------------------------------------
__global__ void finalize_kernel(float* __restrict__ out, int out_size){
    int idx = blockIdx.x*blockDim.x + threadIdx.x;
    if (idx >= out_size || idx >= 18560) return;
    const int FIN = LL & 1;  // = 1
    if (idx < 6656){
        int i = idx/104, rem = idx%104, j = rem/13, tt = rem%13;
        out[idx] = d_outputs[FIN][(j*BB+i)*LL + tt];
    } else if (idx < 13312){
        int q = idx - 6656;
        int i = q/104, rem = q%104, j = rem/13, tt = rem%13;
        out[idx] = d_samples[FIN][(j*BB+i)*LL + tt];
    } else if (idx < 13376){
        out[idx] = d_entelem[idx-13312];
    } else if (idx < 13888){
        out[idx] = d_logRs[idx-13376];
    } else if (idx < 17984){
        out[idx] = d_logRss[idx-13888];
    } else if (idx < 18496){
        out[idx] = d_phik[idx-17984];
    } else {
        out[idx] = d_entplot[idx-18496];
    }
}

// ---------------- host driver ------------------------------------------------------
extern "C" void kernel_launch(void* const* d_in, const int* in_sizes, int n_in,
                              void* d_out, int out_size){
    const float* x_feat  = (const float*)d_in[0];
    const float* W_in_op = (const float*)d_in[1];
    const float* b_in_op = (const float*)d_in[2];
    const float* W_ih    = (const float*)d_in[3];
    const float* W_hh    = (const float*)d_in[4];
    const float* b_ih    = (const float*)d_in[5];
    const float* b_hh    = (const float*)d_in[6];
    const float* W_fc1   = (const float*)d_in[7];
    const float* b_fc1   = (const float*)d_in[8];
    const float* W_out   = (const float*)d_in[9];
    const float* b_out   = (const float*)d_in[10];
    const float* gu      = (const float*)d_in[11];
    (void)in_sizes; (void)n_in;

    void* tmp;
    cudaGetSymbolAddress(&tmp, d_ht);    float* p_ht  = (float*)tmp;
    cudaGetSymbolAddress(&tmp, d_ct);    float* p_ct  = (float*)tmp;
    cudaGetSymbolAddress(&tmp, d_xW);    float* p_xW  = (float*)tmp;
    cudaGetSymbolAddress(&tmp, d_E);     float* p_E   = (float*)tmp;
    cudaGetSymbolAddress(&tmp, d_Gt);    float* p_Gt  = (float*)tmp;
    cudaGetSymbolAddress(&tmp, d_Whh2);  float* p_Wh2 = (float*)tmp;
    cudaGetSymbolAddress(&tmp, d_hd);    float* p_hd  = (float*)tmp;
    cudaGetSymbolAddress(&tmp, d_lp);    float* p_lp  = (float*)tmp;

    init_kernel<<<256,256>>>(W_in_op, b_in_op);
    reorder_whh<<<(G4*HH+255)/256,256>>>(W_hh);

    // xW = x_feat @ W_ih[:, :1024]^T + b_ih + b_hh    (64 x 4096)
    gemm_db<1><<<dim3(64,1),256>>>(x_feat,1024, W_ih,1152, p_xW,G4,
                                   BB,G4,1024, b_ih, b_hh);
    // Gt = E @ W_ih[:, 1024:]^T                        (401 x 4096)
    gemm_db<0><<<dim3(64,7),256>>>(p_E,128, W_ih+1024,1152, p_Gt,G4,
                                   V1,G4,128, nullptr, nullptr);
    permute_gates<<<((BB+V1)*G4+255)/256,256>>>();

    for (int t = 0; t < LL; t++){
        int cur = t & 1;
        float* h_cur = p_ht + (size_t)cur*RR*HH;
        float* c_cur = p_ct + (size_t)cur*RR*HH;
        if (t == 0){
            lstm0<<<RR,256>>>(h_cur, c_cur);
        } else {
            int prv = (t+1) & 1;
            gemm_gates<<<dim3(32,4),512>>>(p_ht + (size_t)prv*RR*HH,
                                           p_ct + (size_t)prv*RR*HH,
                                           h_cur, c_cur, p_Wh2);
        }
        // hd = relu(h_new @ W_fc1^T + b_fc1)
        gemm_db<3><<<dim3(16,8),256>>>(h_cur,1024, W_fc1,1024, p_hd,HH,
                                       RR,HH,1024, b_fc1, nullptr);
        // logits = hd @ W_out^T + b_out
        gemm_db<4><<<dim3(7,8),256>>>(p_hd,1024, W_out,1024, p_lp,VV,
                                      RR,VV,1024, b_out, nullptr);
        select_kernel<<<BB,256>>>(gu, t, cur);
    }

    finalize_kernel<<<(18560+255)/256,256>>>((float*)d_out, out_size);
}

// round 3
// speedup vs baseline: 2.1740x; 1.1648x over previous
#include <cuda_runtime.h>
#include <math.h>
#include <stdint.h>

#define BB 64      // batch
#define KB 8       // beams
#define RR 512     // BB*KB
#define HH 1024    // hidden
#define VV 400     // vocab
#define V1 401
#define LL 13      // program_len
#define G4 4096    // 4*HH
#define NP 1000    // log_R quadrature points
#define SK 4       // split-K slices for fc1/out

typedef unsigned long long ull;

// ---------------- persistent scratch -----------------------------------------
__device__ float d_ht[2][RR*HH];
__device__ float d_ct[2][RR*HH];
__device__ float d_Gmx[2][RR];
__device__ float d_logp[2][RR];
__device__ int   d_prev[RR];
__device__ int   d_order[RR];
__device__ float d_samples[2][RR*LL];
__device__ float d_outputs[2][RR*LL];
__device__ float d_entplot[BB];
__device__ float d_entelem[BB];
__device__ float d_xW[BB*G4];
__device__ float d_xW2[BB*G4];
__device__ float d_E[V1*128];
__device__ float d_Gt[V1*G4];
__device__ float d_Gt2[V1*G4];
__device__ float d_Whh2[G4*HH];
__device__ float d_fc1p[SK][RR*HH];   // fc1 split-K partials (pre-bias, pre-relu)
__device__ float d_lpp[SK][RR*VV];    // out split-K partials (pre-bias)
__device__ float d_lpn[RR*VV];        // normalized log_probs
__device__ float d_phik[BB*KB];
__device__ float d_logRs[BB*KB];
__device__ float d_logRss[BB*KB*KB];

// ---------------- helpers ------------------------------------------------------
__device__ __forceinline__ float sigmoidf(float x){ return 1.f/(1.f+expf(-x)); }

__device__ __forceinline__ float log1mexp(float x){
    x = fminf(x, -1e-38f);
    if (x > -0.6931472f) return logf(-expm1f(x));
    return log1pf(-expf(x));
}

__device__ __forceinline__ ull pkdup(float x){
    ull r; unsigned u = __float_as_uint(x);
    asm("mov.b64 %0, {%1, %1};" : "=l"(r) : "r"(u));
    return r;
}
__device__ __forceinline__ float2 upk2(ull v){
    unsigned lo, hi;
    asm("mov.b64 {%0, %1}, %2;" : "=r"(lo), "=r"(hi) : "l"(v));
    return make_float2(__uint_as_float(lo), __uint_as_float(hi));
}
__device__ __forceinline__ void fma2(ull &c, ull a, ull b){
    asm("fma.rn.f32x2 %0, %1, %2, %0;" : "+l"(c) : "l"(a), "l"(b));
}

// ---------------- init ----------------------------------------------------------
__global__ void init_kernel(const float* __restrict__ W_in_op,
                            const float* __restrict__ b_in_op){
    int idx = blockIdx.x*blockDim.x + threadIdx.x;
    int stride = gridDim.x*blockDim.x;
    for (int i = idx; i < RR;    i += stride){ d_Gmx[0][i]=0.f; d_logp[0][i]=0.f; }
    for (int i = idx; i < RR*LL; i += stride){ d_samples[0][i]=0.f; d_outputs[0][i]=0.f; }
    for (int i = idx; i < BB;    i += stride){ d_entplot[i]=0.f; d_entelem[i]=0.f; }
    for (int i = idx; i < V1*128; i += stride){
        int s = i >> 7, m = i & 127;
        d_E[i] = fmaxf(W_in_op[m*V1 + s] + b_in_op[m], 0.f);
    }
}

__global__ void reorder_whh(const float* __restrict__ W){
    int idx = blockIdx.x*blockDim.x + threadIdx.x;
    if (idx >= G4*HH) return;
    int c = idx >> 10, k = idx & 1023;
    int h = c >> 2, g = c & 3;
    d_Whh2[idx] = W[(size_t)(g*HH + h)*HH + k];
}

__global__ void permute_gates(){
    int idx = blockIdx.x*blockDim.x + threadIdx.x;
    if (idx >= (BB+V1)*G4) return;
    int row = idx / G4, c = idx - row*G4;
    int g = c >> 10, h = c & 1023;
    int dstc = 4*h + g;
    if (row < BB) d_xW2[row*G4 + dstc] = d_xW[idx];
    else          d_Gt2[(row-BB)*G4 + dstc] = d_Gt[idx - BB*G4];
}

// ---------------- t=0 LSTM (h=0,c=0, prev token = VV) -----------------------------
__global__ void __launch_bounds__(256) lstm0(float* __restrict__ h0, float* __restrict__ c0){
    int r = blockIdx.x, tid = threadIdx.x;
    int b = r & 63;
    for (int u = tid; u < HH; u += 256){
        float4 xw = *(const float4*)&d_xW2[(size_t)b*G4 + u*4];
        float4 gt = *(const float4*)&d_Gt2[(size_t)VV*G4 + u*4];
        float ig = xw.x+gt.x, gg = xw.z+gt.z, og = xw.w+gt.w;
        float cn = sigmoidf(ig)*tanhf(gg);
        c0[(size_t)r*HH+u] = cn;
        h0[(size_t)r*HH+u] = sigmoidf(og)*tanhf(cn);
    }
}

// ---------------- setup GEMM (64x64x16 double buffered, scalar) -------------------
template<int MODE>
__global__ void __launch_bounds__(256) gemm_db(
    const float* __restrict__ A, int lda,
    const float* __restrict__ B, int ldb,
    float* __restrict__ C, int ldc,
    int M, int N, int K,
    const float* __restrict__ bias1,
    const float* __restrict__ bias2)
{
    __shared__ float As[2][16][64+4];
    __shared__ float Bs[2][16][64+4];
    const int tid = threadIdx.x;
    const int row0 = blockIdx.y*64, col0 = blockIdx.x*64;
    const int arow = tid >> 2, ak = (tid & 3)*4;
    const int ty = tid >> 4, tx = tid & 15;

    const int ar = row0 + arow, br = col0 + arow;
    float4 a4 = make_float4(0,0,0,0), b4 = make_float4(0,0,0,0);
    if (ar < M) a4 = *(const float4*)(A + (size_t)ar*lda + ak);
    if (br < N) b4 = *(const float4*)(B + (size_t)br*ldb + ak);
    As[0][ak+0][arow]=a4.x; As[0][ak+1][arow]=a4.y; As[0][ak+2][arow]=a4.z; As[0][ak+3][arow]=a4.w;
    Bs[0][ak+0][arow]=b4.x; Bs[0][ak+1][arow]=b4.y; Bs[0][ak+2][arow]=b4.z; Bs[0][ak+3][arow]=b4.w;
    __syncthreads();

    float acc[4][4];
#pragma unroll
    for (int i=0;i<4;i++)
#pragma unroll
        for (int j=0;j<4;j++) acc[i][j]=0.f;

    const int NT = K/16;
    for (int it=0; it<NT; it++){
        int cur = it & 1;
        float4 a4n, b4n;
        if (it+1 < NT){
            int k0 = (it+1)*16;
            a4n = make_float4(0,0,0,0); b4n = make_float4(0,0,0,0);
            if (ar < M) a4n = *(const float4*)(A + (size_t)ar*lda + k0 + ak);
            if (br < N) b4n = *(const float4*)(B + (size_t)br*ldb + k0 + ak);
        }
#pragma unroll
        for (int kk=0; kk<16; kk++){
            float4 ra = *(const float4*)&As[cur][kk][ty*4];
            float4 rb = *(const float4*)&Bs[cur][kk][tx*4];
            float r[4]={ra.x,ra.y,ra.z,ra.w};
            float cb[4]={rb.x,rb.y,rb.z,rb.w};
#pragma unroll
            for (int i=0;i<4;i++)
#pragma unroll
                for (int j=0;j<4;j++) acc[i][j] = fmaf(r[i], cb[j], acc[i][j]);
        }
        if (it+1 < NT){
            int nb = cur^1;
            As[nb][ak+0][arow]=a4n.x; As[nb][ak+1][arow]=a4n.y; As[nb][ak+2][arow]=a4n.z; As[nb][ak+3][arow]=a4n.w;
            Bs[nb][ak+0][arow]=b4n.x; Bs[nb][ak+1][arow]=b4n.y; Bs[nb][ak+2][arow]=b4n.z; Bs[nb][ak+3][arow]=b4n.w;
        }
        __syncthreads();
    }
#pragma unroll
    for (int i=0;i<4;i++){
        int r = row0 + ty*4 + i;
        if (r >= M) continue;
#pragma unroll
        for (int j=0;j<4;j++){
            int c = col0 + tx*4 + j;
            if (c >= N) continue;
            float v = acc[i][j];
            if (MODE==1) v += bias1[c] + bias2[c];
            else if (MODE==3) v = fmaxf(v + bias1[c], 0.f);
            else if (MODE==4) v += bias1[c];
            C[(size_t)r*ldc + c] = v;
        }
    }
}

// ---------------- gates GEMM + fused LSTM (128x128x16, 256 thr, f32x2, dbuf) -----
__global__ void __launch_bounds__(256) gemm_gates_f2(
    const float* __restrict__ hprev, const float* __restrict__ cprev,
    float* __restrict__ hcur, float* __restrict__ ccur,
    const float* __restrict__ Bw)
{
    __shared__ float As[2][16][128+4];
    __shared__ float Bs[2][16][128+4];
    __shared__ int ord_s[128];
    const int tid = threadIdx.x;
    const int row0 = blockIdx.y*128, col0 = blockIdx.x*128;
    if (tid < 128) ord_s[tid] = d_order[row0 + tid];
    const int arow = tid >> 1, ak = (tid & 1)*8;
    const int ty = tid >> 4, tx = tid & 15;
    __syncthreads();

    const float* Arow = hprev + (size_t)ord_s[arow]*HH + ak;
    const float* Brow = Bw   + (size_t)(col0+arow)*HH + ak;

    float4 a0 = *(const float4*)Arow,     a1 = *(const float4*)(Arow+4);
    float4 b0 = *(const float4*)Brow,     b1 = *(const float4*)(Brow+4);
#pragma unroll
    for (int j=0;j<4;j++){
        As[0][ak+j][arow]   = ((const float*)&a0)[j];
        As[0][ak+4+j][arow] = ((const float*)&a1)[j];
        Bs[0][ak+j][arow]   = ((const float*)&b0)[j];
        Bs[0][ak+4+j][arow] = ((const float*)&b1)[j];
    }
    __syncthreads();

    ull acc[8][4];
#pragma unroll
    for (int i=0;i<8;i++)
#pragma unroll
        for (int p=0;p<4;p++) acc[i][p]=0ull;

    const int NT = HH/16;
    for (int it=0; it<NT; it++){
        int cur = it & 1;
        float4 a0n,a1n,b0n,b1n;
        if (it+1 < NT){
            int k0 = (it+1)*16;
            a0n = *(const float4*)(Arow + k0);     a1n = *(const float4*)(Arow + k0 + 4);
            b0n = *(const float4*)(Brow + k0);     b1n = *(const float4*)(Brow + k0 + 4);
        }
#pragma unroll
        for (int kk=0; kk<16; kk++){
            const float* Ar = &As[cur][kk][ty*8];
            const float* Br = &Bs[cur][kk][tx*8];
            float4 af0 = *(const float4*)Ar, af1 = *(const float4*)(Ar+4);
            ulonglong2 bq0 = *(const ulonglong2*)Br;
            ulonglong2 bq1 = *(const ulonglong2*)(Br+4);
            ull bp0=bq0.x, bp1=bq0.y, bp2=bq1.x, bp3=bq1.y;
            float av[8] = {af0.x,af0.y,af0.z,af0.w,af1.x,af1.y,af1.z,af1.w};
#pragma unroll
            for (int i=0;i<8;i++){
                ull ap = pkdup(av[i]);
                fma2(acc[i][0], ap, bp0);
                fma2(acc[i][1], ap, bp1);
                fma2(acc[i][2], ap, bp2);
                fma2(acc[i][3], ap, bp3);
            }
        }
        if (it+1 < NT){
            int nb = cur^1;
#pragma unroll
            for (int j=0;j<4;j++){
                As[nb][ak+j][arow]   = ((const float*)&a0n)[j];
                As[nb][ak+4+j][arow] = ((const float*)&a1n)[j];
                Bs[nb][ak+j][arow]   = ((const float*)&b0n)[j];
                Bs[nb][ak+4+j][arow] = ((const float*)&b1n)[j];
            }
        }
        __syncthreads();
    }

    // epilogue: cols col0+tx*8 .. +7 = gates(i,f,g,o) of hidden units u0, u0+1
    const int u0 = (col0 >> 2) + tx*2;
#pragma unroll
    for (int i=0;i<8;i++){
        int r_ = row0 + ty*8 + i;
        int b  = r_ & 63;
        int pv = d_prev[r_];
        int o  = ord_s[ty*8 + i];
        float4 xw0 = *(const float4*)&d_xW2[(size_t)b*G4  + (u0<<2)];
        float4 gt0 = *(const float4*)&d_Gt2[(size_t)pv*G4 + (u0<<2)];
        float4 xw1 = *(const float4*)&d_xW2[(size_t)b*G4  + (u0<<2) + 4];
        float4 gt1 = *(const float4*)&d_Gt2[(size_t)pv*G4 + (u0<<2) + 4];
        float2 q0 = upk2(acc[i][0]), q1 = upk2(acc[i][1]);
        float2 q2 = upk2(acc[i][2]), q3 = upk2(acc[i][3]);
        {
            float ig = q0.x + xw0.x + gt0.x;
            float fg = q0.y + xw0.y + gt0.y;
            float gg = q1.x + xw0.z + gt0.z;
            float og = q1.y + xw0.w + gt0.w;
            float cold = cprev[(size_t)o*HH + u0];
            float cn = sigmoidf(fg)*cold + sigmoidf(ig)*tanhf(gg);
            ccur[(size_t)r_*HH + u0] = cn;
            hcur[(size_t)r_*HH + u0] = sigmoidf(og)*tanhf(cn);
        }
        {
            float ig = q2.x + xw1.x + gt1.x;
            float fg = q2.y + xw1.y + gt1.y;
            float gg = q3.x + xw1.z + gt1.z;
            float og = q3.y + xw1.w + gt1.w;
            float cold = cprev[(size_t)o*HH + u0 + 1];
            float cn = sigmoidf(fg)*cold + sigmoidf(ig)*tanhf(gg);
            ccur[(size_t)r_*HH + u0 + 1] = cn;
            hcur[(size_t)r_*HH + u0 + 1] = sigmoidf(og)*tanhf(cn);
        }
    }
}

// ---------------- fc1 split-K GEMM (128x128, f32x2): partials, no bias -----------
__global__ void __launch_bounds__(256) gemm_fc1_f2(
    const float* __restrict__ A, const float* __restrict__ W)
{
    __shared__ float As[2][16][128+4];
    __shared__ float Bs[2][16][128+4];
    const int tid = threadIdx.x;
    const int row0 = blockIdx.y*128, col0 = blockIdx.x*128;
    const int kb = blockIdx.z * (HH/SK);
    const int arow = tid >> 1, ak = (tid & 1)*8;
    const int ty = tid >> 4, tx = tid & 15;

    const float* Arow = A + (size_t)(row0+arow)*HH + kb + ak;
    const float* Brow = W + (size_t)(col0+arow)*HH + kb + ak;

    float4 a0 = *(const float4*)Arow, a1 = *(const float4*)(Arow+4);
    float4 b0 = *(const float4*)Brow, b1 = *(const float4*)(Brow+4);
#pragma unroll
    for (int j=0;j<4;j++){
        As[0][ak+j][arow]=((const float*)&a0)[j]; As[0][ak+4+j][arow]=((const float*)&a1)[j];
        Bs[0][ak+j][arow]=((const float*)&b0)[j]; Bs[0][ak+4+j][arow]=((const float*)&b1)[j];
    }
    __syncthreads();

    ull acc[8][4];
#pragma unroll
    for (int i=0;i<8;i++)
#pragma unroll
        for (int p=0;p<4;p++) acc[i][p]=0ull;

    const int NT = (HH/SK)/16;
    for (int it=0; it<NT; it++){
        int cur = it & 1;
        float4 a0n,a1n,b0n,b1n;
        if (it+1 < NT){
            int k0 = (it+1)*16;
            a0n=*(const float4*)(Arow+k0); a1n=*(const float4*)(Arow+k0+4);
            b0n=*(const float4*)(Brow+k0); b1n=*(const float4*)(Brow+k0+4);
        }
#pragma unroll
        for (int kk=0; kk<16; kk++){
            const float* Ar = &As[cur][kk][ty*8];
            const float* Br = &Bs[cur][kk][tx*8];
            float4 af0 = *(const float4*)Ar, af1 = *(const float4*)(Ar+4);
            ulonglong2 bq0 = *(const ulonglong2*)Br;
            ulonglong2 bq1 = *(const ulonglong2*)(Br+4);
            float av[8] = {af0.x,af0.y,af0.z,af0.w,af1.x,af1.y,af1.z,af1.w};
#pragma unroll
            for (int i=0;i<8;i++){
                ull ap = pkdup(av[i]);
                fma2(acc[i][0], ap, bq0.x);
                fma2(acc[i][1], ap, bq0.y);
                fma2(acc[i][2], ap, bq1.x);
                fma2(acc[i][3], ap, bq1.y);
            }
        }
        if (it+1 < NT){
            int nb = cur^1;
#pragma unroll
            for (int j=0;j<4;j++){
                As[nb][ak+j][arow]=((const float*)&a0n)[j]; As[nb][ak+4+j][arow]=((const float*)&a1n)[j];
                Bs[nb][ak+j][arow]=((const float*)&b0n)[j]; Bs[nb][ak+4+j][arow]=((const float*)&b1n)[j];
            }
        }
        __syncthreads();
    }

    float* Cp = d_fc1p[blockIdx.z];
#pragma unroll
    for (int i=0;i<8;i++){
        int r = row0 + ty*8 + i;
        float2 q0=upk2(acc[i][0]), q1=upk2(acc[i][1]), q2=upk2(acc[i][2]), q3=upk2(acc[i][3]);
        float4 v0 = make_float4(q0.x,q0.y,q1.x,q1.y);
        float4 v1 = make_float4(q2.x,q2.y,q3.x,q3.y);
        *(float4*)&Cp[(size_t)r*HH + col0 + tx*8]     = v0;
        *(float4*)&Cp[(size_t)r*HH + col0 + tx*8 + 4] = v1;
    }
}

// ---------------- out split-K GEMM: A = relu(sum fc1 partials + b_fc1) -----------
__global__ void __launch_bounds__(256) gemm_out_f2(
    const float* __restrict__ W, const float* __restrict__ b_fc1)
{
    __shared__ float As[2][16][128+4];
    __shared__ float Bs[2][16][128+4];
    const int tid = threadIdx.x;
    const int row0 = blockIdx.y*128, col0 = blockIdx.x*128;
    const int kb = blockIdx.z * (HH/SK);
    const int arow = tid >> 1, ak = (tid & 1)*8;
    const int ty = tid >> 4, tx = tid & 15;
    const int br = col0 + arow;

    const size_t aoff = (size_t)(row0+arow)*HH + kb + ak;
    const float* Brow = (br < VV) ? (W + (size_t)br*HH + kb + ak) : nullptr;

    float4 a0, a1, b0, b1;
    {
        float4 p0=*(const float4*)&d_fc1p[0][aoff], p1=*(const float4*)&d_fc1p[1][aoff];
        float4 p2=*(const float4*)&d_fc1p[2][aoff], p3=*(const float4*)&d_fc1p[3][aoff];
        float4 bf=*(const float4*)&b_fc1[kb+ak];
        a0.x=fmaxf(p0.x+p1.x+p2.x+p3.x+bf.x,0.f); a0.y=fmaxf(p0.y+p1.y+p2.y+p3.y+bf.y,0.f);
        a0.z=fmaxf(p0.z+p1.z+p2.z+p3.z+bf.z,0.f); a0.w=fmaxf(p0.w+p1.w+p2.w+p3.w+bf.w,0.f);
        p0=*(const float4*)&d_fc1p[0][aoff+4]; p1=*(const float4*)&d_fc1p[1][aoff+4];
        p2=*(const float4*)&d_fc1p[2][aoff+4]; p3=*(const float4*)&d_fc1p[3][aoff+4];
        bf=*(const float4*)&b_fc1[kb+ak+4];
        a1.x=fmaxf(p0.x+p1.x+p2.x+p3.x+bf.x,0.f); a1.y=fmaxf(p0.y+p1.y+p2.y+p3.y+bf.y,0.f);
        a1.z=fmaxf(p0.z+p1.z+p2.z+p3.z+bf.z,0.f); a1.w=fmaxf(p0.w+p1.w+p2.w+p3.w+bf.w,0.f);
        b0 = Brow ? *(const float4*)Brow     : make_float4(0,0,0,0);
        b1 = Brow ? *(const float4*)(Brow+4) : make_float4(0,0,0,0);
    }
#pragma unroll
    for (int j=0;j<4;j++){
        As[0][ak+j][arow]=((const float*)&a0)[j]; As[0][ak+4+j][arow]=((const float*)&a1)[j];
        Bs[0][ak+j][arow]=((const float*)&b0)[j]; Bs[0][ak+4+j][arow]=((const float*)&b1)[j];
    }
    __syncthreads();

    ull acc[8][4];
#pragma unroll
    for (int i=0;i<8;i++)
#pragma unroll
        for (int p=0;p<4;p++) acc[i][p]=0ull;

    const int NT = (HH/SK)/16;
    for (int it=0; it<NT; it++){
        int cur = it & 1;
        float4 a0n,a1n,b0n,b1n;
        if (it+1 < NT){
            int k0 = (it+1)*16;
            float4 p0=*(const float4*)&d_fc1p[0][aoff+k0], p1=*(const float4*)&d_fc1p[1][aoff+k0];
            float4 p2=*(const float4*)&d_fc1p[2][aoff+k0], p3=*(const float4*)&d_fc1p[3][aoff+k0];
            float4 bf=*(const float4*)&b_fc1[kb+ak+k0];
            a0n.x=fmaxf(p0.x+p1.x+p2.x+p3.x+bf.x,0.f); a0n.y=fmaxf(p0.y+p1.y+p2.y+p3.y+bf.y,0.f);
            a0n.z=fmaxf(p0.z+p1.z+p2.z+p3.z+bf.z,0.f); a0n.w=fmaxf(p0.w+p1.w+p2.w+p3.w+bf.w,0.f);
            p0=*(const float4*)&d_fc1p[0][aoff+k0+4]; p1=*(const float4*)&d_fc1p[1][aoff+k0+4];
            p2=*(const float4*)&d_fc1p[2][aoff+k0+4]; p3=*(const float4*)&d_fc1p[3][aoff+k0+4];
            bf=*(const float4*)&b_fc1[kb+ak+k0+4];
            a1n.x=fmaxf(p0.x+p1.x+p2.x+p3.x+bf.x,0.f); a1n.y=fmaxf(p0.y+p1.y+p2.y+p3.y+bf.y,0.f);
            a1n.z=fmaxf(p0.z+p1.z+p2.z+p3.z+bf.z,0.f); a1n.w=fmaxf(p0.w+p1.w+p2.w+p3.w+bf.w,0.f);
            b0n = Brow ? *(const float4*)(Brow+k0)   : make_float4(0,0,0,0);
            b1n = Brow ? *(const float4*)(Brow+k0+4) : make_float4(0,0,0,0);
        }
#pragma unroll
        for (int kk=0; kk<16; kk++){
            const float* Ar = &As[cur][kk][ty*8];
            const float* Br = &Bs[cur][kk][tx*8];
            float4 af0 = *(const float4*)Ar, af1 = *(const float4*)(Ar+4);
            ulonglong2 bq0 = *(const ulonglong2*)Br;
            ulonglong2 bq1 = *(const ulonglong2*)(Br+4);
            float av[8] = {af0.x,af0.y,af0.z,af0.w,af1.x,af1.y,af1.z,af1.w};
#pragma unroll
            for (int i=0;i<8;i++){
                ull ap = pkdup(av[i]);
                fma2(acc[i][0], ap, bq0.x);
                fma2(acc[i][1], ap, bq0.y);
                fma2(acc[i][2], ap, bq1.x);
                fma2(acc[i][3], ap, bq1.y);
            }
        }
        if (it+1 < NT){
            int nb = cur^1;
#pragma unroll
            for (int j=0;j<4;j++){
                As[nb][ak+j][arow]=((const float*)&a0n)[j]; As[nb][ak+4+j][arow]=((const float*)&a1n)[j];
                Bs[nb][ak+j][arow]=((const float*)&b0n)[j]; Bs[nb][ak+4+j][arow]=((const float*)&b1n)[j];
            }
        }
        __syncthreads();
    }

    float* Cp = d_lpp[blockIdx.z];
    const int c0 = col0 + tx*8;
    if (c0 + 8 <= VV){
#pragma unroll
        for (int i=0;i<8;i++){
            int r = row0 + ty*8 + i;
            float2 q0=upk2(acc[i][0]), q1=upk2(acc[i][1]), q2=upk2(acc[i][2]), q3=upk2(acc[i][3]);
            *(float4*)&Cp[(size_t)r*VV + c0]     = make_float4(q0.x,q0.y,q1.x,q1.y);
            *(float4*)&Cp[(size_t)r*VV + c0 + 4] = make_float4(q2.x,q2.y,q3.x,q3.y);
        }
    }
}

// ---------------- warp LSE ---------------------------------------------------------
__device__ __forceinline__ float warpLSE(const float* __restrict__ base,
                                         const float* __restrict__ t1,
                                         const float* __restrict__ t2){
    int lane = threadIdx.x & 31;
    float m = -INFINITY, s = 0.f;
    for (int n = lane; n < NP; n += 32){
        float x = base[n];
        if (t1) x -= t1[n];
        if (t2) x -= t2[n];
        if (x > m){ s = s*expf(m-x) + 1.f; m = x; } else s += expf(x-m);
    }
#pragma unroll
    for (int off=16; off; off>>=1){
        float m2 = __shfl_xor_sync(0xffffffffu, m, off);
        float s2 = __shfl_xor_sync(0xffffffffu, s, off);
        float mm = fmaxf(m, m2);
        s = s*expf(m-mm) + s2*expf(m2-mm);
        m = mm;
    }
    return m + logf(s);
}

// ---------------- fused select (per batch element) ---------------------------------
__global__ void __launch_bounds__(256) select_kernel(const float* __restrict__ gu,
                                                     const float* __restrict__ b_out,
                                                     int t, int cur){
    __shared__ float pool[KB*NP + NP];
    __shared__ float rv[256];
    __shared__ int   ri[256];
    __shared__ float entS[KB], phiS[KB], gvalS[KB], logIs_s[KB+1];
    __shared__ int   ordS[KB], snewS[KB];

    const int i = blockIdx.x, tid = threadIdx.x;
    const int lane = tid & 31, w = tid >> 5;
    float (*gm)[VV] = (float(*)[VV])pool;

    const int r = w*BB + i;
    const size_t rb = (size_t)r*VV;

    // fused: lp = sum of SK out partials + b_out (kept in registers, 13/lane)
    float lv[13];
#pragma unroll
    for (int ii=0; ii<13; ii++){
        int v = lane + ii*32;
        float val = -INFINITY;
        if (v < VV)
            val = d_lpp[0][rb+v] + d_lpp[1][rb+v] + d_lpp[2][rb+v] + d_lpp[3][rb+v] + b_out[v];
        lv[ii] = val;
    }
    float m = -INFINITY;
#pragma unroll
    for (int ii=0; ii<13; ii++) m = fmaxf(m, lv[ii]);
#pragma unroll
    for (int off=16; off; off>>=1) m = fmaxf(m, __shfl_xor_sync(0xffffffffu, m, off));
    float s = 0.f;
#pragma unroll
    for (int ii=0; ii<13; ii++){ int v = lane+ii*32; if (v < VV) s += expf(lv[ii]-m); }
#pragma unroll
    for (int off=16; off; off>>=1) s += __shfl_xor_sync(0xffffffffu, s, off);
    float lse = m + logf(s);

    float lpr = d_logp[cur][r];
    float Gr  = d_Gmx[cur][r];
    const float* u = gu + ((size_t)t*RR + r)*VV;
    float ent = 0.f, zm = -INFINITY;
#pragma unroll
    for (int ii=0; ii<13; ii++){
        int v = lane + ii*32;
        if (v >= VV) continue;
        float l = lv[ii]-lse;
        d_lpn[rb+v] = l;
        ent += l*expf(l);
        float gmb = -logf(-logf(u[v]*(1.f-2e-7f)+1e-7f));
        float gph = l + lpr + gmb;
        gm[w][v] = gph;
        zm = fmaxf(zm, gph);
    }
#pragma unroll
    for (int off=16; off; off>>=1){
        ent += __shfl_xor_sync(0xffffffffu, ent, off);
        zm = fmaxf(zm, __shfl_xor_sync(0xffffffffu, zm, off));
    }
    if (lane==0) entS[w] = ent;
    for (int v=lane; v<VV; v+=32){
        float gph = gm[w][v];
        float vv = Gr - gph + log1mexp(gph - zm);
        float val = Gr - fmaxf(vv,0.f) - log1pf(expf(-fabsf(vv)));
        gm[w][v] = (t==0 && w>0) ? -INFINITY : val;
    }
    __syncthreads();

    // top-k (value desc, flat idx = beam*VV+v asc on ties)
    for (int round=0; round<KB; round++){
        float bv = -INFINITY; int bi = 0x7fffffff;
        for (int idx=tid; idx<KB*VV; idx+=256){
            float v = pool[idx];
            if (v > bv || (v == bv && idx < bi)){ bv=v; bi=idx; }
        }
        rv[tid]=bv; ri[tid]=bi; __syncthreads();
        for (int off=128; off; off>>=1){
            if (tid < off){
                if (rv[tid+off] > rv[tid] || (rv[tid+off]==rv[tid] && ri[tid+off]<ri[tid])){
                    rv[tid]=rv[tid+off]; ri[tid]=ri[tid+off];
                }
            }
            __syncthreads();
        }
        if (tid==0){
            int widx = ri[0]; int j = widx/VV, v = widx - j*VV;
            gvalS[round]=rv[0]; ordS[round]=j; snewS[round]=v;
            pool[widx] = -INFINITY;
        }
        __syncthreads();
    }

    // gather
    const int nxt = cur^1;
    for (int idx=tid; idx<KB*LL; idx+=256){
        int j = idx/LL, tt = idx - j*LL;
        if (tt == t) continue;
        int rn = j*BB+i, o = ordS[j]*BB+i;
        d_samples[nxt][rn*LL+tt] = d_samples[cur][o*LL+tt];
        d_outputs[nxt][rn*LL+tt] = d_outputs[cur][o*LL+tt];
    }
    if (tid < KB){
        int j = tid, rn = j*BB+i, o = ordS[j]*BB+i, sv = snewS[j];
        float lpv = d_lpn[(size_t)o*VV + sv];
        float nl  = d_logp[cur][o] + lpv;
        d_samples[nxt][rn*LL+t] = (float)sv;
        d_outputs[nxt][rn*LL+t] = lpv;
        d_logp[nxt][rn] = nl;
        d_Gmx[nxt][rn]  = gvalS[j];
        d_prev[rn]  = sv;
        d_order[rn] = o;
        d_phik[i*KB+j] = nl;
        phiS[j] = nl;
    }
    __syncthreads();

    // compute_log_R
    float (*Ts)[NP] = (float(*)[NP])pool;
    float* base = pool + KB*NP;
    float p[KB], pS = 0.f;
#pragma unroll
    for (int j=0;j<KB;j++){ p[j] = expf(phiS[j]); pS += p[j]; }
    for (int n=tid; n<NP; n+=256){
        float lu = logf(((float)n + 0.5f)/(float)NP);
        float bs = -pS*lu;
#pragma unroll
        for (int j=0;j<KB;j++){
            float x = log1mexp(p[j]*lu);
            Ts[j][n] = x;
            bs += x;
        }
        base[n] = bs;
    }
    __syncthreads();

    const float logN = logf((float)NP);
    float resA = warpLSE(base, Ts[w], nullptr) - logN;
    if (lane==0) logIs_s[w] = resA;
    if (w==0){
        float li = warpLSE(base, nullptr, nullptr) - logN;
        if (lane==0) logIs_s[KB] = li;
    }
    __syncthreads();
    float logI = logIs_s[KB];
    if (tid < KB) d_logRs[i*KB+tid] = logIs_s[tid] - logI;

    for (int pp = w; pp < 28; pp += 8){
        int a = 0, rem = pp;
        while (rem >= 7 - a){ rem -= (7 - a); a++; }
        int b = a + 1 + rem;
        float lss = warpLSE(base, Ts[a], Ts[b]) - logN;
        if (lane==0){
            d_logRss[i*64 + a*8 + b] = lss - logIs_s[a];
            d_logRss[i*64 + b*8 + a] = lss - logIs_s[b];
        }
    }
    if (tid < KB) d_logRss[i*64 + tid*9] = 0.f;
    if (tid == 0){
        float Wsum = 0.f, ws = 0.f;
#pragma unroll
        for (int j=0;j<KB;j++){
            float wq = expf(phiS[j] + logIs_s[j] - logI);
            Wsum += wq;
            ws   += wq * entS[ordS[j]];
        }
        d_entplot[i] += ws;
        d_entelem[i] += ws / Wsum;
    }
}

// ---------------- output assembly ---------------------------------------------------
__global__ void finalize_kernel(float* __restrict__ out, int out_size){
    int idx = blockIdx.x*blockDim.x + threadIdx.x;
    if (idx >= out_size || idx >= 18560) return;
    const int FIN = LL & 1;
    if (idx < 6656){
        int i = idx/104, rem = idx%104, j = rem/13, tt = rem%13;
        out[idx] = d_outputs[FIN][(j*BB+i)*LL + tt];
    } else if (idx < 13312){
        int q = idx - 6656;
        int i = q/104, rem = q%104, j = rem/13, tt = rem%13;
        out[idx] = d_samples[FIN][(j*BB+i)*LL + tt];
    } else if (idx < 13376){
        out[idx] = d_entelem[idx-13312];
    } else if (idx < 13888){
        out[idx] = d_logRs[idx-13376];
    } else if (idx < 17984){
        out[idx] = d_logRss[idx-13888];
    } else if (idx < 18496){
        out[idx] = d_phik[idx-17984];
    } else {
        out[idx] = d_entplot[idx-18496];
    }
}

// ---------------- host driver ---------------------------------------------------------
extern "C" void kernel_launch(void* const* d_in, const int* in_sizes, int n_in,
                              void* d_out, int out_size){
    const float* x_feat  = (const float*)d_in[0];
    const float* W_in_op = (const float*)d_in[1];
    const float* b_in_op = (const float*)d_in[2];
    const float* W_ih    = (const float*)d_in[3];
    const float* W_hh    = (const float*)d_in[4];
    const float* b_ih    = (const float*)d_in[5];
    const float* b_hh    = (const float*)d_in[6];
    const float* W_fc1   = (const float*)d_in[7];
    const float* b_fc1   = (const float*)d_in[8];
    const float* W_out   = (const float*)d_in[9];
    const float* b_out   = (const float*)d_in[10];
    const float* gu      = (const float*)d_in[11];
    (void)in_sizes; (void)n_in;

    void* tmp;
    cudaGetSymbolAddress(&tmp, d_ht);    float* p_ht  = (float*)tmp;
    cudaGetSymbolAddress(&tmp, d_ct);    float* p_ct  = (float*)tmp;
    cudaGetSymbolAddress(&tmp, d_xW);    float* p_xW  = (float*)tmp;
    cudaGetSymbolAddress(&tmp, d_E);     float* p_E   = (float*)tmp;
    cudaGetSymbolAddress(&tmp, d_Gt);    float* p_Gt  = (float*)tmp;
    cudaGetSymbolAddress(&tmp, d_Whh2);  float* p_Wh2 = (float*)tmp;

    init_kernel<<<256,256>>>(W_in_op, b_in_op);
    reorder_whh<<<(G4*HH+255)/256,256>>>(W_hh);

    gemm_db<1><<<dim3(64,1),256>>>(x_feat,1024, W_ih,1152, p_xW,G4,
                                   BB,G4,1024, b_ih, b_hh);
    gemm_db<0><<<dim3(64,7),256>>>(p_E,128, W_ih+1024,1152, p_Gt,G4,
                                   V1,G4,128, nullptr, nullptr);
    permute_gates<<<((BB+V1)*G4+255)/256,256>>>();

    for (int t = 0; t < LL; t++){
        int cur = t & 1;
        float* h_cur = p_ht + (size_t)cur*RR*HH;
        float* c_cur = p_ct + (size_t)cur*RR*HH;
        if (t == 0){
            lstm0<<<RR,256>>>(h_cur, c_cur);
        } else {
            int prv = (t+1) & 1;
            gemm_gates_f2<<<dim3(32,4),256>>>(p_ht + (size_t)prv*RR*HH,
                                              p_ct + (size_t)prv*RR*HH,
                                              h_cur, c_cur, p_Wh2);
        }
        gemm_fc1_f2<<<dim3(8,4,SK),256>>>(h_cur, W_fc1);
        gemm_out_f2<<<dim3(4,4,SK),256>>>(W_out, b_fc1);
        select_kernel<<<BB,256>>>(gu, b_out, t, cur);
    }

    finalize_kernel<<<(18560+255)/256,256>>>((float*)d_out, out_size);
}

// round 6
// speedup vs baseline: 2.1862x; 1.0056x over previous
#include <cuda_runtime.h>
#include <cuda_bf16.h>
#include <math.h>
#include <stdint.h>

#define BB 64      // batch
#define KB 8       // beams
#define RR 512     // BB*KB
#define HH 1024    // hidden
#define VV 400     // vocab
#define V1 401
#define LL 13      // program_len
#define G4 4096    // 4*HH
#define NP 1000    // log_R quadrature points
#define SK 4       // split-K slices for fc1/out

typedef unsigned long long ull;

// ---------------- persistent scratch -----------------------------------------
__device__ float d_ht[2][RR*HH];
__device__ float d_ct[2][RR*HH];
__device__ float d_Gmx[2][RR];
__device__ float d_logp[2][RR];
__device__ int   d_prev[RR];
__device__ int   d_order[RR];
__device__ float d_samples[2][RR*LL];
__device__ float d_outputs[2][RR*LL];
__device__ float d_entplot[BB];
__device__ float d_entelem[BB];
__device__ float d_xW[BB*G4];
__device__ float d_xW2[BB*G4];
__device__ float d_E[V1*128];
__device__ float d_Gt[V1*G4];
__device__ float d_Gt2[V1*G4];
__device__ float d_Whh2[G4*HH];
__device__ __nv_bfloat16 d_wb[3][G4*HH];      // W_hh2 bf16 3-way splits
__device__ __nv_bfloat16 d_hb[2][3][RR*HH];   // h bf16 3-way splits (double buffered)
__device__ float d_fc1p[SK][RR*HH];
__device__ float d_lpp[SK][RR*VV];
__device__ float d_lpn[RR*VV];
__device__ float d_phik[BB*KB];
__device__ float d_logRs[BB*KB];
__device__ float d_logRss[BB*KB*KB];

// ---------------- helpers ------------------------------------------------------
__device__ __forceinline__ float sigmoidf(float x){ return 1.f/(1.f+expf(-x)); }

__device__ __forceinline__ float log1mexp(float x){
    x = fminf(x, -1e-38f);
    if (x > -0.6931472f) return logf(-expm1f(x));
    return log1pf(-expf(x));
}

__device__ __forceinline__ ull pkdup(float x){
    ull r; unsigned u = __float_as_uint(x);
    asm("mov.b64 %0, {%1, %1};" : "=l"(r) : "r"(u));
    return r;
}
__device__ __forceinline__ float2 upk2(ull v){
    unsigned lo, hi;
    asm("mov.b64 {%0, %1}, %2;" : "=r"(lo), "=r"(hi) : "l"(v));
    return make_float2(__uint_as_float(lo), __uint_as_float(hi));
}
__device__ __forceinline__ void fma2(ull &c, ull a, ull b){
    asm("fma.rn.f32x2 %0, %1, %2, %0;" : "+l"(c) : "l"(a), "l"(b));
}

__device__ __forceinline__ uint32_t smem_u32(const void* p){
    uint32_t a;
    asm("{ .reg .u64 t; cvta.to.shared.u64 t, %1; cvt.u32.u64 %0, t; }" : "=r"(a) : "l"(p));
    return a;
}

// ldmatrix (sm_75+, valid on plain sm_103)
__device__ __forceinline__ void ldsm_x4(unsigned* r, uint32_t addr){
    asm volatile("ldmatrix.sync.aligned.m8n8.x4.shared.b16 {%0,%1,%2,%3}, [%4];"
        : "=r"(r[0]), "=r"(r[1]), "=r"(r[2]), "=r"(r[3]) : "r"(addr));
}
__device__ __forceinline__ void ldsm_x2(unsigned* r, uint32_t addr){
    asm volatile("ldmatrix.sync.aligned.m8n8.x2.shared.b16 {%0,%1}, [%2];"
        : "=r"(r[0]), "=r"(r[1]) : "r"(addr));
}
// mma.sync bf16 (sm_80+, valid on plain sm_103)
__device__ __forceinline__ void mma_bf16(float* c, const unsigned* a, const unsigned* b){
    asm volatile("mma.sync.aligned.m16n8k16.row.col.f32.bf16.bf16.f32 "
        "{%0,%1,%2,%3}, {%4,%5,%6,%7}, {%8,%9}, {%0,%1,%2,%3};"
        : "+f"(c[0]), "+f"(c[1]), "+f"(c[2]), "+f"(c[3])
        : "r"(a[0]), "r"(a[1]), "r"(a[2]), "r"(a[3]), "r"(b[0]), "r"(b[1]));
}

// ---------------- init ----------------------------------------------------------
__global__ void init_kernel(const float* __restrict__ W_in_op,
                            const float* __restrict__ b_in_op){
    int idx = blockIdx.x*blockDim.x + threadIdx.x;
    int stride = gridDim.x*blockDim.x;
    for (int i = idx; i < RR;    i += stride){ d_Gmx[0][i]=0.f; d_logp[0][i]=0.f; }
    for (int i = idx; i < RR*LL; i += stride){ d_samples[0][i]=0.f; d_outputs[0][i]=0.f; }
    for (int i = idx; i < BB;    i += stride){ d_entplot[i]=0.f; d_entelem[i]=0.f; }
    for (int i = idx; i < V1*128; i += stride){
        int s = i >> 7, m = i & 127;
        d_E[i] = fmaxf(W_in_op[m*V1 + s] + b_in_op[m], 0.f);
    }
}

__global__ void reorder_whh(const float* __restrict__ W){
    int idx = blockIdx.x*blockDim.x + threadIdx.x;
    if (idx >= G4*HH) return;
    int c = idx >> 10, k = idx & 1023;
    int h = c >> 2, g = c & 3;
    d_Whh2[idx] = W[(size_t)(g*HH + h)*HH + k];
}

__global__ void split_whh(){
    int idx = blockIdx.x*blockDim.x + threadIdx.x;
    if (idx >= G4*HH) return;
    float w = d_Whh2[idx];
    __nv_bfloat16 b0 = __float2bfloat16(w);
    float r1 = w - __bfloat162float(b0);
    __nv_bfloat16 b1 = __float2bfloat16(r1);
    float r2 = r1 - __bfloat162float(b1);
    d_wb[0][idx] = b0;
    d_wb[1][idx] = b1;
    d_wb[2][idx] = __float2bfloat16(r2);
}

__global__ void permute_gates(){
    int idx = blockIdx.x*blockDim.x + threadIdx.x;
    if (idx >= (BB+V1)*G4) return;
    int row = idx / G4, c = idx - row*G4;
    int g = c >> 10, h = c & 1023;
    int dstc = 4*h + g;
    if (row < BB) d_xW2[row*G4 + dstc] = d_xW[idx];
    else          d_Gt2[(row-BB)*G4 + dstc] = d_Gt[idx - BB*G4];
}

// ---------------- t=0 LSTM: also emits bf16 splits of h --------------------------
__global__ void __launch_bounds__(256) lstm0(){
    int r = blockIdx.x, tid = threadIdx.x;
    int b = r & 63;
    for (int u = tid; u < HH; u += 256){
        float4 xw = *(const float4*)&d_xW2[(size_t)b*G4 + u*4];
        float4 gt = *(const float4*)&d_Gt2[(size_t)VV*G4 + u*4];
        float ig = xw.x+gt.x, gg = xw.z+gt.z, og = xw.w+gt.w;
        float cn = sigmoidf(ig)*tanhf(gg);
        float hn = sigmoidf(og)*tanhf(cn);
        d_ct[0][(size_t)r*HH+u] = cn;
        d_ht[0][(size_t)r*HH+u] = hn;
        __nv_bfloat16 s0 = __float2bfloat16(hn);
        float r1 = hn - __bfloat162float(s0);
        __nv_bfloat16 s1 = __float2bfloat16(r1);
        float r2 = r1 - __bfloat162float(s1);
        d_hb[0][0][(size_t)r*HH+u] = s0;
        d_hb[0][1][(size_t)r*HH+u] = s1;
        d_hb[0][2][(size_t)r*HH+u] = __float2bfloat16(r2);
    }
}

// ---------------- setup GEMM (64x64x16 double buffered, scalar) -------------------
template<int MODE>
__global__ void __launch_bounds__(256) gemm_db(
    const float* __restrict__ A, int lda,
    const float* __restrict__ B, int ldb,
    float* __restrict__ C, int ldc,
    int M, int N, int K,
    const float* __restrict__ bias1,
    const float* __restrict__ bias2)
{
    __shared__ float As[2][16][64+4];
    __shared__ float Bs[2][16][64+4];
    const int tid = threadIdx.x;
    const int row0 = blockIdx.y*64, col0 = blockIdx.x*64;
    const int arow = tid >> 2, ak = (tid & 3)*4;
    const int ty = tid >> 4, tx = tid & 15;

    const int ar = row0 + arow, br = col0 + arow;
    float4 a4 = make_float4(0,0,0,0), b4 = make_float4(0,0,0,0);
    if (ar < M) a4 = *(const float4*)(A + (size_t)ar*lda + ak);
    if (br < N) b4 = *(const float4*)(B + (size_t)br*ldb + ak);
    As[0][ak+0][arow]=a4.x; As[0][ak+1][arow]=a4.y; As[0][ak+2][arow]=a4.z; As[0][ak+3][arow]=a4.w;
    Bs[0][ak+0][arow]=b4.x; Bs[0][ak+1][arow]=b4.y; Bs[0][ak+2][arow]=b4.z; Bs[0][ak+3][arow]=b4.w;
    __syncthreads();

    float acc[4][4];
#pragma unroll
    for (int i=0;i<4;i++)
#pragma unroll
        for (int j=0;j<4;j++) acc[i][j]=0.f;

    const int NT = K/16;
    for (int it=0; it<NT; it++){
        int cur = it & 1;
        float4 a4n, b4n;
        if (it+1 < NT){
            int k0 = (it+1)*16;
            a4n = make_float4(0,0,0,0); b4n = make_float4(0,0,0,0);
            if (ar < M) a4n = *(const float4*)(A + (size_t)ar*lda + k0 + ak);
            if (br < N) b4n = *(const float4*)(B + (size_t)br*ldb + k0 + ak);
        }
#pragma unroll
        for (int kk=0; kk<16; kk++){
            float4 ra = *(const float4*)&As[cur][kk][ty*4];
            float4 rb = *(const float4*)&Bs[cur][kk][tx*4];
            float r[4]={ra.x,ra.y,ra.z,ra.w};
            float cb[4]={rb.x,rb.y,rb.z,rb.w};
#pragma unroll
            for (int i=0;i<4;i++)
#pragma unroll
                for (int j=0;j<4;j++) acc[i][j] = fmaf(r[i], cb[j], acc[i][j]);
        }
        if (it+1 < NT){
            int nb = cur^1;
            As[nb][ak+0][arow]=a4n.x; As[nb][ak+1][arow]=a4n.y; As[nb][ak+2][arow]=a4n.z; As[nb][ak+3][arow]=a4n.w;
            Bs[nb][ak+0][arow]=b4n.x; Bs[nb][ak+1][arow]=b4n.y; Bs[nb][ak+2][arow]=b4n.z; Bs[nb][ak+3][arow]=b4n.w;
        }
        __syncthreads();
    }
#pragma unroll
    for (int i=0;i<4;i++){
        int r = row0 + ty*4 + i;
        if (r >= M) continue;
#pragma unroll
        for (int j=0;j<4;j++){
            int c = col0 + tx*4 + j;
            if (c >= N) continue;
            float v = acc[i][j];
            if (MODE==1) v += bias1[c] + bias2[c];
            else if (MODE==3) v = fmaxf(v + bias1[c], 0.f);
            else if (MODE==4) v += bias1[c];
            C[(size_t)r*ldc + c] = v;
        }
    }
}

// ---------------- gates GEMM via mma.sync bf16x3 + fused LSTM ---------------------
// CTA 128x128, 8 warps (2x4), warp tile 64x32. K chunks of 16, double buffered.
#define CH_TILE 6144                 // 128 rows * 48B padded
#define CH_BUF  (6*CH_TILE)          // 3 A splits + 3 B splits = 36864 B
#define GM_DSMEM (2*CH_BUF)          // 73728 B (also covers 128x132 f32 epilogue buf)

__global__ void __launch_bounds__(256) gates_mma(int cur){
    extern __shared__ char dsm[];
    __shared__ int ord_s[128];
    const int tid = threadIdx.x, w = tid>>5, lane = tid&31;
    const int prv = cur^1;
    const int row0 = blockIdx.y*128, col0 = blockIdx.x*128;
    const int wr = w>>2, wc = w&3;
    const uint32_t dbase = smem_u32(dsm);

    if (tid < 128) ord_s[tid] = d_order[row0 + tid];
    __syncthreads();

    const __nv_bfloat16* Asrc[3] = {d_hb[prv][0], d_hb[prv][1], d_hb[prv][2]};
    const __nv_bfloat16* Bsrc[3] = {d_wb[0], d_wb[1], d_wb[2]};

    // per-thread chunk-load slots: 6 uint4 each
    const int ld_t    = tid >> 8;          // always 0; tile index derived below
    (void)ld_t;
    int  ld_tile[6], ld_row[6], ld_half[6];
    const __nv_bfloat16* ld_src[6];
#pragma unroll
    for (int j=0;j<6;j++){
        int idx = tid + j*256;
        int t = idx >> 8, pos = idx & 255;
        int row = pos >> 1, half = pos & 1;
        ld_tile[j]=t; ld_row[j]=row; ld_half[j]=half;
        if (t < 3) ld_src[j] = Asrc[t]   + (size_t)ord_s[row]*HH + half*8;
        else       ld_src[j] = Bsrc[t-3] + (size_t)(col0+row)*HH + half*8;
    }

    float acc[4][4][4];
#pragma unroll
    for (int mi=0;mi<4;mi++)
#pragma unroll
        for (int ni=0;ni<4;ni++)
#pragma unroll
            for (int e=0;e<4;e++) acc[mi][ni][e]=0.f;

    uint4 v[6];
#pragma unroll
    for (int j=0;j<6;j++) v[j] = *(const uint4*)(ld_src[j]);
    {
        char* bp = dsm;
#pragma unroll
        for (int j=0;j<6;j++)
            *(uint4*)(bp + ld_tile[j]*CH_TILE + ld_row[j]*48 + ld_half[j]*16) = v[j];
    }
    __syncthreads();

    // ldmatrix base addresses (per-thread constants modulo buffer/k-tile offsets)
    const uint32_t a_lm = dbase + (wr*64 + (lane&15))*48 + (lane>>4)*16;
    const uint32_t b_lm = dbase + (wc*32 + (lane&7))*48 + ((lane>>3)&1)*16;

    for (int kc = 0; kc < 64; kc++){
        if (kc+1 < 64){
#pragma unroll
            for (int j=0;j<6;j++) v[j] = *(const uint4*)(ld_src[j] + (kc+1)*16);
        }
        const uint32_t bb = (kc&1)*CH_BUF;

        unsigned Bf[3][4][2];
#pragma unroll
        for (int s=0;s<3;s++)
#pragma unroll
            for (int ni=0;ni<4;ni++)
                ldsm_x2(Bf[s][ni], b_lm + bb + (3+s)*CH_TILE + ni*8*48);

#pragma unroll
        for (int s=0;s<3;s++){
            unsigned Af[4][4];
#pragma unroll
            for (int mi=0;mi<4;mi++)
                ldsm_x4(Af[mi], a_lm + bb + s*CH_TILE + mi*16*48);
            const int nb = (s==0)?3:((s==1)?2:1);
#pragma unroll
            for (int jb=0;jb<3;jb++){
                if (jb >= nb) break;
#pragma unroll
                for (int mi=0;mi<4;mi++)
#pragma unroll
                    for (int ni=0;ni<4;ni++)
                        mma_bf16(acc[mi][ni], Af[mi], Bf[jb][ni]);
            }
        }

        if (kc+1 < 64){
            char* bp = dsm + ((kc+1)&1)*CH_BUF;
#pragma unroll
            for (int j=0;j<6;j++)
                *(uint4*)(bp + ld_tile[j]*CH_TILE + ld_row[j]*48 + ld_half[j]*16) = v[j];
        }
        __syncthreads();
    }

    // ---- epilogue: dump gates to smem, then LSTM ----
    float* gs = (float*)dsm;                      // 128 x 132 f32
#pragma unroll
    for (int mi=0;mi<4;mi++)
#pragma unroll
        for (int ni=0;ni<4;ni++)
#pragma unroll
            for (int e=0;e<4;e++){
                int rl = wr*64 + mi*16 + (lane>>2) + 8*(e>>1);
                int cl = wc*32 + ni*8 + 2*(lane&3) + (e&1);
                gs[rl*132 + cl] = acc[mi][ni][e];
            }
    __syncthreads();

    const int r  = tid >> 1;
    const int r_ = row0 + r;
    const int o  = ord_s[r];
    const int pv = d_prev[r_];
    const int bi = r_ & 63;
    const int ub = (tid & 1)*16;
#pragma unroll
    for (int q=0;q<16;q++){
        int ul = ub + q;
        int u  = (col0>>2) + ul;
        float4 g4 = *(float4*)&gs[r*132 + ul*4];
        float4 xw = *(const float4*)&d_xW2[(size_t)bi*G4 + col0 + ul*4];
        float4 gt = *(const float4*)&d_Gt2[(size_t)pv*G4 + col0 + ul*4];
        float ig = g4.x + xw.x + gt.x;
        float fg = g4.y + xw.y + gt.y;
        float gg = g4.z + xw.z + gt.z;
        float og = g4.w + xw.w + gt.w;
        float cold = d_ct[prv][(size_t)o*HH + u];
        float cn = sigmoidf(fg)*cold + sigmoidf(ig)*tanhf(gg);
        float hn = sigmoidf(og)*tanhf(cn);
        d_ct[cur][(size_t)r_*HH + u] = cn;
        d_ht[cur][(size_t)r_*HH + u] = hn;
        __nv_bfloat16 s0 = __float2bfloat16(hn);
        float rr1 = hn - __bfloat162float(s0);
        __nv_bfloat16 s1 = __float2bfloat16(rr1);
        float rr2 = rr1 - __bfloat162float(s1);
        d_hb[cur][0][(size_t)r_*HH + u] = s0;
        d_hb[cur][1][(size_t)r_*HH + u] = s1;
        d_hb[cur][2][(size_t)r_*HH + u] = __float2bfloat16(rr2);
    }
}

// ---------------- fc1 split-K GEMM (128x128, f32x2): partials, no bias -----------
__global__ void __launch_bounds__(256) gemm_fc1_f2(
    const float* __restrict__ A, const float* __restrict__ W)
{
    __shared__ float As[2][16][128+4];
    __shared__ float Bs[2][16][128+4];
    const int tid = threadIdx.x;
    const int row0 = blockIdx.y*128, col0 = blockIdx.x*128;
    const int kb = blockIdx.z * (HH/SK);
    const int arow = tid >> 1, ak = (tid & 1)*8;
    const int ty = tid >> 4, tx = tid & 15;

    const float* Arow = A + (size_t)(row0+arow)*HH + kb + ak;
    const float* Brow = W + (size_t)(col0+arow)*HH + kb + ak;

    float4 a0 = *(const float4*)Arow, a1 = *(const float4*)(Arow+4);
    float4 b0 = *(const float4*)Brow, b1 = *(const float4*)(Brow+4);
#pragma unroll
    for (int j=0;j<4;j++){
        As[0][ak+j][arow]=((const float*)&a0)[j]; As[0][ak+4+j][arow]=((const float*)&a1)[j];
        Bs[0][ak+j][arow]=((const float*)&b0)[j]; Bs[0][ak+4+j][arow]=((const float*)&b1)[j];
    }
    __syncthreads();

    ull acc[8][4];
#pragma unroll
    for (int i=0;i<8;i++)
#pragma unroll
        for (int p=0;p<4;p++) acc[i][p]=0ull;

    const int NT = (HH/SK)/16;
    for (int it=0; it<NT; it++){
        int cur = it & 1;
        float4 a0n,a1n,b0n,b1n;
        if (it+1 < NT){
            int k0 = (it+1)*16;
            a0n=*(const float4*)(Arow+k0); a1n=*(const float4*)(Arow+k0+4);
            b0n=*(const float4*)(Brow+k0); b1n=*(const float4*)(Brow+k0+4);
        }
#pragma unroll
        for (int kk=0; kk<16; kk++){
            const float* Ar = &As[cur][kk][ty*8];
            const float* Br = &Bs[cur][kk][tx*8];
            float4 af0 = *(const float4*)Ar, af1 = *(const float4*)(Ar+4);
            ulonglong2 bq0 = *(const ulonglong2*)Br;
            ulonglong2 bq1 = *(const ulonglong2*)(Br+4);
            float av[8] = {af0.x,af0.y,af0.z,af0.w,af1.x,af1.y,af1.z,af1.w};
#pragma unroll
            for (int i=0;i<8;i++){
                ull ap = pkdup(av[i]);
                fma2(acc[i][0], ap, bq0.x);
                fma2(acc[i][1], ap, bq0.y);
                fma2(acc[i][2], ap, bq1.x);
                fma2(acc[i][3], ap, bq1.y);
            }
        }
        if (it+1 < NT){
            int nb = cur^1;
#pragma unroll
            for (int j=0;j<4;j++){
                As[nb][ak+j][arow]=((const float*)&a0n)[j]; As[nb][ak+4+j][arow]=((const float*)&a1n)[j];
                Bs[nb][ak+j][arow]=((const float*)&b0n)[j]; Bs[nb][ak+4+j][arow]=((const float*)&b1n)[j];
            }
        }
        __syncthreads();
    }

    float* Cp = d_fc1p[blockIdx.z];
#pragma unroll
    for (int i=0;i<8;i++){
        int r = row0 + ty*8 + i;
        float2 q0=upk2(acc[i][0]), q1=upk2(acc[i][1]), q2=upk2(acc[i][2]), q3=upk2(acc[i][3]);
        *(float4*)&Cp[(size_t)r*HH + col0 + tx*8]     = make_float4(q0.x,q0.y,q1.x,q1.y);
        *(float4*)&Cp[(size_t)r*HH + col0 + tx*8 + 4] = make_float4(q2.x,q2.y,q3.x,q3.y);
    }
}

// ---------------- out split-K GEMM: A = relu(sum fc1 partials + b_fc1) -----------
__global__ void __launch_bounds__(256) gemm_out_f2(
    const float* __restrict__ W, const float* __restrict__ b_fc1)
{
    __shared__ float As[2][16][128+4];
    __shared__ float Bs[2][16][128+4];
    const int tid = threadIdx.x;
    const int row0 = blockIdx.y*128, col0 = blockIdx.x*128;
    const int kb = blockIdx.z * (HH/SK);
    const int arow = tid >> 1, ak = (tid & 1)*8;
    const int ty = tid >> 4, tx = tid & 15;
    const int br = col0 + arow;

    const size_t aoff = (size_t)(row0+arow)*HH + kb + ak;
    const float* Brow = (br < VV) ? (W + (size_t)br*HH + kb + ak) : nullptr;

    float4 a0, a1, b0, b1;
    {
        float4 p0=*(const float4*)&d_fc1p[0][aoff], p1=*(const float4*)&d_fc1p[1][aoff];
        float4 p2=*(const float4*)&d_fc1p[2][aoff], p3=*(const float4*)&d_fc1p[3][aoff];
        float4 bf=*(const float4*)&b_fc1[kb+ak];
        a0.x=fmaxf(p0.x+p1.x+p2.x+p3.x+bf.x,0.f); a0.y=fmaxf(p0.y+p1.y+p2.y+p3.y+bf.y,0.f);
        a0.z=fmaxf(p0.z+p1.z+p2.z+p3.z+bf.z,0.f); a0.w=fmaxf(p0.w+p1.w+p2.w+p3.w+bf.w,0.f);
        p0=*(const float4*)&d_fc1p[0][aoff+4]; p1=*(const float4*)&d_fc1p[1][aoff+4];
        p2=*(const float4*)&d_fc1p[2][aoff+4]; p3=*(const float4*)&d_fc1p[3][aoff+4];
        bf=*(const float4*)&b_fc1[kb+ak+4];
        a1.x=fmaxf(p0.x+p1.x+p2.x+p3.x+bf.x,0.f); a1.y=fmaxf(p0.y+p1.y+p2.y+p3.y+bf.y,0.f);
        a1.z=fmaxf(p0.z+p1.z+p2.z+p3.z+bf.z,0.f); a1.w=fmaxf(p0.w+p1.w+p2.w+p3.w+bf.w,0.f);
        b0 = Brow ? *(const float4*)Brow     : make_float4(0,0,0,0);
        b1 = Brow ? *(const float4*)(Brow+4) : make_float4(0,0,0,0);
    }
#pragma unroll
    for (int j=0;j<4;j++){
        As[0][ak+j][arow]=((const float*)&a0)[j]; As[0][ak+4+j][arow]=((const float*)&a1)[j];
        Bs[0][ak+j][arow]=((const float*)&b0)[j]; Bs[0][ak+4+j][arow]=((const float*)&b1)[j];
    }
    __syncthreads();

    ull acc[8][4];
#pragma unroll
    for (int i=0;i<8;i++)
#pragma unroll
        for (int p=0;p<4;p++) acc[i][p]=0ull;

    const int NT = (HH/SK)/16;
    for (int it=0; it<NT; it++){
        int cur = it & 1;
        float4 a0n,a1n,b0n,b1n;
        if (it+1 < NT){
            int k0 = (it+1)*16;
            float4 p0=*(const float4*)&d_fc1p[0][aoff+k0], p1=*(const float4*)&d_fc1p[1][aoff+k0];
            float4 p2=*(const float4*)&d_fc1p[2][aoff+k0], p3=*(const float4*)&d_fc1p[3][aoff+k0];
            float4 bf=*(const float4*)&b_fc1[kb+ak+k0];
            a0n.x=fmaxf(p0.x+p1.x+p2.x+p3.x+bf.x,0.f); a0n.y=fmaxf(p0.y+p1.y+p2.y+p3.y+bf.y,0.f);
            a0n.z=fmaxf(p0.z+p1.z+p2.z+p3.z+bf.z,0.f); a0n.w=fmaxf(p0.w+p1.w+p2.w+p3.w+bf.w,0.f);
            p0=*(const float4*)&d_fc1p[0][aoff+k0+4]; p1=*(const float4*)&d_fc1p[1][aoff+k0+4];
            p2=*(const float4*)&d_fc1p[2][aoff+k0+4]; p3=*(const float4*)&d_fc1p[3][aoff+k0+4];
            bf=*(const float4*)&b_fc1[kb+ak+k0+4];
            a1n.x=fmaxf(p0.x+p1.x+p2.x+p3.x+bf.x,0.f); a1n.y=fmaxf(p0.y+p1.y+p2.y+p3.y+bf.y,0.f);
            a1n.z=fmaxf(p0.z+p1.z+p2.z+p3.z+bf.z,0.f); a1n.w=fmaxf(p0.w+p1.w+p2.w+p3.w+bf.w,0.f);
            b0n = Brow ? *(const float4*)(Brow+k0)   : make_float4(0,0,0,0);
            b1n = Brow ? *(const float4*)(Brow+k0+4) : make_float4(0,0,0,0);
        }
#pragma unroll
        for (int kk=0; kk<16; kk++){
            const float* Ar = &As[cur][kk][ty*8];
            const float* Br = &Bs[cur][kk][tx*8];
            float4 af0 = *(const float4*)Ar, af1 = *(const float4*)(Ar+4);
            ulonglong2 bq0 = *(const ulonglong2*)Br;
            ulonglong2 bq1 = *(const ulonglong2*)(Br+4);
            float av[8] = {af0.x,af0.y,af0.z,af0.w,af1.x,af1.y,af1.z,af1.w};
#pragma unroll
            for (int i=0;i<8;i++){
                ull ap = pkdup(av[i]);
                fma2(acc[i][0], ap, bq0.x);
                fma2(acc[i][1], ap, bq0.y);
                fma2(acc[i][2], ap, bq1.x);
                fma2(acc[i][3], ap, bq1.y);
            }
        }
        if (it+1 < NT){
            int nb = cur^1;
#pragma unroll
            for (int j=0;j<4;j++){
                As[nb][ak+j][arow]=((const float*)&a0n)[j]; As[nb][ak+4+j][arow]=((const float*)&a1n)[j];
                Bs[nb][ak+j][arow]=((const float*)&b0n)[j]; Bs[nb][ak+4+j][arow]=((const float*)&b1n)[j];
            }
        }
        __syncthreads();
    }

    float* Cp = d_lpp[blockIdx.z];
    const int c0 = col0 + tx*8;
    if (c0 + 8 <= VV){
#pragma unroll
        for (int i=0;i<8;i++){
            int r = row0 + ty*8 + i;
            float2 q0=upk2(acc[i][0]), q1=upk2(acc[i][1]), q2=upk2(acc[i][2]), q3=upk2(acc[i][3]);
            *(float4*)&Cp[(size_t)r*VV + c0]     = make_float4(q0.x,q0.y,q1.x,q1.y);
            *(float4*)&Cp[(size_t)r*VV + c0 + 4] = make_float4(q2.x,q2.y,q3.x,q3.y);
        }
    }
}

// ---------------- warp LSE ---------------------------------------------------------
__device__ __forceinline__ float warpLSE(const float* __restrict__ base,
                                         const float* __restrict__ t1,
                                         const float* __restrict__ t2){
    int lane = threadIdx.x & 31;
    float m = -INFINITY, s = 0.f;
    for (int n = lane; n < NP; n += 32){
        float x = base[n];
        if (t1) x -= t1[n];
        if (t2) x -= t2[n];
        if (x > m){ s = s*expf(m-x) + 1.f; m = x; } else s += expf(x-m);
    }
#pragma unroll
    for (int off=16; off; off>>=1){
        float m2 = __shfl_xor_sync(0xffffffffu, m, off);
        float s2 = __shfl_xor_sync(0xffffffffu, s, off);
        float mm = fmaxf(m, m2);
        s = s*expf(m-mm) + s2*expf(m2-mm);
        m = mm;
    }
    return m + logf(s);
}

// ---------------- fused select (per batch element) ---------------------------------
__global__ void __launch_bounds__(256) select_kernel(const float* __restrict__ gu,
                                                     const float* __restrict__ b_out,
                                                     int t, int cur){
    __shared__ float pool[KB*NP + NP];
    __shared__ float rv[256];
    __shared__ int   ri[256];
    __shared__ float entS[KB], phiS[KB], gvalS[KB], logIs_s[KB+1];
    __shared__ int   ordS[KB], snewS[KB];

    const int i = blockIdx.x, tid = threadIdx.x;
    const int lane = tid & 31, w = tid >> 5;
    float (*gm)[VV] = (float(*)[VV])pool;

    const int r = w*BB + i;
    const size_t rb = (size_t)r*VV;

    float lv[13];
#pragma unroll
    for (int ii=0; ii<13; ii++){
        int v = lane + ii*32;
        float val = -INFINITY;
        if (v < VV)
            val = d_lpp[0][rb+v] + d_lpp[1][rb+v] + d_lpp[2][rb+v] + d_lpp[3][rb+v] + b_out[v];
        lv[ii] = val;
    }
    float m = -INFINITY;
#pragma unroll
    for (int ii=0; ii<13; ii++) m = fmaxf(m, lv[ii]);
#pragma unroll
    for (int off=16; off; off>>=1) m = fmaxf(m, __shfl_xor_sync(0xffffffffu, m, off));
    float s = 0.f;
#pragma unroll
    for (int ii=0; ii<13; ii++){ int v = lane+ii*32; if (v < VV) s += expf(lv[ii]-m); }
#pragma unroll
    for (int off=16; off; off>>=1) s += __shfl_xor_sync(0xffffffffu, s, off);
    float lse = m + logf(s);

    float lpr = d_logp[cur][r];
    float Gr  = d_Gmx[cur][r];
    const float* u = gu + ((size_t)t*RR + r)*VV;
    float ent = 0.f, zm = -INFINITY;
#pragma unroll
    for (int ii=0; ii<13; ii++){
        int v = lane + ii*32;
        if (v >= VV) continue;
        float l = lv[ii]-lse;
        d_lpn[rb+v] = l;
        ent += l*expf(l);
        float gmb = -logf(-logf(u[v]*(1.f-2e-7f)+1e-7f));
        float gph = l + lpr + gmb;
        gm[w][v] = gph;
        zm = fmaxf(zm, gph);
    }
#pragma unroll
    for (int off=16; off; off>>=1){
        ent += __shfl_xor_sync(0xffffffffu, ent, off);
        zm = fmaxf(zm, __shfl_xor_sync(0xffffffffu, zm, off));
    }
    if (lane==0) entS[w] = ent;
    for (int v=lane; v<VV; v+=32){
        float gph = gm[w][v];
        float vv = Gr - gph + log1mexp(gph - zm);
        float val = Gr - fmaxf(vv,0.f) - log1pf(expf(-fabsf(vv)));
        gm[w][v] = (t==0 && w>0) ? -INFINITY : val;
    }
    __syncthreads();

    for (int round=0; round<KB; round++){
        float bv = -INFINITY; int bi = 0x7fffffff;
        for (int idx=tid; idx<KB*VV; idx+=256){
            float v = pool[idx];
            if (v > bv || (v == bv && idx < bi)){ bv=v; bi=idx; }
        }
        rv[tid]=bv; ri[tid]=bi; __syncthreads();
        for (int off=128; off; off>>=1){
            if (tid < off){
                if (rv[tid+off] > rv[tid] || (rv[tid+off]==rv[tid] && ri[tid+off]<ri[tid])){
                    rv[tid]=rv[tid+off]; ri[tid]=ri[tid+off];
                }
            }
            __syncthreads();
        }
        if (tid==0){
            int widx = ri[0]; int j = widx/VV, v = widx - j*VV;
            gvalS[round]=rv[0]; ordS[round]=j; snewS[round]=v;
            pool[widx] = -INFINITY;
        }
        __syncthreads();
    }

    const int nxt = cur^1;
    for (int idx=tid; idx<KB*LL; idx+=256){
        int j = idx/LL, tt = idx - j*LL;
        if (tt == t) continue;
        int rn = j*BB+i, o = ordS[j]*BB+i;
        d_samples[nxt][rn*LL+tt] = d_samples[cur][o*LL+tt];
        d_outputs[nxt][rn*LL+tt] = d_outputs[cur][o*LL+tt];
    }
    if (tid < KB){
        int j = tid, rn = j*BB+i, o = ordS[j]*BB+i, sv = snewS[j];
        float lpv = d_lpn[(size_t)o*VV + sv];
        float nl  = d_logp[cur][o] + lpv;
        d_samples[nxt][rn*LL+t] = (float)sv;
        d_outputs[nxt][rn*LL+t] = lpv;
        d_logp[nxt][rn] = nl;
        d_Gmx[nxt][rn]  = gvalS[j];
        d_prev[rn]  = sv;
        d_order[rn] = o;
        d_phik[i*KB+j] = nl;
        phiS[j] = nl;
    }
    __syncthreads();

    float (*Ts)[NP] = (float(*)[NP])pool;
    float* base = pool + KB*NP;
    float p[KB], pS = 0.f;
#pragma unroll
    for (int j=0;j<KB;j++){ p[j] = expf(phiS[j]); pS += p[j]; }
    for (int n=tid; n<NP; n+=256){
        float lu = logf(((float)n + 0.5f)/(float)NP);
        float bs = -pS*lu;
#pragma unroll
        for (int j=0;j<KB;j++){
            float x = log1mexp(p[j]*lu);
            Ts[j][n] = x;
            bs += x;
        }
        base[n] = bs;
    }
    __syncthreads();

    const float logN = logf((float)NP);
    float resA = warpLSE(base, Ts[w], nullptr) - logN;
    if (lane==0) logIs_s[w] = resA;
    if (w==0){
        float li = warpLSE(base, nullptr, nullptr) - logN;
        if (lane==0) logIs_s[KB] = li;
    }
    __syncthreads();
    float logI = logIs_s[KB];
    if (tid < KB) d_logRs[i*KB+tid] = logIs_s[tid] - logI;

    for (int pp = w; pp < 28; pp += 8){
        int a = 0, rem = pp;
        while (rem >= 7 - a){ rem -= (7 - a); a++; }
        int b = a + 1 + rem;
        float lss = warpLSE(base, Ts[a], Ts[b]) - logN;
        if (lane==0){
            d_logRss[i*64 + a*8 + b] = lss - logIs_s[a];
            d_logRss[i*64 + b*8 + a] = lss - logIs_s[b];
        }
    }
    if (tid < KB) d_logRss[i*64 + tid*9] = 0.f;
    if (tid == 0){
        float Wsum = 0.f, ws = 0.f;
#pragma unroll
        for (int j=0;j<KB;j++){
            float wq = expf(phiS[j] + logIs_s[j] - logI);
            Wsum += wq;
            ws   += wq * entS[ordS[j]];
        }
        d_entplot[i] += ws;
        d_entelem[i] += ws / Wsum;
    }
}

// ---------------- output assembly ---------------------------------------------------
__global__ void finalize_kernel(float* __restrict__ out, int out_size){
    int idx = blockIdx.x*blockDim.x + threadIdx.x;
    if (idx >= out_size || idx >= 18560) return;
    const int FIN = LL & 1;
    if (idx < 6656){
        int i = idx/104, rem = idx%104, j = rem/13, tt = rem%13;
        out[idx] = d_outputs[FIN][(j*BB+i)*LL + tt];
    } else if (idx < 13312){
        int q = idx - 6656;
        int i = q/104, rem = q%104, j = rem/13, tt = rem%13;
        out[idx] = d_samples[FIN][(j*BB+i)*LL + tt];
    } else if (idx < 13376){
        out[idx] = d_entelem[idx-13312];
    } else if (idx < 13888){
        out[idx] = d_logRs[idx-13376];
    } else if (idx < 17984){
        out[idx] = d_logRss[idx-13888];
    } else if (idx < 18496){
        out[idx] = d_phik[idx-17984];
    } else {
        out[idx] = d_entplot[idx-18496];
    }
}

// ---------------- host driver ---------------------------------------------------------
extern "C" void kernel_launch(void* const* d_in, const int* in_sizes, int n_in,
                              void* d_out, int out_size){
    const float* x_feat  = (const float*)d_in[0];
    const float* W_in_op = (const float*)d_in[1];
    const float* b_in_op = (const float*)d_in[2];
    const float* W_ih    = (const float*)d_in[3];
    const float* W_hh    = (const float*)d_in[4];
    const float* b_ih    = (const float*)d_in[5];
    const float* b_hh    = (const float*)d_in[6];
    const float* W_fc1   = (const float*)d_in[7];
    const float* b_fc1   = (const float*)d_in[8];
    const float* W_out   = (const float*)d_in[9];
    const float* b_out   = (const float*)d_in[10];
    const float* gu      = (const float*)d_in[11];
    (void)in_sizes; (void)n_in;

    void* tmp;
    cudaGetSymbolAddress(&tmp, d_ht);    float* p_ht  = (float*)tmp;
    cudaGetSymbolAddress(&tmp, d_xW);    float* p_xW  = (float*)tmp;
    cudaGetSymbolAddress(&tmp, d_E);     float* p_E   = (float*)tmp;
    cudaGetSymbolAddress(&tmp, d_Gt);    float* p_Gt  = (float*)tmp;

    cudaFuncSetAttribute(gates_mma, cudaFuncAttributeMaxDynamicSharedMemorySize, GM_DSMEM);

    init_kernel<<<256,256>>>(W_in_op, b_in_op);
    reorder_whh<<<(G4*HH+255)/256,256>>>(W_hh);
    split_whh<<<(G4*HH+255)/256,256>>>();

    gemm_db<1><<<dim3(64,1),256>>>(x_feat,1024, W_ih,1152, p_xW,G4,
                                   BB,G4,1024, b_ih, b_hh);
    gemm_db<0><<<dim3(64,7),256>>>(p_E,128, W_ih+1024,1152, p_Gt,G4,
                                   V1,G4,128, nullptr, nullptr);
    permute_gates<<<((BB+V1)*G4+255)/256,256>>>();

    for (int t = 0; t < LL; t++){
        int cur = t & 1;
        if (t == 0){
            lstm0<<<RR,256>>>();
        } else {
            gates_mma<<<dim3(32,4),256,GM_DSMEM>>>(cur);
        }
        gemm_fc1_f2<<<dim3(8,4,SK),256>>>(p_ht + (size_t)cur*RR*HH, W_fc1);
        gemm_out_f2<<<dim3(4,4,SK),256>>>(W_out, b_fc1);
        select_kernel<<<BB,256>>>(gu, b_out, t, cur);
    }

    finalize_kernel<<<(18560+255)/256,256>>>((float*)d_out, out_size);
}

// round 7
// speedup vs baseline: 2.1889x; 1.0012x over previous
#include <cuda_runtime.h>
#include <cuda_bf16.h>
#include <math.h>
#include <stdint.h>

#define BB 64      // batch
#define KB 8       // beams
#define RR 512     // BB*KB
#define HH 1024    // hidden
#define VV 400     // vocab
#define V1 401
#define LL 13      // program_len
#define G4 4096    // 4*HH
#define NP 1000    // log_R quadrature points
#define SK 4       // split-K slices for fc1/out

typedef unsigned long long ull;

// ---------------- persistent scratch -----------------------------------------
__device__ float d_ht[2][RR*HH];
__device__ float d_ct[2][RR*HH];
__device__ float d_Gmx[2][RR];
__device__ float d_logp[2][RR];
__device__ int   d_prev[RR];
__device__ int   d_order[RR];
__device__ float d_samples[2][RR*LL];
__device__ float d_outputs[2][RR*LL];
__device__ float d_entplot[BB];
__device__ float d_entelem[BB];
__device__ float d_xW[BB*G4];
__device__ float d_xW2[BB*G4];
__device__ float d_E[V1*128];
__device__ float d_Gt[V1*G4];
__device__ float d_Gt2[V1*G4];
__device__ float d_Whh2[G4*HH];
__device__ __nv_bfloat16 d_wb[3][G4*HH];      // W_hh2 bf16 3-way splits
__device__ __nv_bfloat16 d_hb[2][3][RR*HH];   // h bf16 3-way splits (double buffered)
__device__ float d_fc1p[SK][RR*HH];
__device__ float d_lpp[SK][RR*VV];
__device__ float d_lpn[RR*VV];
__device__ float d_phik[BB*KB];
__device__ float d_logRs[BB*KB];
__device__ float d_logRss[BB*KB*KB];

// ---------------- helpers ------------------------------------------------------
__device__ __forceinline__ float sigmoidf(float x){ return 1.f/(1.f+expf(-x)); }

__device__ __forceinline__ float log1mexp(float x){
    x = fminf(x, -1e-38f);
    if (x > -0.6931472f) return logf(-expm1f(x));
    return log1pf(-expf(x));
}

__device__ __forceinline__ ull pkdup(float x){
    ull r; unsigned u = __float_as_uint(x);
    asm("mov.b64 %0, {%1, %1};" : "=l"(r) : "r"(u));
    return r;
}
__device__ __forceinline__ float2 upk2(ull v){
    unsigned lo, hi;
    asm("mov.b64 {%0, %1}, %2;" : "=r"(lo), "=r"(hi) : "l"(v));
    return make_float2(__uint_as_float(lo), __uint_as_float(hi));
}
__device__ __forceinline__ void fma2(ull &c, ull a, ull b){
    asm("fma.rn.f32x2 %0, %1, %2, %0;" : "+l"(c) : "l"(a), "l"(b));
}

__device__ __forceinline__ uint32_t smem_u32(const void* p){
    uint32_t a;
    asm("{ .reg .u64 t; cvta.to.shared.u64 t, %1; cvt.u32.u64 %0, t; }" : "=r"(a) : "l"(p));
    return a;
}

// ldmatrix (sm_75+, valid on plain sm_103)
__device__ __forceinline__ void ldsm_x4(unsigned* r, uint32_t addr){
    asm volatile("ldmatrix.sync.aligned.m8n8.x4.shared.b16 {%0,%1,%2,%3}, [%4];"
        : "=r"(r[0]), "=r"(r[1]), "=r"(r[2]), "=r"(r[3]) : "r"(addr));
}
__device__ __forceinline__ void ldsm_x2(unsigned* r, uint32_t addr){
    asm volatile("ldmatrix.sync.aligned.m8n8.x2.shared.b16 {%0,%1}, [%2];"
        : "=r"(r[0]), "=r"(r[1]) : "r"(addr));
}
// mma.sync bf16 (sm_80+, valid on plain sm_103)
__device__ __forceinline__ void mma_bf16(float* c, const unsigned* a, const unsigned* b){
    asm volatile("mma.sync.aligned.m16n8k16.row.col.f32.bf16.bf16.f32 "
        "{%0,%1,%2,%3}, {%4,%5,%6,%7}, {%8,%9}, {%0,%1,%2,%3};"
        : "+f"(c[0]), "+f"(c[1]), "+f"(c[2]), "+f"(c[3])
        : "r"(a[0]), "r"(a[1]), "r"(a[2]), "r"(a[3]), "r"(b[0]), "r"(b[1]));
}

// ---------------- init ----------------------------------------------------------
__global__ void init_kernel(const float* __restrict__ W_in_op,
                            const float* __restrict__ b_in_op){
    int idx = blockIdx.x*blockDim.x + threadIdx.x;
    int stride = gridDim.x*blockDim.x;
    for (int i = idx; i < RR;    i += stride){ d_Gmx[0][i]=0.f; d_logp[0][i]=0.f; }
    for (int i = idx; i < RR*LL; i += stride){ d_samples[0][i]=0.f; d_outputs[0][i]=0.f; }
    for (int i = idx; i < BB;    i += stride){ d_entplot[i]=0.f; d_entelem[i]=0.f; }
    for (int i = idx; i < V1*128; i += stride){
        int s = i >> 7, m = i & 127;
        d_E[i] = fmaxf(W_in_op[m*V1 + s] + b_in_op[m], 0.f);
    }
}

__global__ void reorder_whh(const float* __restrict__ W){
    int idx = blockIdx.x*blockDim.x + threadIdx.x;
    if (idx >= G4*HH) return;
    int c = idx >> 10, k = idx & 1023;
    int h = c >> 2, g = c & 3;
    d_Whh2[idx] = W[(size_t)(g*HH + h)*HH + k];
}

__global__ void split_whh(){
    int idx = blockIdx.x*blockDim.x + threadIdx.x;
    if (idx >= G4*HH) return;
    float w = d_Whh2[idx];
    __nv_bfloat16 b0 = __float2bfloat16(w);
    float r1 = w - __bfloat162float(b0);
    __nv_bfloat16 b1 = __float2bfloat16(r1);
    float r2 = r1 - __bfloat162float(b1);
    d_wb[0][idx] = b0;
    d_wb[1][idx] = b1;
    d_wb[2][idx] = __float2bfloat16(r2);
}

__global__ void permute_gates(){
    int idx = blockIdx.x*blockDim.x + threadIdx.x;
    if (idx >= (BB+V1)*G4) return;
    int row = idx / G4, c = idx - row*G4;
    int g = c >> 10, h = c & 1023;
    int dstc = 4*h + g;
    if (row < BB) d_xW2[row*G4 + dstc] = d_xW[idx];
    else          d_Gt2[(row-BB)*G4 + dstc] = d_Gt[idx - BB*G4];
}

// ---------------- t=0 LSTM: also emits bf16 splits of h --------------------------
__global__ void __launch_bounds__(256) lstm0(){
    int r = blockIdx.x, tid = threadIdx.x;
    int b = r & 63;
    for (int u = tid; u < HH; u += 256){
        float4 xw = *(const float4*)&d_xW2[(size_t)b*G4 + u*4];
        float4 gt = *(const float4*)&d_Gt2[(size_t)VV*G4 + u*4];
        float ig = xw.x+gt.x, gg = xw.z+gt.z, og = xw.w+gt.w;
        float cn = sigmoidf(ig)*tanhf(gg);
        float hn = sigmoidf(og)*tanhf(cn);
        d_ct[0][(size_t)r*HH+u] = cn;
        d_ht[0][(size_t)r*HH+u] = hn;
        __nv_bfloat16 s0 = __float2bfloat16(hn);
        float r1 = hn - __bfloat162float(s0);
        __nv_bfloat16 s1 = __float2bfloat16(r1);
        float r2 = r1 - __bfloat162float(s1);
        d_hb[0][0][(size_t)r*HH+u] = s0;
        d_hb[0][1][(size_t)r*HH+u] = s1;
        d_hb[0][2][(size_t)r*HH+u] = __float2bfloat16(r2);
    }
}

// ---------------- setup GEMM (64x64x16 double buffered, scalar) -------------------
template<int MODE>
__global__ void __launch_bounds__(256) gemm_db(
    const float* __restrict__ A, int lda,
    const float* __restrict__ B, int ldb,
    float* __restrict__ C, int ldc,
    int M, int N, int K,
    const float* __restrict__ bias1,
    const float* __restrict__ bias2)
{
    __shared__ float As[2][16][64+4];
    __shared__ float Bs[2][16][64+4];
    const int tid = threadIdx.x;
    const int row0 = blockIdx.y*64, col0 = blockIdx.x*64;
    const int arow = tid >> 2, ak = (tid & 3)*4;
    const int ty = tid >> 4, tx = tid & 15;

    const int ar = row0 + arow, br = col0 + arow;
    float4 a4 = make_float4(0,0,0,0), b4 = make_float4(0,0,0,0);
    if (ar < M) a4 = *(const float4*)(A + (size_t)ar*lda + ak);
    if (br < N) b4 = *(const float4*)(B + (size_t)br*ldb + ak);
    As[0][ak+0][arow]=a4.x; As[0][ak+1][arow]=a4.y; As[0][ak+2][arow]=a4.z; As[0][ak+3][arow]=a4.w;
    Bs[0][ak+0][arow]=b4.x; Bs[0][ak+1][arow]=b4.y; Bs[0][ak+2][arow]=b4.z; Bs[0][ak+3][arow]=b4.w;
    __syncthreads();

    float acc[4][4];
#pragma unroll
    for (int i=0;i<4;i++)
#pragma unroll
        for (int j=0;j<4;j++) acc[i][j]=0.f;

    const int NT = K/16;
    for (int it=0; it<NT; it++){
        int cur = it & 1;
        float4 a4n, b4n;
        if (it+1 < NT){
            int k0 = (it+1)*16;
            a4n = make_float4(0,0,0,0); b4n = make_float4(0,0,0,0);
            if (ar < M) a4n = *(const float4*)(A + (size_t)ar*lda + k0 + ak);
            if (br < N) b4n = *(const float4*)(B + (size_t)br*ldb + k0 + ak);
        }
#pragma unroll
        for (int kk=0; kk<16; kk++){
            float4 ra = *(const float4*)&As[cur][kk][ty*4];
            float4 rb = *(const float4*)&Bs[cur][kk][tx*4];
            float r[4]={ra.x,ra.y,ra.z,ra.w};
            float cb[4]={rb.x,rb.y,rb.z,rb.w};
#pragma unroll
            for (int i=0;i<4;i++)
#pragma unroll
                for (int j=0;j<4;j++) acc[i][j] = fmaf(r[i], cb[j], acc[i][j]);
        }
        if (it+1 < NT){
            int nb = cur^1;
            As[nb][ak+0][arow]=a4n.x; As[nb][ak+1][arow]=a4n.y; As[nb][ak+2][arow]=a4n.z; As[nb][ak+3][arow]=a4n.w;
            Bs[nb][ak+0][arow]=b4n.x; Bs[nb][ak+1][arow]=b4n.y; Bs[nb][ak+2][arow]=b4n.z; Bs[nb][ak+3][arow]=b4n.w;
        }
        __syncthreads();
    }
#pragma unroll
    for (int i=0;i<4;i++){
        int r = row0 + ty*4 + i;
        if (r >= M) continue;
#pragma unroll
        for (int j=0;j<4;j++){
            int c = col0 + tx*4 + j;
            if (c >= N) continue;
            float v = acc[i][j];
            if (MODE==1) v += bias1[c] + bias2[c];
            else if (MODE==3) v = fmaxf(v + bias1[c], 0.f);
            else if (MODE==4) v += bias1[c];
            C[(size_t)r*ldc + c] = v;
        }
    }
}

// ---------------- gates GEMM via mma.sync bf16x3 + fused LSTM ---------------------
// CTA 128x128, 8 warps (2x4), warp tile 64x32. K chunks of 16, double buffered.
#define CH_TILE 6144                 // 128 rows * 48B padded
#define CH_BUF  (6*CH_TILE)          // 3 A splits + 3 B splits = 36864 B
#define GM_DSMEM (2*CH_BUF)          // 73728 B (also covers 128x132 f32 epilogue buf)

__global__ void __launch_bounds__(256) gates_mma(int cur){
    extern __shared__ char dsm[];
    __shared__ int ord_s[128];
    const int tid = threadIdx.x, w = tid>>5, lane = tid&31;
    const int prv = cur^1;
    const int row0 = blockIdx.y*128, col0 = blockIdx.x*128;
    const int wr = w>>2, wc = w&3;
    const uint32_t dbase = smem_u32(dsm);

    if (tid < 128) ord_s[tid] = d_order[row0 + tid];
    __syncthreads();

    const __nv_bfloat16* Asrc[3] = {d_hb[prv][0], d_hb[prv][1], d_hb[prv][2]};
    const __nv_bfloat16* Bsrc[3] = {d_wb[0], d_wb[1], d_wb[2]};

    // per-thread chunk-load slots: 6 uint4 each
    const int ld_t    = tid >> 8;          // always 0; tile index derived below
    (void)ld_t;
    int  ld_tile[6], ld_row[6], ld_half[6];
    const __nv_bfloat16* ld_src[6];
#pragma unroll
    for (int j=0;j<6;j++){
        int idx = tid + j*256;
        int t = idx >> 8, pos = idx & 255;
        int row = pos >> 1, half = pos & 1;
        ld_tile[j]=t; ld_row[j]=row; ld_half[j]=half;
        if (t < 3) ld_src[j] = Asrc[t]   + (size_t)ord_s[row]*HH + half*8;
        else       ld_src[j] = Bsrc[t-3] + (size_t)(col0+row)*HH + half*8;
    }

    float acc[4][4][4];
#pragma unroll
    for (int mi=0;mi<4;mi++)
#pragma unroll
        for (int ni=0;ni<4;ni++)
#pragma unroll
            for (int e=0;e<4;e++) acc[mi][ni][e]=0.f;

    uint4 v[6];
#pragma unroll
    for (int j=0;j<6;j++) v[j] = *(const uint4*)(ld_src[j]);
    {
        char* bp = dsm;
#pragma unroll
        for (int j=0;j<6;j++)
            *(uint4*)(bp + ld_tile[j]*CH_TILE + ld_row[j]*48 + ld_half[j]*16) = v[j];
    }
    __syncthreads();

    // ldmatrix base addresses (per-thread constants modulo buffer/k-tile offsets)
    const uint32_t a_lm = dbase + (wr*64 + (lane&15))*48 + (lane>>4)*16;
    const uint32_t b_lm = dbase + (wc*32 + (lane&7))*48 + ((lane>>3)&1)*16;

    for (int kc = 0; kc < 64; kc++){
        if (kc+1 < 64){
#pragma unroll
            for (int j=0;j<6;j++) v[j] = *(const uint4*)(ld_src[j] + (kc+1)*16);
        }
        const uint32_t bb = (kc&1)*CH_BUF;

        unsigned Bf[3][4][2];
#pragma unroll
        for (int s=0;s<3;s++)
#pragma unroll
            for (int ni=0;ni<4;ni++)
                ldsm_x2(Bf[s][ni], b_lm + bb + (3+s)*CH_TILE + ni*8*48);

#pragma unroll
        for (int s=0;s<3;s++){
            unsigned Af[4][4];
#pragma unroll
            for (int mi=0;mi<4;mi++)
                ldsm_x4(Af[mi], a_lm + bb + s*CH_TILE + mi*16*48);
            const int nb = (s==0)?3:((s==1)?2:1);
#pragma unroll
            for (int jb=0;jb<3;jb++){
                if (jb >= nb) break;
#pragma unroll
                for (int mi=0;mi<4;mi++)
#pragma unroll
                    for (int ni=0;ni<4;ni++)
                        mma_bf16(acc[mi][ni], Af[mi], Bf[jb][ni]);
            }
        }

        if (kc+1 < 64){
            char* bp = dsm + ((kc+1)&1)*CH_BUF;
#pragma unroll
            for (int j=0;j<6;j++)
                *(uint4*)(bp + ld_tile[j]*CH_TILE + ld_row[j]*48 + ld_half[j]*16) = v[j];
        }
        __syncthreads();
    }

    // ---- epilogue: dump gates to smem, then LSTM ----
    float* gs = (float*)dsm;                      // 128 x 132 f32
#pragma unroll
    for (int mi=0;mi<4;mi++)
#pragma unroll
        for (int ni=0;ni<4;ni++)
#pragma unroll
            for (int e=0;e<4;e++){
                int rl = wr*64 + mi*16 + (lane>>2) + 8*(e>>1);
                int cl = wc*32 + ni*8 + 2*(lane&3) + (e&1);
                gs[rl*132 + cl] = acc[mi][ni][e];
            }
    __syncthreads();

    const int r  = tid >> 1;
    const int r_ = row0 + r;
    const int o  = ord_s[r];
    const int pv = d_prev[r_];
    const int bi = r_ & 63;
    const int ub = (tid & 1)*16;
#pragma unroll
    for (int q=0;q<16;q++){
        int ul = ub + q;
        int u  = (col0>>2) + ul;
        float4 g4 = *(float4*)&gs[r*132 + ul*4];
        float4 xw = *(const float4*)&d_xW2[(size_t)bi*G4 + col0 + ul*4];
        float4 gt = *(const float4*)&d_Gt2[(size_t)pv*G4 + col0 + ul*4];
        float ig = g4.x + xw.x + gt.x;
        float fg = g4.y + xw.y + gt.y;
        float gg = g4.z + xw.z + gt.z;
        float og = g4.w + xw.w + gt.w;
        float cold = d_ct[prv][(size_t)o*HH + u];
        float cn = sigmoidf(fg)*cold + sigmoidf(ig)*tanhf(gg);
        float hn = sigmoidf(og)*tanhf(cn);
        d_ct[cur][(size_t)r_*HH + u] = cn;
        d_ht[cur][(size_t)r_*HH + u] = hn;
        __nv_bfloat16 s0 = __float2bfloat16(hn);
        float rr1 = hn - __bfloat162float(s0);
        __nv_bfloat16 s1 = __float2bfloat16(rr1);
        float rr2 = rr1 - __bfloat162float(s1);
        d_hb[cur][0][(size_t)r_*HH + u] = s0;
        d_hb[cur][1][(size_t)r_*HH + u] = s1;
        d_hb[cur][2][(size_t)r_*HH + u] = __float2bfloat16(rr2);
    }
}

// ---------------- fc1 split-K GEMM (128x128, f32x2): partials, no bias -----------
__global__ void __launch_bounds__(256) gemm_fc1_f2(
    const float* __restrict__ A, const float* __restrict__ W)
{
    __shared__ float As[2][16][128+4];
    __shared__ float Bs[2][16][128+4];
    const int tid = threadIdx.x;
    const int row0 = blockIdx.y*128, col0 = blockIdx.x*128;
    const int kb = blockIdx.z * (HH/SK);
    const int arow = tid >> 1, ak = (tid & 1)*8;
    const int ty = tid >> 4, tx = tid & 15;

    const float* Arow = A + (size_t)(row0+arow)*HH + kb + ak;
    const float* Brow = W + (size_t)(col0+arow)*HH + kb + ak;

    float4 a0 = *(const float4*)Arow, a1 = *(const float4*)(Arow+4);
    float4 b0 = *(const float4*)Brow, b1 = *(const float4*)(Brow+4);
#pragma unroll
    for (int j=0;j<4;j++){
        As[0][ak+j][arow]=((const float*)&a0)[j]; As[0][ak+4+j][arow]=((const float*)&a1)[j];
        Bs[0][ak+j][arow]=((const float*)&b0)[j]; Bs[0][ak+4+j][arow]=((const float*)&b1)[j];
    }
    __syncthreads();

    ull acc[8][4];
#pragma unroll
    for (int i=0;i<8;i++)
#pragma unroll
        for (int p=0;p<4;p++) acc[i][p]=0ull;

    const int NT = (HH/SK)/16;
    for (int it=0; it<NT; it++){
        int cur = it & 1;
        float4 a0n,a1n,b0n,b1n;
        if (it+1 < NT){
            int k0 = (it+1)*16;
            a0n=*(const float4*)(Arow+k0); a1n=*(const float4*)(Arow+k0+4);
            b0n=*(const float4*)(Brow+k0); b1n=*(const float4*)(Brow+k0+4);
        }
#pragma unroll
        for (int kk=0; kk<16; kk++){
            const float* Ar = &As[cur][kk][ty*8];
            const float* Br = &Bs[cur][kk][tx*8];
            float4 af0 = *(const float4*)Ar, af1 = *(const float4*)(Ar+4);
            ulonglong2 bq0 = *(const ulonglong2*)Br;
            ulonglong2 bq1 = *(const ulonglong2*)(Br+4);
            float av[8] = {af0.x,af0.y,af0.z,af0.w,af1.x,af1.y,af1.z,af1.w};
#pragma unroll
            for (int i=0;i<8;i++){
                ull ap = pkdup(av[i]);
                fma2(acc[i][0], ap, bq0.x);
                fma2(acc[i][1], ap, bq0.y);
                fma2(acc[i][2], ap, bq1.x);
                fma2(acc[i][3], ap, bq1.y);
            }
        }
        if (it+1 < NT){
            int nb = cur^1;
#pragma unroll
            for (int j=0;j<4;j++){
                As[nb][ak+j][arow]=((const float*)&a0n)[j]; As[nb][ak+4+j][arow]=((const float*)&a1n)[j];
                Bs[nb][ak+j][arow]=((const float*)&b0n)[j]; Bs[nb][ak+4+j][arow]=((const float*)&b1n)[j];
            }
        }
        __syncthreads();
    }

    float* Cp = d_fc1p[blockIdx.z];
#pragma unroll
    for (int i=0;i<8;i++){
        int r = row0 + ty*8 + i;
        float2 q0=upk2(acc[i][0]), q1=upk2(acc[i][1]), q2=upk2(acc[i][2]), q3=upk2(acc[i][3]);
        *(float4*)&Cp[(size_t)r*HH + col0 + tx*8]     = make_float4(q0.x,q0.y,q1.x,q1.y);
        *(float4*)&Cp[(size_t)r*HH + col0 + tx*8 + 4] = make_float4(q2.x,q2.y,q3.x,q3.y);
    }
}

// ---------------- out split-K GEMM: A = relu(sum fc1 partials + b_fc1) -----------
__global__ void __launch_bounds__(256) gemm_out_f2(
    const float* __restrict__ W, const float* __restrict__ b_fc1)
{
    __shared__ float As[2][16][128+4];
    __shared__ float Bs[2][16][128+4];
    const int tid = threadIdx.x;
    const int row0 = blockIdx.y*128, col0 = blockIdx.x*128;
    const int kb = blockIdx.z * (HH/SK);
    const int arow = tid >> 1, ak = (tid & 1)*8;
    const int ty = tid >> 4, tx = tid & 15;
    const int br = col0 + arow;

    const size_t aoff = (size_t)(row0+arow)*HH + kb + ak;
    const float* Brow = (br < VV) ? (W + (size_t)br*HH + kb + ak) : nullptr;

    float4 a0, a1, b0, b1;
    {
        float4 p0=*(const float4*)&d_fc1p[0][aoff], p1=*(const float4*)&d_fc1p[1][aoff];
        float4 p2=*(const float4*)&d_fc1p[2][aoff], p3=*(const float4*)&d_fc1p[3][aoff];
        float4 bf=*(const float4*)&b_fc1[kb+ak];
        a0.x=fmaxf(p0.x+p1.x+p2.x+p3.x+bf.x,0.f); a0.y=fmaxf(p0.y+p1.y+p2.y+p3.y+bf.y,0.f);
        a0.z=fmaxf(p0.z+p1.z+p2.z+p3.z+bf.z,0.f); a0.w=fmaxf(p0.w+p1.w+p2.w+p3.w+bf.w,0.f);
        p0=*(const float4*)&d_fc1p[0][aoff+4]; p1=*(const float4*)&d_fc1p[1][aoff+4];
        p2=*(const float4*)&d_fc1p[2][aoff+4]; p3=*(const float4*)&d_fc1p[3][aoff+4];
        bf=*(const float4*)&b_fc1[kb+ak+4];
        a1.x=fmaxf(p0.x+p1.x+p2.x+p3.x+bf.x,0.f); a1.y=fmaxf(p0.y+p1.y+p2.y+p3.y+bf.y,0.f);
        a1.z=fmaxf(p0.z+p1.z+p2.z+p3.z+bf.z,0.f); a1.w=fmaxf(p0.w+p1.w+p2.w+p3.w+bf.w,0.f);
        b0 = Brow ? *(const float4*)Brow     : make_float4(0,0,0,0);
        b1 = Brow ? *(const float4*)(Brow+4) : make_float4(0,0,0,0);
    }
#pragma unroll
    for (int j=0;j<4;j++){
        As[0][ak+j][arow]=((const float*)&a0)[j]; As[0][ak+4+j][arow]=((const float*)&a1)[j];
        Bs[0][ak+j][arow]=((const float*)&b0)[j]; Bs[0][ak+4+j][arow]=((const float*)&b1)[j];
    }
    __syncthreads();

    ull acc[8][4];
#pragma unroll
    for (int i=0;i<8;i++)
#pragma unroll
        for (int p=0;p<4;p++) acc[i][p]=0ull;

    const int NT = (HH/SK)/16;
    for (int it=0; it<NT; it++){
        int cur = it & 1;
        float4 a0n,a1n,b0n,b1n;
        if (it+1 < NT){
            int k0 = (it+1)*16;
            float4 p0=*(const float4*)&d_fc1p[0][aoff+k0], p1=*(const float4*)&d_fc1p[1][aoff+k0];
            float4 p2=*(const float4*)&d_fc1p[2][aoff+k0], p3=*(const float4*)&d_fc1p[3][aoff+k0];
            float4 bf=*(const float4*)&b_fc1[kb+ak+k0];
            a0n.x=fmaxf(p0.x+p1.x+p2.x+p3.x+bf.x,0.f); a0n.y=fmaxf(p0.y+p1.y+p2.y+p3.y+bf.y,0.f);
            a0n.z=fmaxf(p0.z+p1.z+p2.z+p3.z+bf.z,0.f); a0n.w=fmaxf(p0.w+p1.w+p2.w+p3.w+bf.w,0.f);
            p0=*(const float4*)&d_fc1p[0][aoff+k0+4]; p1=*(const float4*)&d_fc1p[1][aoff+k0+4];
            p2=*(const float4*)&d_fc1p[2][aoff+k0+4]; p3=*(const float4*)&d_fc1p[3][aoff+k0+4];
            bf=*(const float4*)&b_fc1[kb+ak+k0+4];
            a1n.x=fmaxf(p0.x+p1.x+p2.x+p3.x+bf.x,0.f); a1n.y=fmaxf(p0.y+p1.y+p2.y+p3.y+bf.y,0.f);
            a1n.z=fmaxf(p0.z+p1.z+p2.z+p3.z+bf.z,0.f); a1n.w=fmaxf(p0.w+p1.w+p2.w+p3.w+bf.w,0.f);
            b0n = Brow ? *(const float4*)(Brow+k0)   : make_float4(0,0,0,0);
            b1n = Brow ? *(const float4*)(Brow+k0+4) : make_float4(0,0,0,0);
        }
#pragma unroll
        for (int kk=0; kk<16; kk++){
            const float* Ar = &As[cur][kk][ty*8];
            const float* Br = &Bs[cur][kk][tx*8];
            float4 af0 = *(const float4*)Ar, af1 = *(const float4*)(Ar+4);
            ulonglong2 bq0 = *(const ulonglong2*)Br;
            ulonglong2 bq1 = *(const ulonglong2*)(Br+4);
            float av[8] = {af0.x,af0.y,af0.z,af0.w,af1.x,af1.y,af1.z,af1.w};
#pragma unroll
            for (int i=0;i<8;i++){
                ull ap = pkdup(av[i]);
                fma2(acc[i][0], ap, bq0.x);
                fma2(acc[i][1], ap, bq0.y);
                fma2(acc[i][2], ap, bq1.x);
                fma2(acc[i][3], ap, bq1.y);
            }
        }
        if (it+1 < NT){
            int nb = cur^1;
#pragma unroll
            for (int j=0;j<4;j++){
                As[nb][ak+j][arow]=((const float*)&a0n)[j]; As[nb][ak+4+j][arow]=((const float*)&a1n)[j];
                Bs[nb][ak+j][arow]=((const float*)&b0n)[j]; Bs[nb][ak+4+j][arow]=((const float*)&b1n)[j];
            }
        }
        __syncthreads();
    }

    float* Cp = d_lpp[blockIdx.z];
    const int c0 = col0 + tx*8;
    if (c0 + 8 <= VV){
#pragma unroll
        for (int i=0;i<8;i++){
            int r = row0 + ty*8 + i;
            float2 q0=upk2(acc[i][0]), q1=upk2(acc[i][1]), q2=upk2(acc[i][2]), q3=upk2(acc[i][3]);
            *(float4*)&Cp[(size_t)r*VV + c0]     = make_float4(q0.x,q0.y,q1.x,q1.y);
            *(float4*)&Cp[(size_t)r*VV + c0 + 4] = make_float4(q2.x,q2.y,q3.x,q3.y);
        }
    }
}

// ---------------- warp LSE ---------------------------------------------------------
__device__ __forceinline__ float warpLSE(const float* __restrict__ base,
                                         const float* __restrict__ t1,
                                         const float* __restrict__ t2){
    int lane = threadIdx.x & 31;
    float m = -INFINITY, s = 0.f;
    for (int n = lane; n < NP; n += 32){
        float x = base[n];
        if (t1) x -= t1[n];
        if (t2) x -= t2[n];
        if (x > m){ s = s*expf(m-x) + 1.f; m = x; } else s += expf(x-m);
    }
#pragma unroll
    for (int off=16; off; off>>=1){
        float m2 = __shfl_xor_sync(0xffffffffu, m, off);
        float s2 = __shfl_xor_sync(0xffffffffu, s, off);
        float mm = fmaxf(m, m2);
        s = s*expf(m-mm) + s2*expf(m2-mm);
        m = mm;
    }
    return m + logf(s);
}

// ---------------- fused select (per batch element) ---------------------------------
__global__ void __launch_bounds__(256) select_kernel(const float* __restrict__ gu,
                                                     const float* __restrict__ b_out,
                                                     int t, int cur){
    __shared__ float pool[KB*NP + NP];
    __shared__ float rv[256];
    __shared__ int   ri[256];
    __shared__ float entS[KB], phiS[KB], gvalS[KB], logIs_s[KB+1];
    __shared__ int   ordS[KB], snewS[KB];

    const int i = blockIdx.x, tid = threadIdx.x;
    const int lane = tid & 31, w = tid >> 5;
    float (*gm)[VV] = (float(*)[VV])pool;

    const int r = w*BB + i;
    const size_t rb = (size_t)r*VV;

    float lv[13];
#pragma unroll
    for (int ii=0; ii<13; ii++){
        int v = lane + ii*32;
        float val = -INFINITY;
        if (v < VV)
            val = d_lpp[0][rb+v] + d_lpp[1][rb+v] + d_lpp[2][rb+v] + d_lpp[3][rb+v] + b_out[v];
        lv[ii] = val;
    }
    float m = -INFINITY;
#pragma unroll
    for (int ii=0; ii<13; ii++) m = fmaxf(m, lv[ii]);
#pragma unroll
    for (int off=16; off; off>>=1) m = fmaxf(m, __shfl_xor_sync(0xffffffffu, m, off));
    float s = 0.f;
#pragma unroll
    for (int ii=0; ii<13; ii++){ int v = lane+ii*32; if (v < VV) s += expf(lv[ii]-m); }
#pragma unroll
    for (int off=16; off; off>>=1) s += __shfl_xor_sync(0xffffffffu, s, off);
    float lse = m + logf(s);

    float lpr = d_logp[cur][r];
    float Gr  = d_Gmx[cur][r];
    const float* u = gu + ((size_t)t*RR + r)*VV;
    float ent = 0.f, zm = -INFINITY;
#pragma unroll
    for (int ii=0; ii<13; ii++){
        int v = lane + ii*32;
        if (v >= VV) continue;
        float l = lv[ii]-lse;
        d_lpn[rb+v] = l;
        ent += l*expf(l);
        float gmb = -logf(-logf(u[v]*(1.f-2e-7f)+1e-7f));
        float gph = l + lpr + gmb;
        gm[w][v] = gph;
        zm = fmaxf(zm, gph);
    }
#pragma unroll
    for (int off=16; off; off>>=1){
        ent += __shfl_xor_sync(0xffffffffu, ent, off);
        zm = fmaxf(zm, __shfl_xor_sync(0xffffffffu, zm, off));
    }
    if (lane==0) entS[w] = ent;
    for (int v=lane; v<VV; v+=32){
        float gph = gm[w][v];
        float vv = Gr - gph + log1mexp(gph - zm);
        float val = Gr - fmaxf(vv,0.f) - log1pf(expf(-fabsf(vv)));
        gm[w][v] = (t==0 && w>0) ? -INFINITY : val;
    }
    __syncthreads();

    for (int round=0; round<KB; round++){
        float bv = -INFINITY; int bi = 0x7fffffff;
        for (int idx=tid; idx<KB*VV; idx+=256){
            float v = pool[idx];
            if (v > bv || (v == bv && idx < bi)){ bv=v; bi=idx; }
        }
        rv[tid]=bv; ri[tid]=bi; __syncthreads();
        for (int off=128; off; off>>=1){
            if (tid < off){
                if (rv[tid+off] > rv[tid] || (rv[tid+off]==rv[tid] && ri[tid+off]<ri[tid])){
                    rv[tid]=rv[tid+off]; ri[tid]=ri[tid+off];
                }
            }
            __syncthreads();
        }
        if (tid==0){
            int widx = ri[0]; int j = widx/VV, v = widx - j*VV;
            gvalS[round]=rv[0]; ordS[round]=j; snewS[round]=v;
            pool[widx] = -INFINITY;
        }
        __syncthreads();
    }

    const int nxt = cur^1;
    for (int idx=tid; idx<KB*LL; idx+=256){
        int j = idx/LL, tt = idx - j*LL;
        if (tt == t) continue;
        int rn = j*BB+i, o = ordS[j]*BB+i;
        d_samples[nxt][rn*LL+tt] = d_samples[cur][o*LL+tt];
        d_outputs[nxt][rn*LL+tt] = d_outputs[cur][o*LL+tt];
    }
    if (tid < KB){
        int j = tid, rn = j*BB+i, o = ordS[j]*BB+i, sv = snewS[j];
        float lpv = d_lpn[(size_t)o*VV + sv];
        float nl  = d_logp[cur][o] + lpv;
        d_samples[nxt][rn*LL+t] = (float)sv;
        d_outputs[nxt][rn*LL+t] = lpv;
        d_logp[nxt][rn] = nl;
        d_Gmx[nxt][rn]  = gvalS[j];
        d_prev[rn]  = sv;
        d_order[rn] = o;
        d_phik[i*KB+j] = nl;
        phiS[j] = nl;
    }
    __syncthreads();

    float (*Ts)[NP] = (float(*)[NP])pool;
    float* base = pool + KB*NP;
    float p[KB], pS = 0.f;
#pragma unroll
    for (int j=0;j<KB;j++){ p[j] = expf(phiS[j]); pS += p[j]; }
    for (int n=tid; n<NP; n+=256){
        float lu = logf(((float)n + 0.5f)/(float)NP);
        float bs = -pS*lu;
#pragma unroll
        for (int j=0;j<KB;j++){
            float x = log1mexp(p[j]*lu);
            Ts[j][n] = x;
            bs += x;
        }
        base[n] = bs;
    }
    __syncthreads();

    const float logN = logf((float)NP);
    float resA = warpLSE(base, Ts[w], nullptr) - logN;
    if (lane==0) logIs_s[w] = resA;
    if (w==0){
        float li = warpLSE(base, nullptr, nullptr) - logN;
        if (lane==0) logIs_s[KB] = li;
    }
    __syncthreads();
    float logI = logIs_s[KB];
    if (tid < KB) d_logRs[i*KB+tid] = logIs_s[tid] - logI;

    for (int pp = w; pp < 28; pp += 8){
        int a = 0, rem = pp;
        while (rem >= 7 - a){ rem -= (7 - a); a++; }
        int b = a + 1 + rem;
        float lss = warpLSE(base, Ts[a], Ts[b]) - logN;
        if (lane==0){
            d_logRss[i*64 + a*8 + b] = lss - logIs_s[a];
            d_logRss[i*64 + b*8 + a] = lss - logIs_s[b];
        }
    }
    if (tid < KB) d_logRss[i*64 + tid*9] = 0.f;
    if (tid == 0){
        float Wsum = 0.f, ws = 0.f;
#pragma unroll
        for (int j=0;j<KB;j++){
            float wq = expf(phiS[j] + logIs_s[j] - logI);
            Wsum += wq;
            ws   += wq * entS[ordS[j]];
        }
        d_entplot[i] += ws;
        d_entelem[i] += ws / Wsum;
    }
}

// ---------------- output assembly ---------------------------------------------------
__global__ void finalize_kernel(float* __restrict__ out, int out_size){
    int idx = blockIdx.x*blockDim.x + threadIdx.x;
    if (idx >= out_size || idx >= 18560) return;
    const int FIN = LL & 1;
    if (idx < 6656){
        int i = idx/104, rem = idx%104, j = rem/13, tt = rem%13;
        out[idx] = d_outputs[FIN][(j*BB+i)*LL + tt];
    } else if (idx < 13312){
        int q = idx - 6656;
        int i = q/104, rem = q%104, j = rem/13, tt = rem%13;
        out[idx] = d_samples[FIN][(j*BB+i)*LL + tt];
    } else if (idx < 13376){
        out[idx] = d_entelem[idx-13312];
    } else if (idx < 13888){
        out[idx] = d_logRs[idx-13376];
    } else if (idx < 17984){
        out[idx] = d_logRss[idx-13888];
    } else if (idx < 18496){
        out[idx] = d_phik[idx-17984];
    } else {
        out[idx] = d_entplot[idx-18496];
    }
}

// ---------------- host driver ---------------------------------------------------------
extern "C" void kernel_launch(void* const* d_in, const int* in_sizes, int n_in,
                              void* d_out, int out_size){
    const float* x_feat  = (const float*)d_in[0];
    const float* W_in_op = (const float*)d_in[1];
    const float* b_in_op = (const float*)d_in[2];
    const float* W_ih    = (const float*)d_in[3];
    const float* W_hh    = (const float*)d_in[4];
    const float* b_ih    = (const float*)d_in[5];
    const float* b_hh    = (const float*)d_in[6];
    const float* W_fc1   = (const float*)d_in[7];
    const float* b_fc1   = (const float*)d_in[8];
    const float* W_out   = (const float*)d_in[9];
    const float* b_out   = (const float*)d_in[10];
    const float* gu      = (const float*)d_in[11];
    (void)in_sizes; (void)n_in;

    void* tmp;
    cudaGetSymbolAddress(&tmp, d_ht);    float* p_ht  = (float*)tmp;
    cudaGetSymbolAddress(&tmp, d_xW);    float* p_xW  = (float*)tmp;
    cudaGetSymbolAddress(&tmp, d_E);     float* p_E   = (float*)tmp;
    cudaGetSymbolAddress(&tmp, d_Gt);    float* p_Gt  = (float*)tmp;

    cudaFuncSetAttribute(gates_mma, cudaFuncAttributeMaxDynamicSharedMemorySize, GM_DSMEM);

    init_kernel<<<256,256>>>(W_in_op, b_in_op);
    reorder_whh<<<(G4*HH+255)/256,256>>>(W_hh);
    split_whh<<<(G4*HH+255)/256,256>>>();

    gemm_db<1><<<dim3(64,1),256>>>(x_feat,1024, W_ih,1152, p_xW,G4,
                                   BB,G4,1024, b_ih, b_hh);
    gemm_db<0><<<dim3(64,7),256>>>(p_E,128, W_ih+1024,1152, p_Gt,G4,
                                   V1,G4,128, nullptr, nullptr);
    permute_gates<<<((BB+V1)*G4+255)/256,256>>>();

    for (int t = 0; t < LL; t++){
        int cur = t & 1;
        if (t == 0){
            lstm0<<<RR,256>>>();
        } else {
            gates_mma<<<dim3(32,4),256,GM_DSMEM>>>(cur);
        }
        gemm_fc1_f2<<<dim3(8,4,SK),256>>>(p_ht + (size_t)cur*RR*HH, W_fc1);
        gemm_out_f2<<<dim3(4,4,SK),256>>>(W_out, b_fc1);
        select_kernel<<<BB,256>>>(gu, b_out, t, cur);
    }

    finalize_kernel<<<(18560+255)/256,256>>>((float*)d_out, out_size);
}

// round 8
// speedup vs baseline: 2.4391x; 1.1143x over previous
#include <cuda_runtime.h>
#include <cuda_bf16.h>
#include <math.h>
#include <stdint.h>

#define BB 64      // batch
#define KB 8       // beams
#define RR 512     // BB*KB
#define HH 1024    // hidden
#define VV 400     // vocab
#define V1 401
#define LL 13      // program_len
#define G4 4096    // 4*HH
#define NP 1000    // log_R quadrature points
#define SK 4       // split-K slices for fc1/out

typedef unsigned long long ull;

// ---------------- persistent scratch -----------------------------------------
__device__ float d_ht[2][RR*HH];
__device__ float d_ct[2][RR*HH];
__device__ float d_Gmx[2][RR];
__device__ float d_logp[2][RR];
__device__ int   d_prev[RR];
__device__ int   d_order[RR];
__device__ float d_samples[2][RR*LL];
__device__ float d_outputs[2][RR*LL];
__device__ float d_entplot[BB];
__device__ float d_entelem[BB];
__device__ float d_xW[BB*G4];
__device__ float d_xW2[BB*G4];
__device__ float d_E[V1*128];
__device__ float d_Gt[V1*G4];
__device__ float d_Gt2[V1*G4];
__device__ float d_Whh2[G4*HH];
__device__ float d_graw[RR*G4];       // ungathered gate pre-activations h@Whh2^T
__device__ float d_fc1p[SK][RR*HH];
__device__ float d_lpp[SK][RR*VV];
__device__ float d_lpn[RR*VV];
__device__ float d_phik[BB*KB];
__device__ float d_logRs[BB*KB];
__device__ float d_logRss[BB*KB*KB];

// ---------------- helpers ------------------------------------------------------
__device__ __forceinline__ float sigmoidf(float x){ return 1.f/(1.f+expf(-x)); }

__device__ __forceinline__ float log1mexp(float x){
    x = fminf(x, -1e-38f);
    if (x > -0.6931472f) return logf(-expm1f(x));
    return log1pf(-expf(x));
}

__device__ __forceinline__ ull pkdup(float x){
    ull r; unsigned u = __float_as_uint(x);
    asm("mov.b64 %0, {%1, %1};" : "=l"(r) : "r"(u));
    return r;
}
__device__ __forceinline__ float2 upk2(ull v){
    unsigned lo, hi;
    asm("mov.b64 {%0, %1}, %2;" : "=r"(lo), "=r"(hi) : "l"(v));
    return make_float2(__uint_as_float(lo), __uint_as_float(hi));
}
__device__ __forceinline__ void fma2(ull &c, ull a, ull b){
    asm("fma.rn.f32x2 %0, %1, %2, %0;" : "+l"(c) : "l"(a), "l"(b));
}

// ---------------- init ----------------------------------------------------------
__global__ void init_kernel(const float* __restrict__ W_in_op,
                            const float* __restrict__ b_in_op){
    int idx = blockIdx.x*blockDim.x + threadIdx.x;
    int stride = gridDim.x*blockDim.x;
    for (int i = idx; i < RR;    i += stride){ d_Gmx[0][i]=0.f; d_logp[0][i]=0.f; }
    for (int i = idx; i < RR*LL; i += stride){ d_samples[0][i]=0.f; d_outputs[0][i]=0.f; }
    for (int i = idx; i < BB;    i += stride){ d_entplot[i]=0.f; d_entelem[i]=0.f; }
    for (int i = idx; i < V1*128; i += stride){
        int s = i >> 7, m = i & 127;
        d_E[i] = fmaxf(W_in_op[m*V1 + s] + b_in_op[m], 0.f);
    }
}

__global__ void reorder_whh(const float* __restrict__ W){
    int idx = blockIdx.x*blockDim.x + threadIdx.x;
    if (idx >= G4*HH) return;
    int c = idx >> 10, k = idx & 1023;
    int h = c >> 2, g = c & 3;
    d_Whh2[idx] = W[(size_t)(g*HH + h)*HH + k];
}

__global__ void permute_gates(){
    int idx = blockIdx.x*blockDim.x + threadIdx.x;
    if (idx >= (BB+V1)*G4) return;
    int row = idx / G4, c = idx - row*G4;
    int g = c >> 10, h = c & 1023;
    int dstc = 4*h + g;
    if (row < BB) d_xW2[row*G4 + dstc] = d_xW[idx];
    else          d_Gt2[(row-BB)*G4 + dstc] = d_Gt[idx - BB*G4];
}

// ---------------- setup GEMM (64x64x16 double buffered, scalar) -------------------
template<int MODE>
__global__ void __launch_bounds__(256) gemm_db(
    const float* __restrict__ A, int lda,
    const float* __restrict__ B, int ldb,
    float* __restrict__ C, int ldc,
    int M, int N, int K,
    const float* __restrict__ bias1,
    const float* __restrict__ bias2)
{
    __shared__ float As[2][16][64+4];
    __shared__ float Bs[2][16][64+4];
    const int tid = threadIdx.x;
    const int row0 = blockIdx.y*64, col0 = blockIdx.x*64;
    const int arow = tid >> 2, ak = (tid & 3)*4;
    const int ty = tid >> 4, tx = tid & 15;

    const int ar = row0 + arow, br = col0 + arow;
    float4 a4 = make_float4(0,0,0,0), b4 = make_float4(0,0,0,0);
    if (ar < M) a4 = *(const float4*)(A + (size_t)ar*lda + ak);
    if (br < N) b4 = *(const float4*)(B + (size_t)br*ldb + ak);
    As[0][ak+0][arow]=a4.x; As[0][ak+1][arow]=a4.y; As[0][ak+2][arow]=a4.z; As[0][ak+3][arow]=a4.w;
    Bs[0][ak+0][arow]=b4.x; Bs[0][ak+1][arow]=b4.y; Bs[0][ak+2][arow]=b4.z; Bs[0][ak+3][arow]=b4.w;
    __syncthreads();

    float acc[4][4];
#pragma unroll
    for (int i=0;i<4;i++)
#pragma unroll
        for (int j=0;j<4;j++) acc[i][j]=0.f;

    const int NT = K/16;
    for (int it=0; it<NT; it++){
        int cur = it & 1;
        float4 a4n, b4n;
        if (it+1 < NT){
            int k0 = (it+1)*16;
            a4n = make_float4(0,0,0,0); b4n = make_float4(0,0,0,0);
            if (ar < M) a4n = *(const float4*)(A + (size_t)ar*lda + k0 + ak);
            if (br < N) b4n = *(const float4*)(B + (size_t)br*ldb + k0 + ak);
        }
#pragma unroll
        for (int kk=0; kk<16; kk++){
            float4 ra = *(const float4*)&As[cur][kk][ty*4];
            float4 rb = *(const float4*)&Bs[cur][kk][tx*4];
            float r[4]={ra.x,ra.y,ra.z,ra.w};
            float cb[4]={rb.x,rb.y,rb.z,rb.w};
#pragma unroll
            for (int i=0;i<4;i++)
#pragma unroll
                for (int j=0;j<4;j++) acc[i][j] = fmaf(r[i], cb[j], acc[i][j]);
        }
        if (it+1 < NT){
            int nb = cur^1;
            As[nb][ak+0][arow]=a4n.x; As[nb][ak+1][arow]=a4n.y; As[nb][ak+2][arow]=a4n.z; As[nb][ak+3][arow]=a4n.w;
            Bs[nb][ak+0][arow]=b4n.x; Bs[nb][ak+1][arow]=b4n.y; Bs[nb][ak+2][arow]=b4n.z; Bs[nb][ak+3][arow]=b4n.w;
        }
        __syncthreads();
    }
#pragma unroll
    for (int i=0;i<4;i++){
        int r = row0 + ty*4 + i;
        if (r >= M) continue;
#pragma unroll
        for (int j=0;j<4;j++){
            int c = col0 + tx*4 + j;
            if (c >= N) continue;
            float v = acc[i][j];
            if (MODE==1) v += bias1[c] + bias2[c];
            else if (MODE==3) v = fmaxf(v + bias1[c], 0.f);
            else if (MODE==4) v += bias1[c];
            C[(size_t)r*ldc + c] = v;
        }
    }
}

// ---------------- graw GEMM (512x4096x1024, f32x2, no gather, no epilogue) --------
__global__ void __launch_bounds__(256) gemm_graw(
    const float* __restrict__ A, const float* __restrict__ W)
{
    __shared__ float As[2][16][128+4];
    __shared__ float Bs[2][16][128+4];
    const int tid = threadIdx.x;
    const int row0 = blockIdx.y*128, col0 = blockIdx.x*128;
    const int arow = tid >> 1, ak = (tid & 1)*8;
    const int ty = tid >> 4, tx = tid & 15;

    const float* Arow = A + (size_t)(row0+arow)*HH + ak;
    const float* Brow = W + (size_t)(col0+arow)*HH + ak;

    float4 a0 = *(const float4*)Arow, a1 = *(const float4*)(Arow+4);
    float4 b0 = *(const float4*)Brow, b1 = *(const float4*)(Brow+4);
#pragma unroll
    for (int j=0;j<4;j++){
        As[0][ak+j][arow]=((const float*)&a0)[j]; As[0][ak+4+j][arow]=((const float*)&a1)[j];
        Bs[0][ak+j][arow]=((const float*)&b0)[j]; Bs[0][ak+4+j][arow]=((const float*)&b1)[j];
    }
    __syncthreads();

    ull acc[8][4];
#pragma unroll
    for (int i=0;i<8;i++)
#pragma unroll
        for (int p=0;p<4;p++) acc[i][p]=0ull;

    const int NT = HH/16;
    for (int it=0; it<NT; it++){
        int cur = it & 1;
        float4 a0n,a1n,b0n,b1n;
        if (it+1 < NT){
            int k0 = (it+1)*16;
            a0n=*(const float4*)(Arow+k0); a1n=*(const float4*)(Arow+k0+4);
            b0n=*(const float4*)(Brow+k0); b1n=*(const float4*)(Brow+k0+4);
        }
#pragma unroll
        for (int kk=0; kk<16; kk++){
            const float* Ar = &As[cur][kk][ty*8];
            const float* Br = &Bs[cur][kk][tx*8];
            float4 af0 = *(const float4*)Ar, af1 = *(const float4*)(Ar+4);
            ulonglong2 bq0 = *(const ulonglong2*)Br;
            ulonglong2 bq1 = *(const ulonglong2*)(Br+4);
            float av[8] = {af0.x,af0.y,af0.z,af0.w,af1.x,af1.y,af1.z,af1.w};
#pragma unroll
            for (int i=0;i<8;i++){
                ull ap = pkdup(av[i]);
                fma2(acc[i][0], ap, bq0.x);
                fma2(acc[i][1], ap, bq0.y);
                fma2(acc[i][2], ap, bq1.x);
                fma2(acc[i][3], ap, bq1.y);
            }
        }
        if (it+1 < NT){
            int nb = cur^1;
#pragma unroll
            for (int j=0;j<4;j++){
                As[nb][ak+j][arow]=((const float*)&a0n)[j]; As[nb][ak+4+j][arow]=((const float*)&a1n)[j];
                Bs[nb][ak+j][arow]=((const float*)&b0n)[j]; Bs[nb][ak+4+j][arow]=((const float*)&b1n)[j];
            }
        }
        __syncthreads();
    }

#pragma unroll
    for (int i=0;i<8;i++){
        int r = row0 + ty*8 + i;
        float2 q0=upk2(acc[i][0]), q1=upk2(acc[i][1]), q2=upk2(acc[i][2]), q3=upk2(acc[i][3]);
        *(float4*)&d_graw[(size_t)r*G4 + col0 + tx*8]     = make_float4(q0.x,q0.y,q1.x,q1.y);
        *(float4*)&d_graw[(size_t)r*G4 + col0 + tx*8 + 4] = make_float4(q2.x,q2.y,q3.x,q3.y);
    }
}

// ---------------- LSTM elementwise: gather G_raw rows + nonlinearity --------------
__global__ void __launch_bounds__(256) lstm_elem(int t, int cur){
    const int r = blockIdx.x, tid = threadIdx.x;
    const int prv = cur^1;
    const int b = r & 63;
    int o, pv;
    if (t == 0){ o = r; pv = VV; } else { o = d_order[r]; pv = d_prev[r]; }
    const float4* gr = (const float4*)(d_graw + (size_t)o*G4);
    const float4* xw = (const float4*)(d_xW2 + (size_t)b*G4);
    const float4* gt = (const float4*)(d_Gt2 + (size_t)pv*G4);
    const float* cpf = d_ct[prv] + (size_t)o*HH;
    float* hf = d_ht[cur] + (size_t)r*HH;
    float* cf = d_ct[cur] + (size_t)r*HH;
#pragma unroll
    for (int q=0;q<4;q++){
        int u = tid + q*256;
        float4 g = (t==0) ? make_float4(0,0,0,0) : gr[u];
        float4 x = xw[u];
        float4 G = gt[u];
        float ig = g.x + x.x + G.x;
        float fg = g.y + x.y + G.y;
        float gg = g.z + x.z + G.z;
        float og = g.w + x.w + G.w;
        float cold = (t==0) ? 0.f : cpf[u];
        float cn = sigmoidf(fg)*cold + sigmoidf(ig)*tanhf(gg);
        cf[u] = cn;
        hf[u] = sigmoidf(og)*tanhf(cn);
    }
}

// ---------------- fc1 split-K GEMM (128x128, f32x2): partials, no bias -----------
__global__ void __launch_bounds__(256) gemm_fc1_f2(
    const float* __restrict__ A, const float* __restrict__ W)
{
    __shared__ float As[2][16][128+4];
    __shared__ float Bs[2][16][128+4];
    const int tid = threadIdx.x;
    const int row0 = blockIdx.y*128, col0 = blockIdx.x*128;
    const int kb = blockIdx.z * (HH/SK);
    const int arow = tid >> 1, ak = (tid & 1)*8;
    const int ty = tid >> 4, tx = tid & 15;

    const float* Arow = A + (size_t)(row0+arow)*HH + kb + ak;
    const float* Brow = W + (size_t)(col0+arow)*HH + kb + ak;

    float4 a0 = *(const float4*)Arow, a1 = *(const float4*)(Arow+4);
    float4 b0 = *(const float4*)Brow, b1 = *(const float4*)(Brow+4);
#pragma unroll
    for (int j=0;j<4;j++){
        As[0][ak+j][arow]=((const float*)&a0)[j]; As[0][ak+4+j][arow]=((const float*)&a1)[j];
        Bs[0][ak+j][arow]=((const float*)&b0)[j]; Bs[0][ak+4+j][arow]=((const float*)&b1)[j];
    }
    __syncthreads();

    ull acc[8][4];
#pragma unroll
    for (int i=0;i<8;i++)
#pragma unroll
        for (int p=0;p<4;p++) acc[i][p]=0ull;

    const int NT = (HH/SK)/16;
    for (int it=0; it<NT; it++){
        int cur = it & 1;
        float4 a0n,a1n,b0n,b1n;
        if (it+1 < NT){
            int k0 = (it+1)*16;
            a0n=*(const float4*)(Arow+k0); a1n=*(const float4*)(Arow+k0+4);
            b0n=*(const float4*)(Brow+k0); b1n=*(const float4*)(Brow+k0+4);
        }
#pragma unroll
        for (int kk=0; kk<16; kk++){
            const float* Ar = &As[cur][kk][ty*8];
            const float* Br = &Bs[cur][kk][tx*8];
            float4 af0 = *(const float4*)Ar, af1 = *(const float4*)(Ar+4);
            ulonglong2 bq0 = *(const ulonglong2*)Br;
            ulonglong2 bq1 = *(const ulonglong2*)(Br+4);
            float av[8] = {af0.x,af0.y,af0.z,af0.w,af1.x,af1.y,af1.z,af1.w};
#pragma unroll
            for (int i=0;i<8;i++){
                ull ap = pkdup(av[i]);
                fma2(acc[i][0], ap, bq0.x);
                fma2(acc[i][1], ap, bq0.y);
                fma2(acc[i][2], ap, bq1.x);
                fma2(acc[i][3], ap, bq1.y);
            }
        }
        if (it+1 < NT){
            int nb = cur^1;
#pragma unroll
            for (int j=0;j<4;j++){
                As[nb][ak+j][arow]=((const float*)&a0n)[j]; As[nb][ak+4+j][arow]=((const float*)&a1n)[j];
                Bs[nb][ak+j][arow]=((const float*)&b0n)[j]; Bs[nb][ak+4+j][arow]=((const float*)&b1n)[j];
            }
        }
        __syncthreads();
    }

    float* Cp = d_fc1p[blockIdx.z];
#pragma unroll
    for (int i=0;i<8;i++){
        int r = row0 + ty*8 + i;
        float2 q0=upk2(acc[i][0]), q1=upk2(acc[i][1]), q2=upk2(acc[i][2]), q3=upk2(acc[i][3]);
        *(float4*)&Cp[(size_t)r*HH + col0 + tx*8]     = make_float4(q0.x,q0.y,q1.x,q1.y);
        *(float4*)&Cp[(size_t)r*HH + col0 + tx*8 + 4] = make_float4(q2.x,q2.y,q3.x,q3.y);
    }
}

// ---------------- out split-K GEMM: A = relu(sum fc1 partials + b_fc1) -----------
__global__ void __launch_bounds__(256) gemm_out_f2(
    const float* __restrict__ W, const float* __restrict__ b_fc1)
{
    __shared__ float As[2][16][128+4];
    __shared__ float Bs[2][16][128+4];
    const int tid = threadIdx.x;
    const int row0 = blockIdx.y*128, col0 = blockIdx.x*128;
    const int kb = blockIdx.z * (HH/SK);
    const int arow = tid >> 1, ak = (tid & 1)*8;
    const int ty = tid >> 4, tx = tid & 15;
    const int br = col0 + arow;

    const size_t aoff = (size_t)(row0+arow)*HH + kb + ak;
    const float* Brow = (br < VV) ? (W + (size_t)br*HH + kb + ak) : nullptr;

    float4 a0, a1, b0, b1;
    {
        float4 p0=*(const float4*)&d_fc1p[0][aoff], p1=*(const float4*)&d_fc1p[1][aoff];
        float4 p2=*(const float4*)&d_fc1p[2][aoff], p3=*(const float4*)&d_fc1p[3][aoff];
        float4 bf=*(const float4*)&b_fc1[kb+ak];
        a0.x=fmaxf(p0.x+p1.x+p2.x+p3.x+bf.x,0.f); a0.y=fmaxf(p0.y+p1.y+p2.y+p3.y+bf.y,0.f);
        a0.z=fmaxf(p0.z+p1.z+p2.z+p3.z+bf.z,0.f); a0.w=fmaxf(p0.w+p1.w+p2.w+p3.w+bf.w,0.f);
        p0=*(const float4*)&d_fc1p[0][aoff+4]; p1=*(const float4*)&d_fc1p[1][aoff+4];
        p2=*(const float4*)&d_fc1p[2][aoff+4]; p3=*(const float4*)&d_fc1p[3][aoff+4];
        bf=*(const float4*)&b_fc1[kb+ak+4];
        a1.x=fmaxf(p0.x+p1.x+p2.x+p3.x+bf.x,0.f); a1.y=fmaxf(p0.y+p1.y+p2.y+p3.y+bf.y,0.f);
        a1.z=fmaxf(p0.z+p1.z+p2.z+p3.z+bf.z,0.f); a1.w=fmaxf(p0.w+p1.w+p2.w+p3.w+bf.w,0.f);
        b0 = Brow ? *(const float4*)Brow     : make_float4(0,0,0,0);
        b1 = Brow ? *(const float4*)(Brow+4) : make_float4(0,0,0,0);
    }
#pragma unroll
    for (int j=0;j<4;j++){
        As[0][ak+j][arow]=((const float*)&a0)[j]; As[0][ak+4+j][arow]=((const float*)&a1)[j];
        Bs[0][ak+j][arow]=((const float*)&b0)[j]; Bs[0][ak+4+j][arow]=((const float*)&b1)[j];
    }
    __syncthreads();

    ull acc[8][4];
#pragma unroll
    for (int i=0;i<8;i++)
#pragma unroll
        for (int p=0;p<4;p++) acc[i][p]=0ull;

    const int NT = (HH/SK)/16;
    for (int it=0; it<NT; it++){
        int cur = it & 1;
        float4 a0n,a1n,b0n,b1n;
        if (it+1 < NT){
            int k0 = (it+1)*16;
            float4 p0=*(const float4*)&d_fc1p[0][aoff+k0], p1=*(const float4*)&d_fc1p[1][aoff+k0];
            float4 p2=*(const float4*)&d_fc1p[2][aoff+k0], p3=*(const float4*)&d_fc1p[3][aoff+k0];
            float4 bf=*(const float4*)&b_fc1[kb+ak+k0];
            a0n.x=fmaxf(p0.x+p1.x+p2.x+p3.x+bf.x,0.f); a0n.y=fmaxf(p0.y+p1.y+p2.y+p3.y+bf.y,0.f);
            a0n.z=fmaxf(p0.z+p1.z+p2.z+p3.z+bf.z,0.f); a0n.w=fmaxf(p0.w+p1.w+p2.w+p3.w+bf.w,0.f);
            p0=*(const float4*)&d_fc1p[0][aoff+k0+4]; p1=*(const float4*)&d_fc1p[1][aoff+k0+4];
            p2=*(const float4*)&d_fc1p[2][aoff+k0+4]; p3=*(const float4*)&d_fc1p[3][aoff+k0+4];
            bf=*(const float4*)&b_fc1[kb+ak+k0+4];
            a1n.x=fmaxf(p0.x+p1.x+p2.x+p3.x+bf.x,0.f); a1n.y=fmaxf(p0.y+p1.y+p2.y+p3.y+bf.y,0.f);
            a1n.z=fmaxf(p0.z+p1.z+p2.z+p3.z+bf.z,0.f); a1n.w=fmaxf(p0.w+p1.w+p2.w+p3.w+bf.w,0.f);
            b0n = Brow ? *(const float4*)(Brow+k0)   : make_float4(0,0,0,0);
            b1n = Brow ? *(const float4*)(Brow+k0+4) : make_float4(0,0,0,0);
        }
#pragma unroll
        for (int kk=0; kk<16; kk++){
            const float* Ar = &As[cur][kk][ty*8];
            const float* Br = &Bs[cur][kk][tx*8];
            float4 af0 = *(const float4*)Ar, af1 = *(const float4*)(Ar+4);
            ulonglong2 bq0 = *(const ulonglong2*)Br;
            ulonglong2 bq1 = *(const ulonglong2*)(Br+4);
            float av[8] = {af0.x,af0.y,af0.z,af0.w,af1.x,af1.y,af1.z,af1.w};
#pragma unroll
            for (int i=0;i<8;i++){
                ull ap = pkdup(av[i]);
                fma2(acc[i][0], ap, bq0.x);
                fma2(acc[i][1], ap, bq0.y);
                fma2(acc[i][2], ap, bq1.x);
                fma2(acc[i][3], ap, bq1.y);
            }
        }
        if (it+1 < NT){
            int nb = cur^1;
#pragma unroll
            for (int j=0;j<4;j++){
                As[nb][ak+j][arow]=((const float*)&a0n)[j]; As[nb][ak+4+j][arow]=((const float*)&a1n)[j];
                Bs[nb][ak+j][arow]=((const float*)&b0n)[j]; Bs[nb][ak+4+j][arow]=((const float*)&b1n)[j];
            }
        }
        __syncthreads();
    }

    float* Cp = d_lpp[blockIdx.z];
    const int c0 = col0 + tx*8;
    if (c0 + 8 <= VV){
#pragma unroll
        for (int i=0;i<8;i++){
            int r = row0 + ty*8 + i;
            float2 q0=upk2(acc[i][0]), q1=upk2(acc[i][1]), q2=upk2(acc[i][2]), q3=upk2(acc[i][3]);
            *(float4*)&Cp[(size_t)r*VV + c0]     = make_float4(q0.x,q0.y,q1.x,q1.y);
            *(float4*)&Cp[(size_t)r*VV + c0 + 4] = make_float4(q2.x,q2.y,q3.x,q3.y);
        }
    }
}

// ---------------- warp LSE ---------------------------------------------------------
__device__ __forceinline__ float warpLSE(const float* __restrict__ base,
                                         const float* __restrict__ t1,
                                         const float* __restrict__ t2){
    int lane = threadIdx.x & 31;
    float m = -INFINITY, s = 0.f;
    for (int n = lane; n < NP; n += 32){
        float x = base[n];
        if (t1) x -= t1[n];
        if (t2) x -= t2[n];
        if (x > m){ s = s*expf(m-x) + 1.f; m = x; } else s += expf(x-m);
    }
#pragma unroll
    for (int off=16; off; off>>=1){
        float m2 = __shfl_xor_sync(0xffffffffu, m, off);
        float s2 = __shfl_xor_sync(0xffffffffu, s, off);
        float mm = fmaxf(m, m2);
        s = s*expf(m-mm) + s2*expf(m2-mm);
        m = mm;
    }
    return m + logf(s);
}

// ---------------- fused select (per batch element) ---------------------------------
__global__ void __launch_bounds__(256) select_kernel(const float* __restrict__ gu,
                                                     const float* __restrict__ b_out,
                                                     int t, int cur){
    __shared__ float pool[KB*NP + NP];
    __shared__ float rv[256];
    __shared__ int   ri[256];
    __shared__ float entS[KB], phiS[KB], gvalS[KB], logIs_s[KB+1];
    __shared__ int   ordS[KB], snewS[KB];

    const int i = blockIdx.x, tid = threadIdx.x;
    const int lane = tid & 31, w = tid >> 5;
    float (*gm)[VV] = (float(*)[VV])pool;

    const int r = w*BB + i;
    const size_t rb = (size_t)r*VV;

    float lv[13];
#pragma unroll
    for (int ii=0; ii<13; ii++){
        int v = lane + ii*32;
        float val = -INFINITY;
        if (v < VV)
            val = d_lpp[0][rb+v] + d_lpp[1][rb+v] + d_lpp[2][rb+v] + d_lpp[3][rb+v] + b_out[v];
        lv[ii] = val;
    }
    float m = -INFINITY;
#pragma unroll
    for (int ii=0; ii<13; ii++) m = fmaxf(m, lv[ii]);
#pragma unroll
    for (int off=16; off; off>>=1) m = fmaxf(m, __shfl_xor_sync(0xffffffffu, m, off));
    float s = 0.f;
#pragma unroll
    for (int ii=0; ii<13; ii++){ int v = lane+ii*32; if (v < VV) s += expf(lv[ii]-m); }
#pragma unroll
    for (int off=16; off; off>>=1) s += __shfl_xor_sync(0xffffffffu, s, off);
    float lse = m + logf(s);

    float lpr = d_logp[cur][r];
    float Gr  = d_Gmx[cur][r];
    const float* u = gu + ((size_t)t*RR + r)*VV;
    float ent = 0.f, zm = -INFINITY;
#pragma unroll
    for (int ii=0; ii<13; ii++){
        int v = lane + ii*32;
        if (v >= VV) continue;
        float l = lv[ii]-lse;
        d_lpn[rb+v] = l;
        ent += l*expf(l);
        float gmb = -logf(-logf(u[v]*(1.f-2e-7f)+1e-7f));
        float gph = l + lpr + gmb;
        gm[w][v] = gph;
        zm = fmaxf(zm, gph);
    }
#pragma unroll
    for (int off=16; off; off>>=1){
        ent += __shfl_xor_sync(0xffffffffu, ent, off);
        zm = fmaxf(zm, __shfl_xor_sync(0xffffffffu, zm, off));
    }
    if (lane==0) entS[w] = ent;
    for (int v=lane; v<VV; v+=32){
        float gph = gm[w][v];
        float vv = Gr - gph + log1mexp(gph - zm);
        float val = Gr - fmaxf(vv,0.f) - log1pf(expf(-fabsf(vv)));
        gm[w][v] = (t==0 && w>0) ? -INFINITY : val;
    }
    __syncthreads();

    for (int round=0; round<KB; round++){
        float bv = -INFINITY; int bi = 0x7fffffff;
        for (int idx=tid; idx<KB*VV; idx+=256){
            float v = pool[idx];
            if (v > bv || (v == bv && idx < bi)){ bv=v; bi=idx; }
        }
        rv[tid]=bv; ri[tid]=bi; __syncthreads();
        for (int off=128; off; off>>=1){
            if (tid < off){
                if (rv[tid+off] > rv[tid] || (rv[tid+off]==rv[tid] && ri[tid+off]<ri[tid])){
                    rv[tid]=rv[tid+off]; ri[tid]=ri[tid+off];
                }
            }
            __syncthreads();
        }
        if (tid==0){
            int widx = ri[0]; int j = widx/VV, v = widx - j*VV;
            gvalS[round]=rv[0]; ordS[round]=j; snewS[round]=v;
            pool[widx] = -INFINITY;
        }
        __syncthreads();
    }

    const int nxt = cur^1;
    for (int idx=tid; idx<KB*LL; idx+=256){
        int j = idx/LL, tt = idx - j*LL;
        if (tt == t) continue;
        int rn = j*BB+i, o = ordS[j]*BB+i;
        d_samples[nxt][rn*LL+tt] = d_samples[cur][o*LL+tt];
        d_outputs[nxt][rn*LL+tt] = d_outputs[cur][o*LL+tt];
    }
    if (tid < KB){
        int j = tid, rn = j*BB+i, o = ordS[j]*BB+i, sv = snewS[j];
        float lpv = d_lpn[(size_t)o*VV + sv];
        float nl  = d_logp[cur][o] + lpv;
        d_samples[nxt][rn*LL+t] = (float)sv;
        d_outputs[nxt][rn*LL+t] = lpv;
        d_logp[nxt][rn] = nl;
        d_Gmx[nxt][rn]  = gvalS[j];
        d_prev[rn]  = sv;
        d_order[rn] = o;
        d_phik[i*KB+j] = nl;
        phiS[j] = nl;
    }
    __syncthreads();

    float (*Ts)[NP] = (float(*)[NP])pool;
    float* base = pool + KB*NP;
    float p[KB], pS = 0.f;
#pragma unroll
    for (int j=0;j<KB;j++){ p[j] = expf(phiS[j]); pS += p[j]; }
    for (int n=tid; n<NP; n+=256){
        float lu = logf(((float)n + 0.5f)/(float)NP);
        float bs = -pS*lu;
#pragma unroll
        for (int j=0;j<KB;j++){
            float x = log1mexp(p[j]*lu);
            Ts[j][n] = x;
            bs += x;
        }
        base[n] = bs;
    }
    __syncthreads();

    const float logN = logf((float)NP);
    float resA = warpLSE(base, Ts[w], nullptr) - logN;
    if (lane==0) logIs_s[w] = resA;
    if (w==0){
        float li = warpLSE(base, nullptr, nullptr) - logN;
        if (lane==0) logIs_s[KB] = li;
    }
    __syncthreads();
    float logI = logIs_s[KB];
    if (tid < KB) d_logRs[i*KB+tid] = logIs_s[tid] - logI;

    for (int pp = w; pp < 28; pp += 8){
        int a = 0, rem = pp;
        while (rem >= 7 - a){ rem -= (7 - a); a++; }
        int b = a + 1 + rem;
        float lss = warpLSE(base, Ts[a], Ts[b]) - logN;
        if (lane==0){
            d_logRss[i*64 + a*8 + b] = lss - logIs_s[a];
            d_logRss[i*64 + b*8 + a] = lss - logIs_s[b];
        }
    }
    if (tid < KB) d_logRss[i*64 + tid*9] = 0.f;
    if (tid == 0){
        float Wsum = 0.f, ws = 0.f;
#pragma unroll
        for (int j=0;j<KB;j++){
            float wq = expf(phiS[j] + logIs_s[j] - logI);
            Wsum += wq;
            ws   += wq * entS[ordS[j]];
        }
        d_entplot[i] += ws;
        d_entelem[i] += ws / Wsum;
    }
}

// ---------------- output assembly ---------------------------------------------------
__global__ void finalize_kernel(float* __restrict__ out, int out_size){
    int idx = blockIdx.x*blockDim.x + threadIdx.x;
    if (idx >= out_size || idx >= 18560) return;
    const int FIN = LL & 1;
    if (idx < 6656){
        int i = idx/104, rem = idx%104, j = rem/13, tt = rem%13;
        out[idx] = d_outputs[FIN][(j*BB+i)*LL + tt];
    } else if (idx < 13312){
        int q = idx - 6656;
        int i = q/104, rem = q%104, j = rem/13, tt = rem%13;
        out[idx] = d_samples[FIN][(j*BB+i)*LL + tt];
    } else if (idx < 13376){
        out[idx] = d_entelem[idx-13312];
    } else if (idx < 13888){
        out[idx] = d_logRs[idx-13376];
    } else if (idx < 17984){
        out[idx] = d_logRss[idx-13888];
    } else if (idx < 18496){
        out[idx] = d_phik[idx-17984];
    } else {
        out[idx] = d_entplot[idx-18496];
    }
}

// ---------------- host driver ---------------------------------------------------------
extern "C" void kernel_launch(void* const* d_in, const int* in_sizes, int n_in,
                              void* d_out, int out_size){
    const float* x_feat  = (const float*)d_in[0];
    const float* W_in_op = (const float*)d_in[1];
    const float* b_in_op = (const float*)d_in[2];
    const float* W_ih    = (const float*)d_in[3];
    const float* W_hh    = (const float*)d_in[4];
    const float* b_ih    = (const float*)d_in[5];
    const float* b_hh    = (const float*)d_in[6];
    const float* W_fc1   = (const float*)d_in[7];
    const float* b_fc1   = (const float*)d_in[8];
    const float* W_out   = (const float*)d_in[9];
    const float* b_out   = (const float*)d_in[10];
    const float* gu      = (const float*)d_in[11];
    (void)in_sizes; (void)n_in;

    void* tmp;
    cudaGetSymbolAddress(&tmp, d_ht);    float* p_ht  = (float*)tmp;
    cudaGetSymbolAddress(&tmp, d_xW);    float* p_xW  = (float*)tmp;
    cudaGetSymbolAddress(&tmp, d_E);     float* p_E   = (float*)tmp;
    cudaGetSymbolAddress(&tmp, d_Gt);    float* p_Gt  = (float*)tmp;
    cudaGetSymbolAddress(&tmp, d_Whh2);  float* p_Wh2 = (float*)tmp;

    // one-time stream/event creation (created on the non-capturing correctness call;
    // reused, never destroyed — no device-memory allocation involved)
    static cudaStream_t s2 = nullptr;
    static cudaEvent_t evA = nullptr, evB = nullptr;
    if (s2 == nullptr){
        cudaStreamCreateWithFlags(&s2, cudaStreamNonBlocking);
        cudaEventCreateWithFlags(&evA, cudaEventDisableTiming);
        cudaEventCreateWithFlags(&evB, cudaEventDisableTiming);
    }

    // fork stream2 off the (captured) default stream, run W_hh reorder there;
    // all gemm_graw launches also go to s2, so ordering vs reorder is automatic.
    cudaEventRecord(evA, 0);
    cudaStreamWaitEvent(s2, evA, 0);
    reorder_whh<<<(G4*HH+255)/256, 256, 0, s2>>>(W_hh);

    init_kernel<<<256,256>>>(W_in_op, b_in_op);
    gemm_db<1><<<dim3(64,1),256>>>(x_feat,1024, W_ih,1152, p_xW,G4,
                                   BB,G4,1024, b_ih, b_hh);
    gemm_db<0><<<dim3(64,7),256>>>(p_E,128, W_ih+1024,1152, p_Gt,G4,
                                   V1,G4,128, nullptr, nullptr);
    permute_gates<<<((BB+V1)*G4+255)/256,256>>>();

    for (int t = 0; t < LL; t++){
        int cur = t & 1;
        float* h_cur = p_ht + (size_t)cur*RR*HH;

        // gather + LSTM nonlinearity (cheap; needs graw(t-1) joined + select(t-1))
        lstm_elem<<<RR,256>>>(t, cur);

        if (t < LL-1){
            // fork: G_raw(t) = h(t) @ Whh2^T on stream2, concurrent with fc1/out/select
            cudaEventRecord(evA, 0);
            cudaStreamWaitEvent(s2, evA, 0);
            gemm_graw<<<dim3(32,4),256,0,s2>>>(h_cur, p_Wh2);
            cudaEventRecord(evB, s2);
        }

        gemm_fc1_f2<<<dim3(8,4,SK),256>>>(h_cur, W_fc1);
        gemm_out_f2<<<dim3(4,4,SK),256>>>(W_out, b_fc1);
        select_kernel<<<BB,256>>>(gu, b_out, t, cur);

        if (t < LL-1){
            // join: next lstm_elem consumes G_raw(t)
            cudaStreamWaitEvent(0, evB, 0);
        }
    }

    finalize_kernel<<<(18560+255)/256,256>>>((float*)d_out, out_size);
}

// round 9
// speedup vs baseline: 2.9533x; 1.2108x over previous
#include <cuda_runtime.h>
#include <cuda_bf16.h>
#include <math.h>
#include <stdint.h>

#define BB 64      // batch
#define KB 8       // beams
#define RR 512     // BB*KB
#define HH 1024    // hidden
#define VV 400     // vocab
#define V1 401
#define LL 13      // program_len
#define G4 4096    // 4*HH
#define NP 1000    // log_R quadrature points
#define SK 4       // split-K slices for fc1/out

typedef unsigned long long ull;

// ---------------- persistent scratch -----------------------------------------
__device__ float d_ht[2][RR*HH];
__device__ float d_ct[2][RR*HH];
__device__ float d_Gmx[2][RR];
__device__ float d_logp[2][RR];
__device__ int   d_prev[RR];
__device__ int   d_order[RR];
__device__ float d_samples[2][RR*LL];
__device__ float d_outputs[2][RR*LL];
__device__ float d_entplot[BB];
__device__ float d_entelem[BB];
__device__ float d_xW[BB*G4];
__device__ float d_xW2[BB*G4];
__device__ float d_E[V1*128];
__device__ float d_Gt[V1*G4];
__device__ float d_Gt2[V1*G4];
__device__ float d_Whh2[G4*HH];
__device__ __nv_bfloat16 d_w2b[2][G4*HH];   // W_hh2 bf16 2-way split
__device__ __nv_bfloat16 d_h2b[2][RR*HH];   // h bf16 2-way split (current step)
__device__ float d_graw[RR*G4];             // ungathered gate pre-activations
__device__ float d_fc1p[SK][RR*HH];
__device__ float d_lpp[SK][RR*VV];
__device__ float d_lpn[RR*VV];
__device__ float d_phik[BB*KB];
__device__ float d_logRs[BB*KB];
__device__ float d_logRss[BB*KB*KB];

// ---------------- helpers ------------------------------------------------------
__device__ __forceinline__ float sigmoidf(float x){ return 1.f/(1.f+expf(-x)); }

__device__ __forceinline__ float log1mexp(float x){
    x = fminf(x, -1e-38f);
    if (x > -0.6931472f) return logf(-expm1f(x));
    return log1pf(-expf(x));
}

__device__ __forceinline__ ull pkdup(float x){
    ull r; unsigned u = __float_as_uint(x);
    asm("mov.b64 %0, {%1, %1};" : "=l"(r) : "r"(u));
    return r;
}
__device__ __forceinline__ float2 upk2(ull v){
    unsigned lo, hi;
    asm("mov.b64 {%0, %1}, %2;" : "=r"(lo), "=r"(hi) : "l"(v));
    return make_float2(__uint_as_float(lo), __uint_as_float(hi));
}
__device__ __forceinline__ void fma2(ull &c, ull a, ull b){
    asm("fma.rn.f32x2 %0, %1, %2, %0;" : "+l"(c) : "l"(a), "l"(b));
}
__device__ __forceinline__ uint32_t smem_u32(const void* p){
    uint32_t a;
    asm("{ .reg .u64 t; cvta.to.shared.u64 t, %1; cvt.u32.u64 %0, t; }" : "=r"(a) : "l"(p));
    return a;
}
__device__ __forceinline__ void ldsm_x4(unsigned* r, uint32_t addr){
    asm volatile("ldmatrix.sync.aligned.m8n8.x4.shared.b16 {%0,%1,%2,%3}, [%4];"
        : "=r"(r[0]), "=r"(r[1]), "=r"(r[2]), "=r"(r[3]) : "r"(addr));
}
__device__ __forceinline__ void ldsm_x2(unsigned* r, uint32_t addr){
    asm volatile("ldmatrix.sync.aligned.m8n8.x2.shared.b16 {%0,%1}, [%2];"
        : "=r"(r[0]), "=r"(r[1]) : "r"(addr));
}
__device__ __forceinline__ void mma_bf16(float* c, const unsigned* a, const unsigned* b){
    asm volatile("mma.sync.aligned.m16n8k16.row.col.f32.bf16.bf16.f32 "
        "{%0,%1,%2,%3}, {%4,%5,%6,%7}, {%8,%9}, {%0,%1,%2,%3};"
        : "+f"(c[0]), "+f"(c[1]), "+f"(c[2]), "+f"(c[3])
        : "r"(a[0]), "r"(a[1]), "r"(a[2]), "r"(a[3]), "r"(b[0]), "r"(b[1]));
}

// ---------------- init ----------------------------------------------------------
__global__ void init_kernel(const float* __restrict__ W_in_op,
                            const float* __restrict__ b_in_op){
    int idx = blockIdx.x*blockDim.x + threadIdx.x;
    int stride = gridDim.x*blockDim.x;
    for (int i = idx; i < RR;    i += stride){ d_Gmx[0][i]=0.f; d_logp[0][i]=0.f; }
    for (int i = idx; i < RR*LL; i += stride){ d_samples[0][i]=0.f; d_outputs[0][i]=0.f; }
    for (int i = idx; i < BB;    i += stride){ d_entplot[i]=0.f; d_entelem[i]=0.f; }
    for (int i = idx; i < V1*128; i += stride){
        int s = i >> 7, m = i & 127;
        d_E[i] = fmaxf(W_in_op[m*V1 + s] + b_in_op[m], 0.f);
    }
}

__global__ void reorder_whh(const float* __restrict__ W){
    int idx = blockIdx.x*blockDim.x + threadIdx.x;
    if (idx >= G4*HH) return;
    int c = idx >> 10, k = idx & 1023;
    int h = c >> 2, g = c & 3;
    float w = W[(size_t)(g*HH + h)*HH + k];
    d_Whh2[idx] = w;
    __nv_bfloat16 b0 = __float2bfloat16(w);
    d_w2b[0][idx] = b0;
    d_w2b[1][idx] = __float2bfloat16(w - __bfloat162float(b0));
}

__global__ void permute_gates(){
    int idx = blockIdx.x*blockDim.x + threadIdx.x;
    if (idx >= (BB+V1)*G4) return;
    int row = idx / G4, c = idx - row*G4;
    int g = c >> 10, h = c & 1023;
    int dstc = 4*h + g;
    if (row < BB) d_xW2[row*G4 + dstc] = d_xW[idx];
    else          d_Gt2[(row-BB)*G4 + dstc] = d_Gt[idx - BB*G4];
}

// ---------------- setup GEMM (64x64x16 double buffered, scalar) -------------------
template<int MODE>
__global__ void __launch_bounds__(256) gemm_db(
    const float* __restrict__ A, int lda,
    const float* __restrict__ B, int ldb,
    float* __restrict__ C, int ldc,
    int M, int N, int K,
    const float* __restrict__ bias1,
    const float* __restrict__ bias2)
{
    __shared__ float As[2][16][64+4];
    __shared__ float Bs[2][16][64+4];
    const int tid = threadIdx.x;
    const int row0 = blockIdx.y*64, col0 = blockIdx.x*64;
    const int arow = tid >> 2, ak = (tid & 3)*4;
    const int ty = tid >> 4, tx = tid & 15;

    const int ar = row0 + arow, br = col0 + arow;
    float4 a4 = make_float4(0,0,0,0), b4 = make_float4(0,0,0,0);
    if (ar < M) a4 = *(const float4*)(A + (size_t)ar*lda + ak);
    if (br < N) b4 = *(const float4*)(B + (size_t)br*ldb + ak);
    As[0][ak+0][arow]=a4.x; As[0][ak+1][arow]=a4.y; As[0][ak+2][arow]=a4.z; As[0][ak+3][arow]=a4.w;
    Bs[0][ak+0][arow]=b4.x; Bs[0][ak+1][arow]=b4.y; Bs[0][ak+2][arow]=b4.z; Bs[0][ak+3][arow]=b4.w;
    __syncthreads();

    float acc[4][4];
#pragma unroll
    for (int i=0;i<4;i++)
#pragma unroll
        for (int j=0;j<4;j++) acc[i][j]=0.f;

    const int NT = K/16;
    for (int it=0; it<NT; it++){
        int cur = it & 1;
        float4 a4n, b4n;
        if (it+1 < NT){
            int k0 = (it+1)*16;
            a4n = make_float4(0,0,0,0); b4n = make_float4(0,0,0,0);
            if (ar < M) a4n = *(const float4*)(A + (size_t)ar*lda + k0 + ak);
            if (br < N) b4n = *(const float4*)(B + (size_t)br*ldb + k0 + ak);
        }
#pragma unroll
        for (int kk=0; kk<16; kk++){
            float4 ra = *(const float4*)&As[cur][kk][ty*4];
            float4 rb = *(const float4*)&Bs[cur][kk][tx*4];
            float r[4]={ra.x,ra.y,ra.z,ra.w};
            float cb[4]={rb.x,rb.y,rb.z,rb.w};
#pragma unroll
            for (int i=0;i<4;i++)
#pragma unroll
                for (int j=0;j<4;j++) acc[i][j] = fmaf(r[i], cb[j], acc[i][j]);
        }
        if (it+1 < NT){
            int nb = cur^1;
            As[nb][ak+0][arow]=a4n.x; As[nb][ak+1][arow]=a4n.y; As[nb][ak+2][arow]=a4n.z; As[nb][ak+3][arow]=a4n.w;
            Bs[nb][ak+0][arow]=b4n.x; Bs[nb][ak+1][arow]=b4n.y; Bs[nb][ak+2][arow]=b4n.z; Bs[nb][ak+3][arow]=b4n.w;
        }
        __syncthreads();
    }
#pragma unroll
    for (int i=0;i<4;i++){
        int r = row0 + ty*4 + i;
        if (r >= M) continue;
#pragma unroll
        for (int j=0;j<4;j++){
            int c = col0 + tx*4 + j;
            if (c >= N) continue;
            float v = acc[i][j];
            if (MODE==1) v += bias1[c] + bias2[c];
            else if (MODE==3) v = fmaxf(v + bias1[c], 0.f);
            else if (MODE==4) v += bias1[c];
            C[(size_t)r*ldc + c] = v;
        }
    }
}

// ---------------- graw via mma.sync bf16x2 (3 products), no gather ----------------
// CTA 128x128, 8 warps (2x4), warp tile 64x32. K chunks of 16, double buffered.
#define CH_TILE 6144                 // 128 rows * 48B padded
#define CH_BUF  (4*CH_TILE)          // 2 A splits + 2 B splits = 24576 B
#define GM_DSMEM (2*CH_BUF)          // 49152 B

__global__ void __launch_bounds__(256) graw_mma(){
    extern __shared__ char dsm[];
    const int tid = threadIdx.x, w = tid>>5, lane = tid&31;
    const int row0 = blockIdx.y*128, col0 = blockIdx.x*128;
    const int wr = w>>2, wc = w&3;
    const uint32_t dbase = smem_u32(dsm);

    const __nv_bfloat16* Asrc[2] = {d_h2b[0], d_h2b[1]};
    const __nv_bfloat16* Bsrc[2] = {d_w2b[0], d_w2b[1]};

    // per-thread chunk-load slots: 4 uint4 each (4 tiles x 256 units of 16B)
    int ld_tile[4], ld_row[4], ld_half[4];
    const __nv_bfloat16* ld_src[4];
#pragma unroll
    for (int j=0;j<4;j++){
        int idx = tid + j*256;
        int t = idx >> 8, pos = idx & 255;
        int row = pos >> 1, half = pos & 1;
        ld_tile[j]=t; ld_row[j]=row; ld_half[j]=half;
        if (t < 2) ld_src[j] = Asrc[t]   + (size_t)(row0+row)*HH + half*8;
        else       ld_src[j] = Bsrc[t-2] + (size_t)(col0+row)*HH + half*8;
    }

    float acc[4][4][4];
#pragma unroll
    for (int mi=0;mi<4;mi++)
#pragma unroll
        for (int ni=0;ni<4;ni++)
#pragma unroll
            for (int e=0;e<4;e++) acc[mi][ni][e]=0.f;

    uint4 v[4];
#pragma unroll
    for (int j=0;j<4;j++) v[j] = *(const uint4*)(ld_src[j]);
    {
        char* bp = dsm;
#pragma unroll
        for (int j=0;j<4;j++)
            *(uint4*)(bp + ld_tile[j]*CH_TILE + ld_row[j]*48 + ld_half[j]*16) = v[j];
    }
    __syncthreads();

    const uint32_t a_lm = dbase + (wr*64 + (lane&15))*48 + (lane>>4)*16;
    const uint32_t b_lm = dbase + (wc*32 + (lane&7))*48 + ((lane>>3)&1)*16;

    for (int kc = 0; kc < 64; kc++){
        if (kc+1 < 64){
#pragma unroll
            for (int j=0;j<4;j++) v[j] = *(const uint4*)(ld_src[j] + (kc+1)*16);
        }
        const uint32_t bb = (kc&1)*CH_BUF;

        unsigned Bf[2][4][2];
#pragma unroll
        for (int s=0;s<2;s++)
#pragma unroll
            for (int ni=0;ni<4;ni++)
                ldsm_x2(Bf[s][ni], b_lm + bb + (2+s)*CH_TILE + ni*8*48);

#pragma unroll
        for (int s=0;s<2;s++){
            unsigned Af[4][4];
#pragma unroll
            for (int mi=0;mi<4;mi++)
                ldsm_x4(Af[mi], a_lm + bb + s*CH_TILE + mi*16*48);
            const int nb = (s==0) ? 2 : 1;     // pairs: (0,0),(0,1),(1,0)
#pragma unroll
            for (int jb=0;jb<2;jb++){
                if (jb >= nb) break;
#pragma unroll
                for (int mi=0;mi<4;mi++)
#pragma unroll
                    for (int ni=0;ni<4;ni++)
                        mma_bf16(acc[mi][ni], Af[mi], Bf[jb][ni]);
            }
        }

        if (kc+1 < 64){
            char* bp = dsm + ((kc+1)&1)*CH_BUF;
#pragma unroll
            for (int j=0;j<4;j++)
                *(uint4*)(bp + ld_tile[j]*CH_TILE + ld_row[j]*48 + ld_half[j]*16) = v[j];
        }
        __syncthreads();
    }

    // store raw gates (fragment layout identical to Round-7 proven mapping)
#pragma unroll
    for (int mi=0;mi<4;mi++)
#pragma unroll
        for (int ni=0;ni<4;ni++){
            int rl = wr*64 + mi*16 + (lane>>2);
            int cl = wc*32 + ni*8 + 2*(lane&3);
            float2 p0 = make_float2(acc[mi][ni][0], acc[mi][ni][1]);
            float2 p1 = make_float2(acc[mi][ni][2], acc[mi][ni][3]);
            *(float2*)&d_graw[(size_t)(row0+rl)*G4   + col0 + cl] = p0;
            *(float2*)&d_graw[(size_t)(row0+rl+8)*G4 + col0 + cl] = p1;
        }
}

// ---------------- LSTM elementwise: gather G_raw rows + nonlinearity --------------
__global__ void __launch_bounds__(256) lstm_elem(int t, int cur){
    const int r = blockIdx.x, tid = threadIdx.x;
    const int prv = cur^1;
    const int b = r & 63;
    int o, pv;
    if (t == 0){ o = r; pv = VV; } else { o = d_order[r]; pv = d_prev[r]; }
    const float4* gr = (const float4*)(d_graw + (size_t)o*G4);
    const float4* xw = (const float4*)(d_xW2 + (size_t)b*G4);
    const float4* gt = (const float4*)(d_Gt2 + (size_t)pv*G4);
    const float* cpf = d_ct[prv] + (size_t)o*HH;
    float* hf = d_ht[cur] + (size_t)r*HH;
    float* cf = d_ct[cur] + (size_t)r*HH;
#pragma unroll
    for (int q=0;q<4;q++){
        int u = tid + q*256;
        float4 g = (t==0) ? make_float4(0,0,0,0) : gr[u];
        float4 x = xw[u];
        float4 G = gt[u];
        float ig = g.x + x.x + G.x;
        float fg = g.y + x.y + G.y;
        float gg = g.z + x.z + G.z;
        float og = g.w + x.w + G.w;
        float cold = (t==0) ? 0.f : cpf[u];
        float cn = sigmoidf(fg)*cold + sigmoidf(ig)*tanhf(gg);
        float hn = sigmoidf(og)*tanhf(cn);
        cf[u] = cn;
        hf[u] = hn;
        __nv_bfloat16 s0 = __float2bfloat16(hn);
        d_h2b[0][(size_t)r*HH + u] = s0;
        d_h2b[1][(size_t)r*HH + u] = __float2bfloat16(hn - __bfloat162float(s0));
    }
}

// ---------------- fc1 split-K GEMM (128x128, f32x2): partials, no bias -----------
__global__ void __launch_bounds__(256) gemm_fc1_f2(
    const float* __restrict__ A, const float* __restrict__ W)
{
    __shared__ float As[2][16][128+4];
    __shared__ float Bs[2][16][128+4];
    const int tid = threadIdx.x;
    const int row0 = blockIdx.y*128, col0 = blockIdx.x*128;
    const int kb = blockIdx.z * (HH/SK);
    const int arow = tid >> 1, ak = (tid & 1)*8;
    const int ty = tid >> 4, tx = tid & 15;

    const float* Arow = A + (size_t)(row0+arow)*HH + kb + ak;
    const float* Brow = W + (size_t)(col0+arow)*HH + kb + ak;

    float4 a0 = *(const float4*)Arow, a1 = *(const float4*)(Arow+4);
    float4 b0 = *(const float4*)Brow, b1 = *(const float4*)(Brow+4);
#pragma unroll
    for (int j=0;j<4;j++){
        As[0][ak+j][arow]=((const float*)&a0)[j]; As[0][ak+4+j][arow]=((const float*)&a1)[j];
        Bs[0][ak+j][arow]=((const float*)&b0)[j]; Bs[0][ak+4+j][arow]=((const float*)&b1)[j];
    }
    __syncthreads();

    ull acc[8][4];
#pragma unroll
    for (int i=0;i<8;i++)
#pragma unroll
        for (int p=0;p<4;p++) acc[i][p]=0ull;

    const int NT = (HH/SK)/16;
    for (int it=0; it<NT; it++){
        int cur = it & 1;
        float4 a0n,a1n,b0n,b1n;
        if (it+1 < NT){
            int k0 = (it+1)*16;
            a0n=*(const float4*)(Arow+k0); a1n=*(const float4*)(Arow+k0+4);
            b0n=*(const float4*)(Brow+k0); b1n=*(const float4*)(Brow+k0+4);
        }
#pragma unroll
        for (int kk=0; kk<16; kk++){
            const float* Ar = &As[cur][kk][ty*8];
            const float* Br = &Bs[cur][kk][tx*8];
            float4 af0 = *(const float4*)Ar, af1 = *(const float4*)(Ar+4);
            ulonglong2 bq0 = *(const ulonglong2*)Br;
            ulonglong2 bq1 = *(const ulonglong2*)(Br+4);
            float av[8] = {af0.x,af0.y,af0.z,af0.w,af1.x,af1.y,af1.z,af1.w};
#pragma unroll
            for (int i=0;i<8;i++){
                ull ap = pkdup(av[i]);
                fma2(acc[i][0], ap, bq0.x);
                fma2(acc[i][1], ap, bq0.y);
                fma2(acc[i][2], ap, bq1.x);
                fma2(acc[i][3], ap, bq1.y);
            }
        }
        if (it+1 < NT){
            int nb = cur^1;
#pragma unroll
            for (int j=0;j<4;j++){
                As[nb][ak+j][arow]=((const float*)&a0n)[j]; As[nb][ak+4+j][arow]=((const float*)&a1n)[j];
                Bs[nb][ak+j][arow]=((const float*)&b0n)[j]; Bs[nb][ak+4+j][arow]=((const float*)&b1n)[j];
            }
        }
        __syncthreads();
    }

    float* Cp = d_fc1p[blockIdx.z];
#pragma unroll
    for (int i=0;i<8;i++){
        int r = row0 + ty*8 + i;
        float2 q0=upk2(acc[i][0]), q1=upk2(acc[i][1]), q2=upk2(acc[i][2]), q3=upk2(acc[i][3]);
        *(float4*)&Cp[(size_t)r*HH + col0 + tx*8]     = make_float4(q0.x,q0.y,q1.x,q1.y);
        *(float4*)&Cp[(size_t)r*HH + col0 + tx*8 + 4] = make_float4(q2.x,q2.y,q3.x,q3.y);
    }
}

// ---------------- out split-K GEMM: A = relu(sum fc1 partials + b_fc1) -----------
__global__ void __launch_bounds__(256) gemm_out_f2(
    const float* __restrict__ W, const float* __restrict__ b_fc1)
{
    __shared__ float As[2][16][128+4];
    __shared__ float Bs[2][16][128+4];
    const int tid = threadIdx.x;
    const int row0 = blockIdx.y*128, col0 = blockIdx.x*128;
    const int kb = blockIdx.z * (HH/SK);
    const int arow = tid >> 1, ak = (tid & 1)*8;
    const int ty = tid >> 4, tx = tid & 15;
    const int br = col0 + arow;

    const size_t aoff = (size_t)(row0+arow)*HH + kb + ak;
    const float* Brow = (br < VV) ? (W + (size_t)br*HH + kb + ak) : nullptr;

    float4 a0, a1, b0, b1;
    {
        float4 p0=*(const float4*)&d_fc1p[0][aoff], p1=*(const float4*)&d_fc1p[1][aoff];
        float4 p2=*(const float4*)&d_fc1p[2][aoff], p3=*(const float4*)&d_fc1p[3][aoff];
        float4 bf=*(const float4*)&b_fc1[kb+ak];
        a0.x=fmaxf(p0.x+p1.x+p2.x+p3.x+bf.x,0.f); a0.y=fmaxf(p0.y+p1.y+p2.y+p3.y+bf.y,0.f);
        a0.z=fmaxf(p0.z+p1.z+p2.z+p3.z+bf.z,0.f); a0.w=fmaxf(p0.w+p1.w+p2.w+p3.w+bf.w,0.f);
        p0=*(const float4*)&d_fc1p[0][aoff+4]; p1=*(const float4*)&d_fc1p[1][aoff+4];
        p2=*(const float4*)&d_fc1p[2][aoff+4]; p3=*(const float4*)&d_fc1p[3][aoff+4];
        bf=*(const float4*)&b_fc1[kb+ak+4];
        a1.x=fmaxf(p0.x+p1.x+p2.x+p3.x+bf.x,0.f); a1.y=fmaxf(p0.y+p1.y+p2.y+p3.y+bf.y,0.f);
        a1.z=fmaxf(p0.z+p1.z+p2.z+p3.z+bf.z,0.f); a1.w=fmaxf(p0.w+p1.w+p2.w+p3.w+bf.w,0.f);
        b0 = Brow ? *(const float4*)Brow     : make_float4(0,0,0,0);
        b1 = Brow ? *(const float4*)(Brow+4) : make_float4(0,0,0,0);
    }
#pragma unroll
    for (int j=0;j<4;j++){
        As[0][ak+j][arow]=((const float*)&a0)[j]; As[0][ak+4+j][arow]=((const float*)&a1)[j];
        Bs[0][ak+j][arow]=((const float*)&b0)[j]; Bs[0][ak+4+j][arow]=((const float*)&b1)[j];
    }
    __syncthreads();

    ull acc[8][4];
#pragma unroll
    for (int i=0;i<8;i++)
#pragma unroll
        for (int p=0;p<4;p++) acc[i][p]=0ull;

    const int NT = (HH/SK)/16;
    for (int it=0; it<NT; it++){
        int cur = it & 1;
        float4 a0n,a1n,b0n,b1n;
        if (it+1 < NT){
            int k0 = (it+1)*16;
            float4 p0=*(const float4*)&d_fc1p[0][aoff+k0], p1=*(const float4*)&d_fc1p[1][aoff+k0];
            float4 p2=*(const float4*)&d_fc1p[2][aoff+k0], p3=*(const float4*)&d_fc1p[3][aoff+k0];
            float4 bf=*(const float4*)&b_fc1[kb+ak+k0];
            a0n.x=fmaxf(p0.x+p1.x+p2.x+p3.x+bf.x,0.f); a0n.y=fmaxf(p0.y+p1.y+p2.y+p3.y+bf.y,0.f);
            a0n.z=fmaxf(p0.z+p1.z+p2.z+p3.z+bf.z,0.f); a0n.w=fmaxf(p0.w+p1.w+p2.w+p3.w+bf.w,0.f);
            p0=*(const float4*)&d_fc1p[0][aoff+k0+4]; p1=*(const float4*)&d_fc1p[1][aoff+k0+4];
            p2=*(const float4*)&d_fc1p[2][aoff+k0+4]; p3=*(const float4*)&d_fc1p[3][aoff+k0+4];
            bf=*(const float4*)&b_fc1[kb+ak+k0+4];
            a1n.x=fmaxf(p0.x+p1.x+p2.x+p3.x+bf.x,0.f); a1n.y=fmaxf(p0.y+p1.y+p2.y+p3.y+bf.y,0.f);
            a1n.z=fmaxf(p0.z+p1.z+p2.z+p3.z+bf.z,0.f); a1n.w=fmaxf(p0.w+p1.w+p2.w+p3.w+bf.w,0.f);
            b0n = Brow ? *(const float4*)(Brow+k0)   : make_float4(0,0,0,0);
            b1n = Brow ? *(const float4*)(Brow+k0+4) : make_float4(0,0,0,0);
        }
#pragma unroll
        for (int kk=0; kk<16; kk++){
            const float* Ar = &As[cur][kk][ty*8];
            const float* Br = &Bs[cur][kk][tx*8];
            float4 af0 = *(const float4*)Ar, af1 = *(const float4*)(Ar+4);
            ulonglong2 bq0 = *(const ulonglong2*)Br;
            ulonglong2 bq1 = *(const ulonglong2*)(Br+4);
            float av[8] = {af0.x,af0.y,af0.z,af0.w,af1.x,af1.y,af1.z,af1.w};
#pragma unroll
            for (int i=0;i<8;i++){
                ull ap = pkdup(av[i]);
                fma2(acc[i][0], ap, bq0.x);
                fma2(acc[i][1], ap, bq0.y);
                fma2(acc[i][2], ap, bq1.x);
                fma2(acc[i][3], ap, bq1.y);
            }
        }
        if (it+1 < NT){
            int nb = cur^1;
#pragma unroll
            for (int j=0;j<4;j++){
                As[nb][ak+j][arow]=((const float*)&a0n)[j]; As[nb][ak+4+j][arow]=((const float*)&a1n)[j];
                Bs[nb][ak+j][arow]=((const float*)&b0n)[j]; Bs[nb][ak+4+j][arow]=((const float*)&b1n)[j];
            }
        }
        __syncthreads();
    }

    float* Cp = d_lpp[blockIdx.z];
    const int c0 = col0 + tx*8;
    if (c0 + 8 <= VV){
#pragma unroll
        for (int i=0;i<8;i++){
            int r = row0 + ty*8 + i;
            float2 q0=upk2(acc[i][0]), q1=upk2(acc[i][1]), q2=upk2(acc[i][2]), q3=upk2(acc[i][3]);
            *(float4*)&Cp[(size_t)r*VV + c0]     = make_float4(q0.x,q0.y,q1.x,q1.y);
            *(float4*)&Cp[(size_t)r*VV + c0 + 4] = make_float4(q2.x,q2.y,q3.x,q3.y);
        }
    }
}

// ---------------- warp LSE ---------------------------------------------------------
__device__ __forceinline__ float warpLSE(const float* __restrict__ base,
                                         const float* __restrict__ t1,
                                         const float* __restrict__ t2){
    int lane = threadIdx.x & 31;
    float m = -INFINITY, s = 0.f;
    for (int n = lane; n < NP; n += 32){
        float x = base[n];
        if (t1) x -= t1[n];
        if (t2) x -= t2[n];
        if (x > m){ s = s*expf(m-x) + 1.f; m = x; } else s += expf(x-m);
    }
#pragma unroll
    for (int off=16; off; off>>=1){
        float m2 = __shfl_xor_sync(0xffffffffu, m, off);
        float s2 = __shfl_xor_sync(0xffffffffu, s, off);
        float mm = fmaxf(m, m2);
        s = s*expf(m-mm) + s2*expf(m2-mm);
        m = mm;
    }
    return m + logf(s);
}

// ---------------- fused select (per batch element) ---------------------------------
__global__ void __launch_bounds__(256) select_kernel(const float* __restrict__ gu,
                                                     const float* __restrict__ b_out,
                                                     int t, int cur){
    __shared__ float pool[KB*NP + NP];
    __shared__ float rv[256];
    __shared__ int   ri[256];
    __shared__ float entS[KB], phiS[KB], gvalS[KB], logIs_s[KB+1];
    __shared__ int   ordS[KB], snewS[KB];

    const int i = blockIdx.x, tid = threadIdx.x;
    const int lane = tid & 31, w = tid >> 5;
    float (*gm)[VV] = (float(*)[VV])pool;

    const int r = w*BB + i;
    const size_t rb = (size_t)r*VV;

    float lv[13];
#pragma unroll
    for (int ii=0; ii<13; ii++){
        int v = lane + ii*32;
        float val = -INFINITY;
        if (v < VV)
            val = d_lpp[0][rb+v] + d_lpp[1][rb+v] + d_lpp[2][rb+v] + d_lpp[3][rb+v] + b_out[v];
        lv[ii] = val;
    }
    float m = -INFINITY;
#pragma unroll
    for (int ii=0; ii<13; ii++) m = fmaxf(m, lv[ii]);
#pragma unroll
    for (int off=16; off; off>>=1) m = fmaxf(m, __shfl_xor_sync(0xffffffffu, m, off));
    float s = 0.f;
#pragma unroll
    for (int ii=0; ii<13; ii++){ int v = lane+ii*32; if (v < VV) s += expf(lv[ii]-m); }
#pragma unroll
    for (int off=16; off; off>>=1) s += __shfl_xor_sync(0xffffffffu, s, off);
    float lse = m + logf(s);

    float lpr = d_logp[cur][r];
    float Gr  = d_Gmx[cur][r];
    const float* u = gu + ((size_t)t*RR + r)*VV;
    float ent = 0.f, zm = -INFINITY;
#pragma unroll
    for (int ii=0; ii<13; ii++){
        int v = lane + ii*32;
        if (v >= VV) continue;
        float l = lv[ii]-lse;
        d_lpn[rb+v] = l;
        ent += l*expf(l);
        float gmb = -logf(-logf(u[v]*(1.f-2e-7f)+1e-7f));
        float gph = l + lpr + gmb;
        gm[w][v] = gph;
        zm = fmaxf(zm, gph);
    }
#pragma unroll
    for (int off=16; off; off>>=1){
        ent += __shfl_xor_sync(0xffffffffu, ent, off);
        zm = fmaxf(zm, __shfl_xor_sync(0xffffffffu, zm, off));
    }
    if (lane==0) entS[w] = ent;
    for (int v=lane; v<VV; v+=32){
        float gph = gm[w][v];
        float vv = Gr - gph + log1mexp(gph - zm);
        float val = Gr - fmaxf(vv,0.f) - log1pf(expf(-fabsf(vv)));
        gm[w][v] = (t==0 && w>0) ? -INFINITY : val;
    }
    __syncthreads();

    for (int round=0; round<KB; round++){
        float bv = -INFINITY; int bi = 0x7fffffff;
        for (int idx=tid; idx<KB*VV; idx+=256){
            float v = pool[idx];
            if (v > bv || (v == bv && idx < bi)){ bv=v; bi=idx; }
        }
        rv[tid]=bv; ri[tid]=bi; __syncthreads();
        for (int off=128; off; off>>=1){
            if (tid < off){
                if (rv[tid+off] > rv[tid] || (rv[tid+off]==rv[tid] && ri[tid+off]<ri[tid])){
                    rv[tid]=rv[tid+off]; ri[tid]=ri[tid+off];
                }
            }
            __syncthreads();
        }
        if (tid==0){
            int widx = ri[0]; int j = widx/VV, v = widx - j*VV;
            gvalS[round]=rv[0]; ordS[round]=j; snewS[round]=v;
            pool[widx] = -INFINITY;
        }
        __syncthreads();
    }

    const int nxt = cur^1;
    for (int idx=tid; idx<KB*LL; idx+=256){
        int j = idx/LL, tt = idx - j*LL;
        if (tt == t) continue;
        int rn = j*BB+i, o = ordS[j]*BB+i;
        d_samples[nxt][rn*LL+tt] = d_samples[cur][o*LL+tt];
        d_outputs[nxt][rn*LL+tt] = d_outputs[cur][o*LL+tt];
    }
    if (tid < KB){
        int j = tid, rn = j*BB+i, o = ordS[j]*BB+i, sv = snewS[j];
        float lpv = d_lpn[(size_t)o*VV + sv];
        float nl  = d_logp[cur][o] + lpv;
        d_samples[nxt][rn*LL+t] = (float)sv;
        d_outputs[nxt][rn*LL+t] = lpv;
        d_logp[nxt][rn] = nl;
        d_Gmx[nxt][rn]  = gvalS[j];
        d_prev[rn]  = sv;
        d_order[rn] = o;
        d_phik[i*KB+j] = nl;
        phiS[j] = nl;
    }
    __syncthreads();

    float (*Ts)[NP] = (float(*)[NP])pool;
    float* base = pool + KB*NP;
    float p[KB], pS = 0.f;
#pragma unroll
    for (int j=0;j<KB;j++){ p[j] = expf(phiS[j]); pS += p[j]; }
    for (int n=tid; n<NP; n+=256){
        float lu = logf(((float)n + 0.5f)/(float)NP);
        float bs = -pS*lu;
#pragma unroll
        for (int j=0;j<KB;j++){
            float x = log1mexp(p[j]*lu);
            Ts[j][n] = x;
            bs += x;
        }
        base[n] = bs;
    }
    __syncthreads();

    const float logN = logf((float)NP);
    float resA = warpLSE(base, Ts[w], nullptr) - logN;
    if (lane==0) logIs_s[w] = resA;
    if (w==0){
        float li = warpLSE(base, nullptr, nullptr) - logN;
        if (lane==0) logIs_s[KB] = li;
    }
    __syncthreads();
    float logI = logIs_s[KB];
    if (tid < KB) d_logRs[i*KB+tid] = logIs_s[tid] - logI;

    for (int pp = w; pp < 28; pp += 8){
        int a = 0, rem = pp;
        while (rem >= 7 - a){ rem -= (7 - a); a++; }
        int b = a + 1 + rem;
        float lss = warpLSE(base, Ts[a], Ts[b]) - logN;
        if (lane==0){
            d_logRss[i*64 + a*8 + b] = lss - logIs_s[a];
            d_logRss[i*64 + b*8 + a] = lss - logIs_s[b];
        }
    }
    if (tid < KB) d_logRss[i*64 + tid*9] = 0.f;
    if (tid == 0){
        float Wsum = 0.f, ws = 0.f;
#pragma unroll
        for (int j=0;j<KB;j++){
            float wq = expf(phiS[j] + logIs_s[j] - logI);
            Wsum += wq;
            ws   += wq * entS[ordS[j]];
        }
        d_entplot[i] += ws;
        d_entelem[i] += ws / Wsum;
    }
}

// ---------------- output assembly ---------------------------------------------------
__global__ void finalize_kernel(float* __restrict__ out, int out_size){
    int idx = blockIdx.x*blockDim.x + threadIdx.x;
    if (idx >= out_size || idx >= 18560) return;
    const int FIN = LL & 1;
    if (idx < 6656){
        int i = idx/104, rem = idx%104, j = rem/13, tt = rem%13;
        out[idx] = d_outputs[FIN][(j*BB+i)*LL + tt];
    } else if (idx < 13312){
        int q = idx - 6656;
        int i = q/104, rem = q%104, j = rem/13, tt = rem%13;
        out[idx] = d_samples[FIN][(j*BB+i)*LL + tt];
    } else if (idx < 13376){
        out[idx] = d_entelem[idx-13312];
    } else if (idx < 13888){
        out[idx] = d_logRs[idx-13376];
    } else if (idx < 17984){
        out[idx] = d_logRss[idx-13888];
    } else if (idx < 18496){
        out[idx] = d_phik[idx-17984];
    } else {
        out[idx] = d_entplot[idx-18496];
    }
}

// ---------------- host driver ---------------------------------------------------------
extern "C" void kernel_launch(void* const* d_in, const int* in_sizes, int n_in,
                              void* d_out, int out_size){
    const float* x_feat  = (const float*)d_in[0];
    const float* W_in_op = (const float*)d_in[1];
    const float* b_in_op = (const float*)d_in[2];
    const float* W_ih    = (const float*)d_in[3];
    const float* W_hh    = (const float*)d_in[4];
    const float* b_ih    = (const float*)d_in[5];
    const float* b_hh    = (const float*)d_in[6];
    const float* W_fc1   = (const float*)d_in[7];
    const float* b_fc1   = (const float*)d_in[8];
    const float* W_out   = (const float*)d_in[9];
    const float* b_out   = (const float*)d_in[10];
    const float* gu      = (const float*)d_in[11];
    (void)in_sizes; (void)n_in;

    void* tmp;
    cudaGetSymbolAddress(&tmp, d_ht);    float* p_ht  = (float*)tmp;
    cudaGetSymbolAddress(&tmp, d_xW);    float* p_xW  = (float*)tmp;
    cudaGetSymbolAddress(&tmp, d_E);     float* p_E   = (float*)tmp;
    cudaGetSymbolAddress(&tmp, d_Gt);    float* p_Gt  = (float*)tmp;

    static cudaStream_t s2 = nullptr;
    static cudaEvent_t evA = nullptr, evB = nullptr;
    if (s2 == nullptr){
        cudaStreamCreateWithFlags(&s2, cudaStreamNonBlocking);
        cudaEventCreateWithFlags(&evA, cudaEventDisableTiming);
        cudaEventCreateWithFlags(&evB, cudaEventDisableTiming);
        cudaFuncSetAttribute(graw_mma, cudaFuncAttributeMaxDynamicSharedMemorySize, GM_DSMEM);
    }

    // fork stream2 off the (captured) default stream; weight prep runs there
    cudaEventRecord(evA, 0);
    cudaStreamWaitEvent(s2, evA, 0);
    reorder_whh<<<(G4*HH+255)/256, 256, 0, s2>>>(W_hh);

    init_kernel<<<256,256>>>(W_in_op, b_in_op);
    gemm_db<1><<<dim3(64,1),256>>>(x_feat,1024, W_ih,1152, p_xW,G4,
                                   BB,G4,1024, b_ih, b_hh);
    gemm_db<0><<<dim3(64,7),256>>>(p_E,128, W_ih+1024,1152, p_Gt,G4,
                                   V1,G4,128, nullptr, nullptr);
    permute_gates<<<((BB+V1)*G4+255)/256,256>>>();

    for (int t = 0; t < LL; t++){
        int cur = t & 1;
        float* h_cur = p_ht + (size_t)cur*RR*HH;

        // gather + LSTM nonlinearity; also emits bf16x2 splits of h
        lstm_elem<<<RR,256>>>(t, cur);

        if (t < LL-1){
            // fork: G_raw(t) = h(t) @ Whh2^T on tensor pipe (stream2)
            cudaEventRecord(evA, 0);
            cudaStreamWaitEvent(s2, evA, 0);
            graw_mma<<<dim3(32,4),256,GM_DSMEM,s2>>>();
            cudaEventRecord(evB, s2);
        }

        gemm_fc1_f2<<<dim3(8,4,SK),256>>>(h_cur, W_fc1);
        gemm_out_f2<<<dim3(4,4,SK),256>>>(W_out, b_fc1);
        select_kernel<<<BB,256>>>(gu, b_out, t, cur);

        if (t < LL-1){
            cudaStreamWaitEvent(0, evB, 0);
        }
    }

    finalize_kernel<<<(18560+255)/256,256>>>((float*)d_out, out_size);
}

// round 10
// speedup vs baseline: 4.0724x; 1.3789x over previous
#include <cuda_runtime.h>
#include <cuda_bf16.h>
#include <math.h>
#include <stdint.h>

#define BB 64      // batch
#define KB 8       // beams
#define RR 512     // BB*KB
#define HH 1024    // hidden
#define VV 400     // vocab
#define V1 401
#define LL 13      // program_len
#define G4 4096    // 4*HH
#define NP 1000    // log_R quadrature points
#define SK 4       // split-K slices

typedef unsigned long long ull;

// ---------------- persistent scratch -----------------------------------------
__device__ float d_ct[2][RR*HH];
__device__ float d_Gmx[2][RR];
__device__ float d_logp[2][RR];
__device__ int   d_prev[RR];
__device__ int   d_order[RR];
__device__ float d_samples[2][RR*LL];
__device__ float d_outputs[2][RR*LL];
__device__ float d_entplot[BB];
__device__ float d_entelem[BB];
__device__ float d_xW[BB*G4];
__device__ float d_xW2[BB*G4];
__device__ float d_E[V1*128];
__device__ float d_Gt[V1*G4];
__device__ float d_Gt2[V1*G4];
__device__ __nv_bfloat16 d_w2b[2][G4*HH];    // W_hh (interleaved rows) bf16x2
__device__ __nv_bfloat16 d_wf2b[2][HH*HH];   // W_fc1 bf16x2
__device__ __nv_bfloat16 d_wo2b[2][512*HH];  // W_out (padded to 512 rows) bf16x2
__device__ __nv_bfloat16 d_h2b[2][RR*HH];    // h bf16x2 (current step)
__device__ __nv_bfloat16 d_hd2b[2][RR*HH];   // hd bf16x2
__device__ float d_graw[RR*G4];
__device__ float d_fc1p[SK][RR*HH];
__device__ float d_lpp[SK][RR*VV];
__device__ float d_lpn[RR*VV];
__device__ float d_phik[BB*KB];
__device__ float d_logRs[BB*KB];
__device__ float d_logRss[BB*KB*KB];

// ---------------- helpers ------------------------------------------------------
__device__ __forceinline__ float sigmoidf(float x){ return 1.f/(1.f+expf(-x)); }

__device__ __forceinline__ float log1mexp(float x){
    x = fminf(x, -1e-38f);
    if (x > -0.6931472f) return logf(-expm1f(x));
    return log1pf(-expf(x));
}
__device__ __forceinline__ uint32_t smem_u32(const void* p){
    uint32_t a;
    asm("{ .reg .u64 t; cvta.to.shared.u64 t, %1; cvt.u32.u64 %0, t; }" : "=r"(a) : "l"(p));
    return a;
}
__device__ __forceinline__ void ldsm_x4(unsigned* r, uint32_t addr){
    asm volatile("ldmatrix.sync.aligned.m8n8.x4.shared.b16 {%0,%1,%2,%3}, [%4];"
        : "=r"(r[0]), "=r"(r[1]), "=r"(r[2]), "=r"(r[3]) : "r"(addr));
}
__device__ __forceinline__ void ldsm_x2(unsigned* r, uint32_t addr){
    asm volatile("ldmatrix.sync.aligned.m8n8.x2.shared.b16 {%0,%1}, [%2];"
        : "=r"(r[0]), "=r"(r[1]) : "r"(addr));
}
__device__ __forceinline__ void mma_bf16(float* c, const unsigned* a, const unsigned* b){
    asm volatile("mma.sync.aligned.m16n8k16.row.col.f32.bf16.bf16.f32 "
        "{%0,%1,%2,%3}, {%4,%5,%6,%7}, {%8,%9}, {%0,%1,%2,%3};"
        : "+f"(c[0]), "+f"(c[1]), "+f"(c[2]), "+f"(c[3])
        : "r"(a[0]), "r"(a[1]), "r"(a[2]), "r"(a[3]), "r"(b[0]), "r"(b[1]));
}

// ---------------- init ----------------------------------------------------------
__global__ void init_kernel(const float* __restrict__ W_in_op,
                            const float* __restrict__ b_in_op){
    int idx = blockIdx.x*blockDim.x + threadIdx.x;
    int stride = gridDim.x*blockDim.x;
    for (int i = idx; i < RR;    i += stride){ d_Gmx[0][i]=0.f; d_logp[0][i]=0.f; }
    for (int i = idx; i < RR*LL; i += stride){ d_samples[0][i]=0.f; d_outputs[0][i]=0.f; }
    for (int i = idx; i < BB;    i += stride){ d_entplot[i]=0.f; d_entelem[i]=0.f; }
    for (int i = idx; i < V1*128; i += stride){
        int s = i >> 7, m = i & 127;
        d_E[i] = fmaxf(W_in_op[m*V1 + s] + b_in_op[m], 0.f);
    }
}

__global__ void reorder_whh(const float* __restrict__ W){
    int idx = blockIdx.x*blockDim.x + threadIdx.x;
    if (idx >= G4*HH) return;
    int c = idx >> 10, k = idx & 1023;
    int h = c >> 2, g = c & 3;
    float w = W[(size_t)(g*HH + h)*HH + k];
    __nv_bfloat16 b0 = __float2bfloat16(w);
    d_w2b[0][idx] = b0;
    d_w2b[1][idx] = __float2bfloat16(w - __bfloat162float(b0));
}

__global__ void split_fw(const float* __restrict__ W_fc1,
                         const float* __restrict__ W_out){
    int idx = blockIdx.x*blockDim.x + threadIdx.x;
    const int N1 = HH*HH;
    if (idx < N1){
        float w = W_fc1[idx];
        __nv_bfloat16 b0 = __float2bfloat16(w);
        d_wf2b[0][idx] = b0;
        d_wf2b[1][idx] = __float2bfloat16(w - __bfloat162float(b0));
    } else if (idx < N1 + 512*HH){
        int j = idx - N1;
        int row = j >> 10, k = j & 1023;
        float w = (row < VV) ? W_out[(size_t)row*HH + k] : 0.f;
        __nv_bfloat16 b0 = __float2bfloat16(w);
        d_wo2b[0][j] = b0;
        d_wo2b[1][j] = __float2bfloat16(w - __bfloat162float(b0));
    }
}

__global__ void permute_gates(){
    int idx = blockIdx.x*blockDim.x + threadIdx.x;
    if (idx >= (BB+V1)*G4) return;
    int row = idx / G4, c = idx - row*G4;
    int g = c >> 10, h = c & 1023;
    int dstc = 4*h + g;
    if (row < BB) d_xW2[row*G4 + dstc] = d_xW[idx];
    else          d_Gt2[(row-BB)*G4 + dstc] = d_Gt[idx - BB*G4];
}

// ---------------- setup GEMM (64x64x16 double buffered, scalar) -------------------
template<int MODE>
__global__ void __launch_bounds__(256) gemm_db(
    const float* __restrict__ A, int lda,
    const float* __restrict__ B, int ldb,
    float* __restrict__ C, int ldc,
    int M, int N, int K,
    const float* __restrict__ bias1,
    const float* __restrict__ bias2)
{
    __shared__ float As[2][16][64+4];
    __shared__ float Bs[2][16][64+4];
    const int tid = threadIdx.x;
    const int row0 = blockIdx.y*64, col0 = blockIdx.x*64;
    const int arow = tid >> 2, ak = (tid & 3)*4;
    const int ty = tid >> 4, tx = tid & 15;

    const int ar = row0 + arow, br = col0 + arow;
    float4 a4 = make_float4(0,0,0,0), b4 = make_float4(0,0,0,0);
    if (ar < M) a4 = *(const float4*)(A + (size_t)ar*lda + ak);
    if (br < N) b4 = *(const float4*)(B + (size_t)br*ldb + ak);
    As[0][ak+0][arow]=a4.x; As[0][ak+1][arow]=a4.y; As[0][ak+2][arow]=a4.z; As[0][ak+3][arow]=a4.w;
    Bs[0][ak+0][arow]=b4.x; Bs[0][ak+1][arow]=b4.y; Bs[0][ak+2][arow]=b4.z; Bs[0][ak+3][arow]=b4.w;
    __syncthreads();

    float acc[4][4];
#pragma unroll
    for (int i=0;i<4;i++)
#pragma unroll
        for (int j=0;j<4;j++) acc[i][j]=0.f;

    const int NT = K/16;
    for (int it=0; it<NT; it++){
        int cur = it & 1;
        float4 a4n, b4n;
        if (it+1 < NT){
            int k0 = (it+1)*16;
            a4n = make_float4(0,0,0,0); b4n = make_float4(0,0,0,0);
            if (ar < M) a4n = *(const float4*)(A + (size_t)ar*lda + k0 + ak);
            if (br < N) b4n = *(const float4*)(B + (size_t)br*ldb + k0 + ak);
        }
#pragma unroll
        for (int kk=0; kk<16; kk++){
            float4 ra = *(const float4*)&As[cur][kk][ty*4];
            float4 rb = *(const float4*)&Bs[cur][kk][tx*4];
            float r[4]={ra.x,ra.y,ra.z,ra.w};
            float cb[4]={rb.x,rb.y,rb.z,rb.w};
#pragma unroll
            for (int i=0;i<4;i++)
#pragma unroll
                for (int j=0;j<4;j++) acc[i][j] = fmaf(r[i], cb[j], acc[i][j]);
        }
        if (it+1 < NT){
            int nb = cur^1;
            As[nb][ak+0][arow]=a4n.x; As[nb][ak+1][arow]=a4n.y; As[nb][ak+2][arow]=a4n.z; As[nb][ak+3][arow]=a4n.w;
            Bs[nb][ak+0][arow]=b4n.x; Bs[nb][ak+1][arow]=b4n.y; Bs[nb][ak+2][arow]=b4n.z; Bs[nb][ak+3][arow]=b4n.w;
        }
        __syncthreads();
    }
#pragma unroll
    for (int i=0;i<4;i++){
        int r = row0 + ty*4 + i;
        if (r >= M) continue;
#pragma unroll
        for (int j=0;j<4;j++){
            int c = col0 + tx*4 + j;
            if (c >= N) continue;
            float v = acc[i][j];
            if (MODE==1) v += bias1[c] + bias2[c];
            else if (MODE==3) v = fmaxf(v + bias1[c], 0.f);
            else if (MODE==4) v += bias1[c];
            C[(size_t)r*ldc + c] = v;
        }
    }
}

// ---------------- generic bf16x2 HMMA NT GEMM (3 products) ------------------------
// CTA 128x128, 8 warps (2x4), warp tile 64x32. K chunks of 16, double buffered.
#define CH_TILE 6144                 // 128 rows * 48B padded
#define CH_BUF  (4*CH_TILE)          // 2 A splits + 2 B splits
#define GM_DSMEM (2*CH_BUF)          // 49152 B

template<int NCH, bool GUARD>
__global__ void __launch_bounds__(256) mma_nt(
    const __nv_bfloat16* __restrict__ A0, const __nv_bfloat16* __restrict__ A1,
    const __nv_bfloat16* __restrict__ B0, const __nv_bfloat16* __restrict__ B1,
    float* __restrict__ Cb, int ldc, size_t cstride)
{
    extern __shared__ char dsm[];
    const int tid = threadIdx.x, w = tid>>5, lane = tid&31;
    const int row0 = blockIdx.y*128, col0 = blockIdx.x*128;
    const int kb = blockIdx.z * (NCH*16);
    const int wr = w>>2, wc = w&3;
    const uint32_t dbase = smem_u32(dsm);
    float* C = Cb + blockIdx.z * cstride;

    const __nv_bfloat16* Asrc[2] = {A0, A1};
    const __nv_bfloat16* Bsrc[2] = {B0, B1};

    int ld_tile[4], ld_row[4], ld_half[4];
    const __nv_bfloat16* ld_src[4];
#pragma unroll
    for (int j=0;j<4;j++){
        int idx = tid + j*256;
        int t = idx >> 8, pos = idx & 255;
        int row = pos >> 1, half = pos & 1;
        ld_tile[j]=t; ld_row[j]=row; ld_half[j]=half;
        if (t < 2) ld_src[j] = Asrc[t]   + (size_t)(row0+row)*HH + kb + half*8;
        else       ld_src[j] = Bsrc[t-2] + (size_t)(col0+row)*HH + kb + half*8;
    }

    float acc[4][4][4];
#pragma unroll
    for (int mi=0;mi<4;mi++)
#pragma unroll
        for (int ni=0;ni<4;ni++)
#pragma unroll
            for (int e=0;e<4;e++) acc[mi][ni][e]=0.f;

    uint4 v[4];
#pragma unroll
    for (int j=0;j<4;j++) v[j] = *(const uint4*)(ld_src[j]);
    {
        char* bp = dsm;
#pragma unroll
        for (int j=0;j<4;j++)
            *(uint4*)(bp + ld_tile[j]*CH_TILE + ld_row[j]*48 + ld_half[j]*16) = v[j];
    }
    __syncthreads();

    const uint32_t a_lm = dbase + (wr*64 + (lane&15))*48 + (lane>>4)*16;
    const uint32_t b_lm = dbase + (wc*32 + (lane&7))*48 + ((lane>>3)&1)*16;

    for (int kc = 0; kc < NCH; kc++){
        if (kc+1 < NCH){
#pragma unroll
            for (int j=0;j<4;j++) v[j] = *(const uint4*)(ld_src[j] + (kc+1)*16);
        }
        const uint32_t bb = (kc&1)*CH_BUF;

        unsigned Bf[2][4][2];
#pragma unroll
        for (int s=0;s<2;s++)
#pragma unroll
            for (int ni=0;ni<4;ni++)
                ldsm_x2(Bf[s][ni], b_lm + bb + (2+s)*CH_TILE + ni*8*48);

#pragma unroll
        for (int s=0;s<2;s++){
            unsigned Af[4][4];
#pragma unroll
            for (int mi=0;mi<4;mi++)
                ldsm_x4(Af[mi], a_lm + bb + s*CH_TILE + mi*16*48);
            const int nb = (s==0) ? 2 : 1;     // pairs: (0,0),(0,1),(1,0)
#pragma unroll
            for (int jb=0;jb<2;jb++){
                if (jb >= nb) break;
#pragma unroll
                for (int mi=0;mi<4;mi++)
#pragma unroll
                    for (int ni=0;ni<4;ni++)
                        mma_bf16(acc[mi][ni], Af[mi], Bf[jb][ni]);
            }
        }

        if (kc+1 < NCH){
            char* bp = dsm + ((kc+1)&1)*CH_BUF;
#pragma unroll
            for (int j=0;j<4;j++)
                *(uint4*)(bp + ld_tile[j]*CH_TILE + ld_row[j]*48 + ld_half[j]*16) = v[j];
        }
        __syncthreads();
    }

#pragma unroll
    for (int mi=0;mi<4;mi++)
#pragma unroll
        for (int ni=0;ni<4;ni++){
            int rl = wr*64 + mi*16 + (lane>>2);
            int cl = wc*32 + ni*8 + 2*(lane&3);
            if (GUARD && col0+cl >= ldc) continue;
            float2 p0 = make_float2(acc[mi][ni][0], acc[mi][ni][1]);
            float2 p1 = make_float2(acc[mi][ni][2], acc[mi][ni][3]);
            *(float2*)&C[(size_t)(row0+rl)*ldc   + col0 + cl] = p0;
            *(float2*)&C[(size_t)(row0+rl+8)*ldc + col0 + cl] = p1;
        }
}

// ---------------- LSTM elementwise: gather G_raw rows + nonlinearity --------------
__global__ void __launch_bounds__(256) lstm_elem(int t, int cur){
    const int r = blockIdx.x, tid = threadIdx.x;
    const int prv = cur^1;
    const int b = r & 63;
    int o, pv;
    if (t == 0){ o = r; pv = VV; } else { o = d_order[r]; pv = d_prev[r]; }
    const float4* gr = (const float4*)(d_graw + (size_t)o*G4);
    const float4* xw = (const float4*)(d_xW2 + (size_t)b*G4);
    const float4* gt = (const float4*)(d_Gt2 + (size_t)pv*G4);
    const float* cpf = d_ct[prv] + (size_t)o*HH;
    float* cf = d_ct[cur] + (size_t)r*HH;
#pragma unroll
    for (int q=0;q<4;q++){
        int u = tid + q*256;
        float4 g = (t==0) ? make_float4(0,0,0,0) : gr[u];
        float4 x = xw[u];
        float4 G = gt[u];
        float ig = g.x + x.x + G.x;
        float fg = g.y + x.y + G.y;
        float gg = g.z + x.z + G.z;
        float og = g.w + x.w + G.w;
        float cold = (t==0) ? 0.f : cpf[u];
        float cn = sigmoidf(fg)*cold + sigmoidf(ig)*tanhf(gg);
        float hn = sigmoidf(og)*tanhf(cn);
        cf[u] = cn;
        __nv_bfloat16 s0 = __float2bfloat16(hn);
        d_h2b[0][(size_t)r*HH + u] = s0;
        d_h2b[1][(size_t)r*HH + u] = __float2bfloat16(hn - __bfloat162float(s0));
    }
}

// ---------------- hd prep: sum fc1 partials + bias + relu + bf16 split ------------
__global__ void __launch_bounds__(256) hd_prep(const float* __restrict__ b_fc1){
    const int r = blockIdx.x, tid = threadIdx.x;
#pragma unroll
    for (int q=0;q<4;q++){
        int u = tid + q*256;
        size_t off = (size_t)r*HH + u;
        float x = d_fc1p[0][off] + d_fc1p[1][off] + d_fc1p[2][off] + d_fc1p[3][off]
                  + b_fc1[u];
        x = fmaxf(x, 0.f);
        __nv_bfloat16 s0 = __float2bfloat16(x);
        d_hd2b[0][off] = s0;
        d_hd2b[1][off] = __float2bfloat16(x - __bfloat162float(s0));
    }
}

// ---------------- warp LSE ---------------------------------------------------------
__device__ __forceinline__ float warpLSE(const float* __restrict__ base,
                                         const float* __restrict__ t1,
                                         const float* __restrict__ t2){
    int lane = threadIdx.x & 31;
    float m = -INFINITY, s = 0.f;
    for (int n = lane; n < NP; n += 32){
        float x = base[n];
        if (t1) x -= t1[n];
        if (t2) x -= t2[n];
        if (x > m){ s = s*expf(m-x) + 1.f; m = x; } else s += expf(x-m);
    }
#pragma unroll
    for (int off=16; off; off>>=1){
        float m2 = __shfl_xor_sync(0xffffffffu, m, off);
        float s2 = __shfl_xor_sync(0xffffffffu, s, off);
        float mm = fmaxf(m, m2);
        s = s*expf(m-mm) + s2*expf(m2-mm);
        m = mm;
    }
    return m + logf(s);
}

// ---------------- fused select (per batch element) ---------------------------------
__global__ void __launch_bounds__(256) select_kernel(const float* __restrict__ gu,
                                                     const float* __restrict__ b_out,
                                                     int t, int cur){
    __shared__ float pool[KB*NP + NP];
    __shared__ float cv_s[64];
    __shared__ int   ci_s[64];
    __shared__ float entS[KB], phiS[KB], gvalS[KB], logIs_s[KB+1];
    __shared__ int   ordS[KB], snewS[KB];

    const int i = blockIdx.x, tid = threadIdx.x;
    const int lane = tid & 31, w = tid >> 5;

    const int r = w*BB + i;
    const size_t rb = (size_t)r*VV;

    // logits = sum of SK partials + b_out, kept in registers
    float lv[13];
#pragma unroll
    for (int ii=0; ii<13; ii++){
        int v = lane + ii*32;
        float val = -INFINITY;
        if (v < VV)
            val = d_lpp[0][rb+v] + d_lpp[1][rb+v] + d_lpp[2][rb+v] + d_lpp[3][rb+v] + b_out[v];
        lv[ii] = val;
    }
    float m = -INFINITY;
#pragma unroll
    for (int ii=0; ii<13; ii++) m = fmaxf(m, lv[ii]);
#pragma unroll
    for (int off=16; off; off>>=1) m = fmaxf(m, __shfl_xor_sync(0xffffffffu, m, off));
    float s = 0.f;
#pragma unroll
    for (int ii=0; ii<13; ii++){ int v = lane+ii*32; if (v < VV) s += expf(lv[ii]-m); }
#pragma unroll
    for (int off=16; off; off>>=1) s += __shfl_xor_sync(0xffffffffu, s, off);
    float lse = m + logf(s);

    float lpr = d_logp[cur][r];
    float Gr  = d_Gmx[cur][r];
    const float* u = gu + ((size_t)t*RR + r)*VV;
    float ent = 0.f, zm = -INFINITY;
#pragma unroll
    for (int ii=0; ii<13; ii++){
        int v = lane + ii*32;
        if (v >= VV){ lv[ii] = -INFINITY; continue; }
        float l = lv[ii]-lse;
        d_lpn[rb+v] = l;
        ent += l*expf(l);
        float gmb = -logf(-logf(u[v]*(1.f-2e-7f)+1e-7f));
        float gph = l + lpr + gmb;
        lv[ii] = gph;
        zm = fmaxf(zm, gph);
    }
#pragma unroll
    for (int off=16; off; off>>=1){
        ent += __shfl_xor_sync(0xffffffffu, ent, off);
        zm = fmaxf(zm, __shfl_xor_sync(0xffffffffu, zm, off));
    }
    if (lane==0) entS[w] = ent;
#pragma unroll
    for (int ii=0; ii<13; ii++){
        int v = lane + ii*32;
        if (v >= VV) continue;
        float gph = lv[ii];
        float vv = Gr - gph + log1mexp(gph - zm);
        float val = Gr - fmaxf(vv,0.f) - log1pf(expf(-fabsf(vv)));
        lv[ii] = (t==0 && w>0) ? -INFINITY : val;
    }

    // per-warp top-8 (value desc, flat idx asc)
    for (int round=0; round<KB; round++){
        float bv = -INFINITY; int bi = 0x7fffffff;
#pragma unroll
        for (int ii=0; ii<13; ii++){
            int v = lane + ii*32;
            if (v >= VV) continue;
            float x = lv[ii]; int fi = w*VV + v;
            if (x > bv || (x == bv && fi < bi)){ bv = x; bi = fi; }
        }
#pragma unroll
        for (int off=16; off; off>>=1){
            float bv2 = __shfl_xor_sync(0xffffffffu, bv, off);
            int   bi2 = __shfl_xor_sync(0xffffffffu, bi, off);
            if (bv2 > bv || (bv2 == bv && bi2 < bi)){ bv = bv2; bi = bi2; }
        }
        int vwin = bi - w*VV;
        if (vwin >= 0 && vwin < VV && (vwin & 31) == lane) lv[vwin >> 5] = -INFINITY;
        if (lane == 0){ cv_s[w*KB + round] = bv; ci_s[w*KB + round] = bi; }
    }
    __syncthreads();

    // global top-8 over 64 candidates (warp 0)
    if (w == 0){
        float c0 = cv_s[lane], c1 = cv_s[lane+32];
        int   i0 = ci_s[lane], i1 = ci_s[lane+32];
        for (int round=0; round<KB; round++){
            float bv; int bi;
            if (c0 > c1 || (c0 == c1 && i0 < i1)){ bv = c0; bi = i0; }
            else                                 { bv = c1; bi = i1; }
#pragma unroll
            for (int off=16; off; off>>=1){
                float bv2 = __shfl_xor_sync(0xffffffffu, bv, off);
                int   bi2 = __shfl_xor_sync(0xffffffffu, bi, off);
                if (bv2 > bv || (bv2 == bv && bi2 < bi)){ bv = bv2; bi = bi2; }
            }
            if (i0 == bi) c0 = -INFINITY;
            if (i1 == bi) c1 = -INFINITY;
            if (lane == 0){
                gvalS[round] = bv;
                ordS[round]  = bi / VV;
                snewS[round] = bi % VV;
            }
        }
    }
    __syncthreads();

    // gather
    const int nxt = cur^1;
    for (int idx=tid; idx<KB*LL; idx+=256){
        int j = idx/LL, tt = idx - j*LL;
        if (tt == t) continue;
        int rn = j*BB+i, o = ordS[j]*BB+i;
        d_samples[nxt][rn*LL+tt] = d_samples[cur][o*LL+tt];
        d_outputs[nxt][rn*LL+tt] = d_outputs[cur][o*LL+tt];
    }
    if (tid < KB){
        int j = tid, rn = j*BB+i, o = ordS[j]*BB+i, sv = snewS[j];
        float lpv = d_lpn[(size_t)o*VV + sv];
        float nl  = d_logp[cur][o] + lpv;
        d_samples[nxt][rn*LL+t] = (float)sv;
        d_outputs[nxt][rn*LL+t] = lpv;
        d_logp[nxt][rn] = nl;
        d_Gmx[nxt][rn]  = gvalS[j];
        d_prev[rn]  = sv;
        d_order[rn] = o;
        d_phik[i*KB+j] = nl;
        phiS[j] = nl;
    }
    __syncthreads();

    // compute_log_R
    float (*Ts)[NP] = (float(*)[NP])pool;
    float* base = pool + KB*NP;
    float p[KB], pS = 0.f;
#pragma unroll
    for (int j=0;j<KB;j++){ p[j] = expf(phiS[j]); pS += p[j]; }
    for (int n=tid; n<NP; n+=256){
        float lu = logf(((float)n + 0.5f)/(float)NP);
        float bs = -pS*lu;
#pragma unroll
        for (int j=0;j<KB;j++){
            float x = log1mexp(p[j]*lu);
            Ts[j][n] = x;
            bs += x;
        }
        base[n] = bs;
    }
    __syncthreads();

    const float logN = logf((float)NP);
    float resA = warpLSE(base, Ts[w], nullptr) - logN;
    if (lane==0) logIs_s[w] = resA;
    if (w==0){
        float li = warpLSE(base, nullptr, nullptr) - logN;
        if (lane==0) logIs_s[KB] = li;
    }
    __syncthreads();
    float logI = logIs_s[KB];
    if (tid < KB) d_logRs[i*KB+tid] = logIs_s[tid] - logI;

    for (int pp = w; pp < 28; pp += 8){
        int a = 0, rem = pp;
        while (rem >= 7 - a){ rem -= (7 - a); a++; }
        int b = a + 1 + rem;
        float lss = warpLSE(base, Ts[a], Ts[b]) - logN;
        if (lane==0){
            d_logRss[i*64 + a*8 + b] = lss - logIs_s[a];
            d_logRss[i*64 + b*8 + a] = lss - logIs_s[b];
        }
    }
    if (tid < KB) d_logRss[i*64 + tid*9] = 0.f;
    if (tid == 0){
        float Wsum = 0.f, ws = 0.f;
#pragma unroll
        for (int j=0;j<KB;j++){
            float wq = expf(phiS[j] + logIs_s[j] - logI);
            Wsum += wq;
            ws   += wq * entS[ordS[j]];
        }
        d_entplot[i] += ws;
        d_entelem[i] += ws / Wsum;
    }
}

// ---------------- output assembly ---------------------------------------------------
__global__ void finalize_kernel(float* __restrict__ out, int out_size){
    int idx = blockIdx.x*blockDim.x + threadIdx.x;
    if (idx >= out_size || idx >= 18560) return;
    const int FIN = LL & 1;
    if (idx < 6656){
        int i = idx/104, rem = idx%104, j = rem/13, tt = rem%13;
        out[idx] = d_outputs[FIN][(j*BB+i)*LL + tt];
    } else if (idx < 13312){
        int q = idx - 6656;
        int i = q/104, rem = q%104, j = rem/13, tt = rem%13;
        out[idx] = d_samples[FIN][(j*BB+i)*LL + tt];
    } else if (idx < 13376){
        out[idx] = d_entelem[idx-13312];
    } else if (idx < 13888){
        out[idx] = d_logRs[idx-13376];
    } else if (idx < 17984){
        out[idx] = d_logRss[idx-13888];
    } else if (idx < 18496){
        out[idx] = d_phik[idx-17984];
    } else {
        out[idx] = d_entplot[idx-18496];
    }
}

// ---------------- host driver ---------------------------------------------------------
extern "C" void kernel_launch(void* const* d_in, const int* in_sizes, int n_in,
                              void* d_out, int out_size){
    const float* x_feat  = (const float*)d_in[0];
    const float* W_in_op = (const float*)d_in[1];
    const float* b_in_op = (const float*)d_in[2];
    const float* W_ih    = (const float*)d_in[3];
    const float* W_hh    = (const float*)d_in[4];
    const float* b_ih    = (const float*)d_in[5];
    const float* b_hh    = (const float*)d_in[6];
    const float* W_fc1   = (const float*)d_in[7];
    const float* b_fc1   = (const float*)d_in[8];
    const float* W_out   = (const float*)d_in[9];
    const float* b_out   = (const float*)d_in[10];
    const float* gu      = (const float*)d_in[11];
    (void)in_sizes; (void)n_in;

    void* tmp;
    cudaGetSymbolAddress(&tmp, d_xW);    float* p_xW  = (float*)tmp;
    cudaGetSymbolAddress(&tmp, d_E);     float* p_E   = (float*)tmp;
    cudaGetSymbolAddress(&tmp, d_Gt);    float* p_Gt  = (float*)tmp;
    cudaGetSymbolAddress(&tmp, d_h2b);   __nv_bfloat16* p_h2b = (__nv_bfloat16*)tmp;
    cudaGetSymbolAddress(&tmp, d_w2b);   __nv_bfloat16* p_w2b = (__nv_bfloat16*)tmp;
    cudaGetSymbolAddress(&tmp, d_wf2b);  __nv_bfloat16* p_wf  = (__nv_bfloat16*)tmp;
    cudaGetSymbolAddress(&tmp, d_wo2b);  __nv_bfloat16* p_wo  = (__nv_bfloat16*)tmp;
    cudaGetSymbolAddress(&tmp, d_hd2b);  __nv_bfloat16* p_hd2 = (__nv_bfloat16*)tmp;
    cudaGetSymbolAddress(&tmp, d_graw);  float* p_graw = (float*)tmp;
    cudaGetSymbolAddress(&tmp, d_fc1p);  float* p_fc1p = (float*)tmp;
    cudaGetSymbolAddress(&tmp, d_lpp);   float* p_lpp  = (float*)tmp;

    static cudaStream_t s1 = nullptr, s2 = nullptr;
    static cudaEvent_t ev0=nullptr, evA=nullptr, evB=nullptr, evW=nullptr, evEnd=nullptr;
    if (s1 == nullptr){
        cudaStreamCreateWithFlags(&s1, cudaStreamNonBlocking);
        cudaStreamCreateWithFlags(&s2, cudaStreamNonBlocking);
        cudaEventCreateWithFlags(&ev0, cudaEventDisableTiming);
        cudaEventCreateWithFlags(&evA, cudaEventDisableTiming);
        cudaEventCreateWithFlags(&evB, cudaEventDisableTiming);
        cudaEventCreateWithFlags(&evW, cudaEventDisableTiming);
        cudaEventCreateWithFlags(&evEnd, cudaEventDisableTiming);
        cudaFuncSetAttribute(mma_nt<64,false>, cudaFuncAttributeMaxDynamicSharedMemorySize, GM_DSMEM);
        cudaFuncSetAttribute(mma_nt<16,false>, cudaFuncAttributeMaxDynamicSharedMemorySize, GM_DSMEM);
        cudaFuncSetAttribute(mma_nt<16,true>,  cudaFuncAttributeMaxDynamicSharedMemorySize, GM_DSMEM);
    }

    // fork both worker streams off the capture-origin stream 0
    cudaEventRecord(ev0, 0);
    cudaStreamWaitEvent(s1, ev0, 0);
    cudaStreamWaitEvent(s2, ev0, 0);

    // s2: weight prep for loop GEMMs
    reorder_whh<<<(G4*HH+255)/256, 256, 0, s2>>>(W_hh);
    split_fw<<<((HH*HH + 512*HH)+255)/256, 256, 0, s2>>>(W_fc1, W_out);
    cudaEventRecord(evW, s2);

    // s1: setup chain
    init_kernel<<<256,256,0,s1>>>(W_in_op, b_in_op);
    gemm_db<1><<<dim3(64,1),256,0,s1>>>(x_feat,1024, W_ih,1152, p_xW,G4,
                                        BB,G4,1024, b_ih, b_hh);
    gemm_db<0><<<dim3(64,7),256,0,s1>>>(p_E,128, W_ih+1024,1152, p_Gt,G4,
                                        V1,G4,128, nullptr, nullptr);
    permute_gates<<<((BB+V1)*G4+255)/256,256,0,s1>>>();
    cudaStreamWaitEvent(s1, evW, 0);   // fc1/out weights ready before loop

    for (int t = 0; t < LL; t++){
        int cur = t & 1;

        lstm_elem<<<RR,256,0,s1>>>(t, cur);

        if (t < LL-1){
            // fork: G_raw(t) = h(t) @ Whh^T on s2 (bf16x2 HMMA)
            cudaEventRecord(evA, s1);
            cudaStreamWaitEvent(s2, evA, 0);
            mma_nt<64,false><<<dim3(32,4,1),256,GM_DSMEM,s2>>>(
                p_h2b, p_h2b + (size_t)RR*HH,
                p_w2b, p_w2b + (size_t)G4*HH,
                p_graw, G4, 0);
            cudaEventRecord(evB, s2);
        }

        // fc1 (split-K=4, HMMA) -> partials
        mma_nt<16,false><<<dim3(8,4,SK),256,GM_DSMEM,s1>>>(
            p_h2b, p_h2b + (size_t)RR*HH,
            p_wf,  p_wf  + (size_t)HH*HH,
            p_fc1p, HH, (size_t)RR*HH);
        hd_prep<<<RR,256,0,s1>>>(b_fc1);
        // out (split-K=4, HMMA) -> partials
        mma_nt<16,true><<<dim3(4,4,SK),256,GM_DSMEM,s1>>>(
            p_hd2, p_hd2 + (size_t)RR*HH,
            p_wo,  p_wo  + (size_t)512*HH,
            p_lpp, VV, (size_t)RR*VV);
        select_kernel<<<BB,256,0,s1>>>(gu, b_out, t, cur);

        if (t < LL-1){
            cudaStreamWaitEvent(s1, evB, 0);   // next lstm consumes G_raw(t)
        }
    }

    finalize_kernel<<<(18560+255)/256,256,0,s1>>>((float*)d_out, out_size);
    cudaEventRecord(evEnd, s1);
    cudaStreamWaitEvent(0, evEnd, 0);
}